// round 7
// baseline (speedup 1.0000x reference)
#include <cuda_runtime.h>
#include <cuda_fp16.h>
#include <math.h>
#include <stdint.h>

// ---- problem constants ----
#define NTOK 844      // B*T = 2*422
#define TSEQ 422
#define BSZ  2
#define CDIM 768
#define NH   32
#define HSD  24
#define NE   32
#define F4D  3072
#define NL   2
#define NV   100

typedef __half fp16;

// ---- device scratch ----
__device__ float g_x  [NTOK * CDIM];
__device__ float g_h  [NTOK * CDIM];
__device__ float g_qkv[NTOK * 3 * CDIM];
__device__ float g_gates[NTOK * NE];
__device__ float g_eo [(size_t)NTOK * NE * CDIM];

__device__ fp16 g_hh [NTOK * CDIM],  g_hl [NTOK * CDIM];
__device__ fp16 g_atth[NTOK * CDIM], g_attl[NTOK * CDIM];
__device__ fp16 g_wph[CDIM * 3 * CDIM], g_wpl[CDIM * 3 * CDIM];   // [c][3C]
__device__ fp16 g_woh[NL * CDIM * CDIM], g_wol[NL * CDIM * CDIM]; // natural [k][n]
__device__ fp16 g_w1h[(size_t)NL * NE * CDIM * F4D];
__device__ fp16 g_w1l[(size_t)NL * NE * CDIM * F4D];
__device__ fp16 g_w2h[(size_t)NL * NE * F4D * CDIM];
__device__ fp16 g_w2l[(size_t)NL * NE * F4D * CDIM];
__device__ fp16 g_hidh[(size_t)NTOK * NE * F4D];

// ======================= helpers =======================
__device__ __forceinline__ float gelu_exact(float v) {
    return 0.5f * v * (1.f + erff(v * 0.70710678118654752f));
}

__device__ __forceinline__ void mma16816(float* d, const unsigned* a, const unsigned* b) {
    asm volatile(
        "mma.sync.aligned.m16n8k16.row.col.f32.f16.f16.f32 "
        "{%0,%1,%2,%3}, {%4,%5,%6,%7}, {%8,%9}, {%0,%1,%2,%3};"
        : "+f"(d[0]), "+f"(d[1]), "+f"(d[2]), "+f"(d[3])
        : "r"(a[0]), "r"(a[1]), "r"(a[2]), "r"(a[3]), "r"(b[0]), "r"(b[1]));
}

__device__ __forceinline__ void cpa16(unsigned s, const void* g, int sz) {
    asm volatile("cp.async.cg.shared.global [%0], [%1], 16, %2;"
                 :: "r"(s), "l"(g), "r"(sz));
}
#define CPA_COMMIT() asm volatile("cp.async.commit_group;" ::: "memory")
#define CPA_WAIT(n)  asm volatile("cp.async.wait_group %0;" :: "n"(n) : "memory")

#define LDSM4(r0, r1, r2, r3, addr)                                            \
    asm volatile("ldmatrix.sync.aligned.m8n8.x4.shared.b16 {%0,%1,%2,%3}, [%4];" \
        : "=r"(r0), "=r"(r1), "=r"(r2), "=r"(r3) : "r"(addr))
#define LDSM4T(r0, r1, r2, r3, addr)                                           \
    asm volatile("ldmatrix.sync.aligned.m8n8.x4.trans.shared.b16 {%0,%1,%2,%3}, [%4];" \
        : "=r"(r0), "=r"(r1), "=r"(r2), "=r"(r3) : "r"(addr))

// ======================= fp16 split HMMA GEMM (B in natural [k][n]) =========
// C_e[m,n] = epi( sum_k A_e[m,k]*B_e[k,n] ). A: [m][k] fp16 hi(/lo) planes.
// B: [k][n] fp16 hi/lo planes, fragments via ldmatrix.trans.
// NT=3: AhBh+AhBl+AlBh (err ~2^-22).  NT=2: AhBh+AhBl (err ~2^-12), no A-lo.
// 128x128 tile/CTA, 8 warps (64x32). EP: 0 Cf; 1 Cf+bias; 2 Cf+=(+bias);
// 3 gelu(+bias)->Ch. NSTG-stage cp.async pipeline, one syncthreads per chunk.
#define APLANE 10240               // 128 rows * 80B
#define BPLANE 8704                // 32 k-rows * 272B
#define SMEM_NT2 82944             // 3 stages * (APLANE + 2*BPLANE)
#define SMEM_NT3 75776             // 2 stages * (2*APLANE + 2*BPLANE)

template <int EP, int NT, int NSTG>
__global__ void __launch_bounds__(256, 2)
mma_gemm(const fp16* __restrict__ Ah, const fp16* __restrict__ Al,
         long long lda, long long aExp,
         const fp16* __restrict__ Bh, const fp16* __restrict__ Bl,
         long long ldb, long long bExp,
         const float* __restrict__ bias, long long biasExp,
         float* __restrict__ Cf, fp16* __restrict__ Ch,
         long long ldc, long long cExp,
         int M, int Ntiles, int KC) {
    constexpr int APL = (NT == 3) ? 2 : 1;
    constexpr unsigned STAGE_B = APL * APLANE + 2 * BPLANE;
    extern __shared__ char smc[];
    unsigned smbase;
    asm("{ .reg .u64 t; cvta.to.shared.u64 t, %1; cvt.u32.u64 %0, t; }"
        : "=r"(smbase) : "l"(smc));

    const int tid = threadIdx.x, wid = tid >> 5, lane = tid & 31;
    const int g = lane >> 2, tg = lane & 3;
    const int wm = wid >> 2, wn = wid & 3;
    const int e = blockIdx.y;
    const int nt = blockIdx.x % Ntiles, mt = blockIdx.x / Ntiles;
    const int n0 = nt * 128, m0 = mt * 128;

    const fp16* Abh = Ah + (size_t)e * aExp;
    const fp16* Abl = (NT == 3) ? (Al + (size_t)e * aExp) : nullptr;
    const fp16* Bbh = Bh + (size_t)e * bExp;
    const fp16* Bbl = Bl + (size_t)e * bExp;

    // ldmatrix lane address components
    const int s4 = lane >> 3, lr = lane & 7;
    const int aRowL = lr + (s4 & 1) * 8, aColL = (s4 >> 1) * 8;   // A non-trans
    const int bKL = lr + (s4 & 1) * 8, bN8 = (lane >> 4) * 8;     // B trans

    float acc[4][4][4];
#pragma unroll
    for (int i = 0; i < 4; i++)
#pragma unroll
        for (int j = 0; j < 4; j++)
#pragma unroll
            for (int r = 0; r < 4; r++) acc[i][j][r] = 0.f;

    auto issue = [&](int c) {
        const int k0 = c * 32;
        unsigned sb = smbase + (unsigned)(c % NSTG) * STAGE_B;
        // A planes: [m][k] rows 64B -> smem 80B stride
#pragma unroll
        for (int i = 0; i < 2; i++) {
            int item = tid + i * 256;
            int row = item >> 2, c4 = item & 3;
            int m = m0 + row;
            int sz = (m < M) ? 16 : 0;
            size_t go = (size_t)(m < M ? m : 0) * lda + k0 + c4 * 8;
            unsigned so = sb + row * 80 + c4 * 16;
            cpa16(so, Abh + go, sz);
            if (NT == 3) cpa16(so + APLANE, Abl + go, sz);
        }
        // B planes: [k][n] natural, 32 k-rows x 256B -> smem 272B stride
#pragma unroll
        for (int i = 0; i < 2; i++) {
            int item = tid + i * 256;
            int k = item >> 4, c16 = item & 15;
            size_t go = (size_t)(k0 + k) * ldb + n0 + c16 * 8;
            unsigned so = sb + APL * APLANE + k * 272 + c16 * 16;
            cpa16(so, Bbh + go, 16);
            cpa16(so + BPLANE, Bbl + go, 16);
        }
    };

#pragma unroll
    for (int s = 0; s < NSTG - 1; s++) { issue(s); CPA_COMMIT(); }

    for (int c = 0; c < KC; ++c) {
        if (KC - 1 - c >= NSTG - 2) { CPA_WAIT(NSTG - 2); }
        else                        { CPA_WAIT(0); }
        __syncthreads();
        if (c + NSTG - 1 < KC) { issue(c + NSTG - 1); CPA_COMMIT(); }

        unsigned sb = smbase + (unsigned)(c % NSTG) * STAGE_B;
        unsigned sbB = sb + APL * APLANE;
#pragma unroll
        for (int ks = 0; ks < 2; ks++) {
            const int kb = ks * 16;
            unsigned bh_[4][2], bl_[4][2];
#pragma unroll
            for (int p = 0; p < 2; p++) {
                int nn = wn * 32 + p * 16 + bN8;
                unsigned ba = sbB + (unsigned)((kb + bKL) * 272 + nn * 2);
                LDSM4T(bh_[2 * p][0], bh_[2 * p][1], bh_[2 * p + 1][0], bh_[2 * p + 1][1], ba);
                LDSM4T(bl_[2 * p][0], bl_[2 * p][1], bl_[2 * p + 1][0], bl_[2 * p + 1][1],
                       ba + BPLANE);
            }
#pragma unroll
            for (int mi = 0; mi < 4; mi++) {
                int rm0 = wm * 64 + mi * 16;
                unsigned aa = sb + (unsigned)((rm0 + aRowL) * 80 + (kb + aColL) * 2);
                unsigned ah_[4], al_[4];
                LDSM4(ah_[0], ah_[1], ah_[2], ah_[3], aa);
                if (NT == 3) LDSM4(al_[0], al_[1], al_[2], al_[3], aa + APLANE);
#pragma unroll
                for (int ni = 0; ni < 4; ni++) {
                    mma16816(acc[mi][ni], ah_, bh_[ni]);
                    mma16816(acc[mi][ni], ah_, bl_[ni]);
                    if (NT == 3) mma16816(acc[mi][ni], al_, bh_[ni]);
                }
            }
        }
    }
    __syncthreads();   // all warps done reading smem before epilogue reuse

    // ---- epilogue: regs -> smem (fp32, stride 132) -> coalesced gmem ----
    float* sOut = (float*)smc;
#pragma unroll
    for (int mi = 0; mi < 4; mi++) {
        int lrow = wm * 64 + mi * 16 + g;
#pragma unroll
        for (int ni = 0; ni < 4; ni++) {
            int j = wn * 32 + ni * 8 + tg * 2;
            float b0 = 0.f, b1 = 0.f;
            if (EP >= 1) {
                b0 = bias[(size_t)e * biasExp + n0 + j];
                b1 = bias[(size_t)e * biasExp + n0 + j + 1];
            }
#pragma unroll
            for (int hh = 0; hh < 2; hh++) {
                float v0 = acc[mi][ni][hh * 2 + 0] + b0;
                float v1 = acc[mi][ni][hh * 2 + 1] + b1;
                if (EP == 3) { v0 = gelu_exact(v0); v1 = gelu_exact(v1); }
                float2 o2 = make_float2(v0, v1);
                *(float2*)&sOut[(lrow + hh * 8) * 132 + j] = o2;
            }
        }
    }
    __syncthreads();

    if (EP == 3) {
#pragma unroll
        for (int i = 0; i < 8; i++) {
            int item = tid + i * 256;
            int row = item >> 4;
            int c8 = (item & 15) * 8;
            int m = m0 + row;
            if (m >= M) continue;
            float4 f0 = *(float4*)&sOut[row * 132 + c8];
            float4 f1 = *(float4*)&sOut[row * 132 + c8 + 4];
            __half2 h0 = __floats2half2_rn(f0.x, f0.y);
            __half2 h1 = __floats2half2_rn(f0.z, f0.w);
            __half2 h2 = __floats2half2_rn(f1.x, f1.y);
            __half2 h3 = __floats2half2_rn(f1.z, f1.w);
            uint4 u = make_uint4(*(unsigned*)&h0, *(unsigned*)&h1,
                                 *(unsigned*)&h2, *(unsigned*)&h3);
            *(uint4*)(Ch + (size_t)e * cExp + (size_t)m * ldc + n0 + c8) = u;
        }
    } else {
#pragma unroll
        for (int i = 0; i < 16; i++) {
            int item = tid + i * 256;
            int row = item >> 5;
            int c4 = (item & 31) * 4;
            int m = m0 + row;
            if (m >= M) continue;
            float4 v = *(float4*)&sOut[row * 132 + c4];
            float* p = Cf + (size_t)e * cExp + (size_t)m * ldc + n0 + c4;
            if (EP == 2) {
                float4 old = *(float4*)p;
                v.x += old.x; v.y += old.y; v.z += old.z; v.w += old.w;
            }
            *(float4*)p = v;
        }
    }
}

// ======================= streaming fp32 -> fp16 hi/lo split =================
__global__ void convS(const float* __restrict__ src,
                      fp16* __restrict__ th, fp16* __restrict__ tl,
                      size_t n4) {
    size_t i = (size_t)blockIdx.x * blockDim.x + threadIdx.x;
    if (i >= n4) return;
    float4 v = ((const float4*)src)[i];
    __half2 h0 = __floats2half2_rn(v.x, v.y);
    __half2 h1 = __floats2half2_rn(v.z, v.w);
    float2 r0 = __half22float2(h0), r1 = __half22float2(h1);
    __half2 l0 = __floats2half2_rn(v.x - r0.x, v.y - r0.y);
    __half2 l1 = __floats2half2_rn(v.z - r1.x, v.w - r1.y);
    ((uint2*)th)[i] = make_uint2(*(unsigned*)&h0, *(unsigned*)&h1);
    ((uint2*)tl)[i] = make_uint2(*(unsigned*)&l0, *(unsigned*)&l1);
}

// ======================= pack Wq/Wk/Wv -> [c][3C] fp16 planes ===============
__global__ void pack_qkv(const float* __restrict__ Wq,
                         const float* __restrict__ Wk,
                         const float* __restrict__ Wv,
                         fp16* __restrict__ th, fp16* __restrict__ tl) {
    int i = blockIdx.x * blockDim.x + threadIdx.x;
    if (i >= CDIM * CDIM) return;
    int c = i / CDIM, j = i % CDIM;
    int h = j / HSD, s = j % HSD;
    size_t src = ((size_t)h * CDIM + c) * HSD + s;
    size_t dst = (size_t)c * (3 * CDIM) + j;
    float vq = Wq[src], vk = Wk[src], vv = Wv[src];
    fp16 hq = __float2half_rn(vq), hk = __float2half_rn(vk), hv = __float2half_rn(vv);
    th[dst] = hq;              tl[dst] = __float2half_rn(vq - __half2float(hq));
    th[dst + CDIM] = hk;       tl[dst + CDIM] = __float2half_rn(vk - __half2float(hk));
    th[dst + 2 * CDIM] = hv;   tl[dst + 2 * CDIM] = __float2half_rn(vv - __half2float(hv));
}

// ======================= embedding =======================
__global__ void embed_kernel(const int* __restrict__ idx,
                             const float* __restrict__ tok,
                             const float* __restrict__ pos,
                             float* __restrict__ x) {
    int n = blockIdx.x;
    int t = n % TSEQ;
    int v = idx[n];
    for (int c = threadIdx.x; c < CDIM; c += blockDim.x)
        x[n * CDIM + c] = tok[v * CDIM + c] + pos[t * CDIM + c];
}

// ======================= layernorm (fp32 + fp16 hi/lo planes) ==============
__global__ void ln_kernel(const float* __restrict__ x,
                          const float* __restrict__ g,
                          const float* __restrict__ b,
                          float* __restrict__ out,
                          fp16* __restrict__ oh, fp16* __restrict__ ol) {
    int n = blockIdx.x;
    int tid = threadIdx.x;
    __shared__ float s1[256], s2[256];
    const float* xr = x + (size_t)n * CDIM;
    float a = 0.f, q = 0.f;
    for (int c = tid; c < CDIM; c += 256) { float v = xr[c]; a += v; q += v * v; }
    s1[tid] = a; s2[tid] = q;
    __syncthreads();
    for (int s = 128; s > 0; s >>= 1) {
        if (tid < s) { s1[tid] += s1[tid + s]; s2[tid] += s2[tid + s]; }
        __syncthreads();
    }
    float mean = s1[0] * (1.f / CDIM);
    float var  = s2[0] * (1.f / CDIM) - mean * mean;
    float r = rsqrtf(var + 1e-5f);
    for (int c = tid; c < CDIM; c += 256) {
        float o = (xr[c] - mean) * r * g[c] + b[c];
        size_t p = (size_t)n * CDIM + c;
        out[p] = o;
        fp16 hi = __float2half_rn(o);
        oh[p] = hi;
        ol[p] = __float2half_rn(o - __half2float(hi));
    }
}

// ======================= attention =======================
__global__ void attn_kernel(const float* __restrict__ qkv,
                            fp16* __restrict__ atth, fp16* __restrict__ attl) {
    int t = blockIdx.x, h = blockIdx.y, b = blockIdx.z;
    int tid = threadIdx.x;
    __shared__ float sc[TSEQ];
    __shared__ float qs[HSD];
    __shared__ float red[128];
    __shared__ float part[5 * HSD];

    int n0 = b * TSEQ;
    const float* Q = qkv + (size_t)(n0 + t) * (3 * CDIM) + h * HSD;
    if (tid < HSD) qs[tid] = Q[tid];
    __syncthreads();

    const float scale = 0.20412414523193154f;
    float lmax = -1e30f;
    for (int u = tid; u <= t; u += 128) {
        const float* Kp = qkv + (size_t)(n0 + u) * (3 * CDIM) + CDIM + h * HSD;
        float d = 0.f;
#pragma unroll
        for (int s = 0; s < HSD; s++) d += qs[s] * Kp[s];
        d *= scale;
        sc[u] = d;
        lmax = fmaxf(lmax, d);
    }
    red[tid] = lmax;
    __syncthreads();
    for (int s = 64; s > 0; s >>= 1) {
        if (tid < s) red[tid] = fmaxf(red[tid], red[tid + s]);
        __syncthreads();
    }
    float mx = red[0];
    __syncthreads();

    float lsum = 0.f;
    for (int u = tid; u <= t; u += 128) {
        float ev = expf(sc[u] - mx);
        sc[u] = ev;
        lsum += ev;
    }
    red[tid] = lsum;
    __syncthreads();
    for (int s = 64; s > 0; s >>= 1) {
        if (tid < s) red[tid] += red[tid + s];
        __syncthreads();
    }
    float inv = 1.f / red[0];
    __syncthreads();

    if (tid < 120) {
        int s = tid % HSD, gg = tid / HSD;
        float a = 0.f;
        for (int u = gg; u <= t; u += 5) {
            const float* Vp = qkv + (size_t)(n0 + u) * (3 * CDIM) + 2 * CDIM + h * HSD;
            a += sc[u] * Vp[s];
        }
        part[gg * HSD + s] = a;
    }
    __syncthreads();
    if (tid < HSD) {
        float a = (part[tid] + part[HSD + tid] + part[2 * HSD + tid]
                 + part[3 * HSD + tid] + part[4 * HSD + tid]) * inv;
        size_t o = (size_t)(n0 + t) * CDIM + h * HSD + tid;
        fp16 hi = __float2half_rn(a);
        atth[o] = hi;
        attl[o] = __float2half_rn(a - __half2float(hi));
    }
}

// ======================= gate softmax =======================
__global__ void gate_kernel(const float* __restrict__ h2,
                            const float* __restrict__ gw,
                            const float* __restrict__ gb,
                            float* __restrict__ gates) {
    int n = blockIdx.x;
    int e = threadIdx.x;
    const float* hr = h2 + (size_t)n * CDIM;
    float acc = gb[e];
    for (int c = 0; c < CDIM; c++) acc += hr[c] * gw[c * NE + e];
    float mx = acc;
    for (int o = 16; o > 0; o >>= 1) mx = fmaxf(mx, __shfl_xor_sync(0xFFFFFFFFu, mx, o));
    float ex = expf(acc - mx);
    float sm = ex;
    for (int o = 16; o > 0; o >>= 1) sm += __shfl_xor_sync(0xFFFFFFFFu, sm, o);
    gates[n * NE + e] = ex / sm;
}

// ======================= MoE combine =======================
__global__ void combine_kernel(const float* __restrict__ eo,
                               const float* __restrict__ gates,
                               float* __restrict__ x) {
    int n = blockIdx.x;
    __shared__ float gs[NE];
    if (threadIdx.x < NE) gs[threadIdx.x] = gates[n * NE + threadIdx.x];
    __syncthreads();
    for (int c = threadIdx.x; c < CDIM; c += blockDim.x) {
        float a = 0.f;
        const float* er = eo + (size_t)n * (NE * CDIM) + c;
#pragma unroll 8
        for (int e = 0; e < NE; e++) a += gs[e] * er[e * CDIM];
        x[(size_t)n * CDIM + c] += a;
    }
}

// ======================= scalar SGEMM (lm head only) =======================
__global__ void __launch_bounds__(256)
lm_head_kernel(const float* __restrict__ A, const float* __restrict__ B,
               const float* __restrict__ bias, float* __restrict__ C,
               int M, int N, int K) {
    __shared__ float As[64][17];
    __shared__ float Bs[16][64];
    int tid = threadIdx.x;
    int jTile = blockIdx.x * 64;
    int mTile = blockIdx.y * 64;
    int tx = tid & 15, ty = tid >> 4;

    float acc[4][4];
#pragma unroll
    for (int r = 0; r < 4; r++)
#pragma unroll
        for (int c = 0; c < 4; c++) acc[r][c] = 0.f;

    int aRow = tid >> 2, aK = (tid & 3) * 4;
    int bJ = tid & 63, bK0 = tid >> 6;

    for (int k0 = 0; k0 < K; k0 += 16) {
        int m = mTile + aRow;
        if (m < M) {
            float4 av = *(const float4*)(A + (size_t)m * K + k0 + aK);
            As[aRow][aK + 0] = av.x; As[aRow][aK + 1] = av.y;
            As[aRow][aK + 2] = av.z; As[aRow][aK + 3] = av.w;
        } else {
            As[aRow][aK + 0] = 0.f; As[aRow][aK + 1] = 0.f;
            As[aRow][aK + 2] = 0.f; As[aRow][aK + 3] = 0.f;
        }
#pragma unroll
        for (int i = 0; i < 4; i++) {
            int kk = bK0 + i * 4;
            Bs[kk][bJ] = (jTile + bJ < N)
                ? B[(size_t)(k0 + kk) * N + jTile + bJ] : 0.f;
        }
        __syncthreads();
#pragma unroll
        for (int k = 0; k < 16; k++) {
            float4 bv = *(const float4*)&Bs[k][tx * 4];
            float a0 = As[ty * 4 + 0][k], a1 = As[ty * 4 + 1][k];
            float a2 = As[ty * 4 + 2][k], a3 = As[ty * 4 + 3][k];
            acc[0][0] += a0 * bv.x; acc[0][1] += a0 * bv.y; acc[0][2] += a0 * bv.z; acc[0][3] += a0 * bv.w;
            acc[1][0] += a1 * bv.x; acc[1][1] += a1 * bv.y; acc[1][2] += a1 * bv.z; acc[1][3] += a1 * bv.w;
            acc[2][0] += a2 * bv.x; acc[2][1] += a2 * bv.y; acc[2][2] += a2 * bv.z; acc[2][3] += a2 * bv.w;
            acc[3][0] += a3 * bv.x; acc[3][1] += a3 * bv.y; acc[3][2] += a3 * bv.z; acc[3][3] += a3 * bv.w;
        }
        __syncthreads();
    }
#pragma unroll
    for (int r = 0; r < 4; r++) {
        int m = mTile + ty * 4 + r;
        if (m >= M) continue;
#pragma unroll
        for (int c = 0; c < 4; c++) {
            int j = jTile + tx * 4 + c;
            if (j >= N) continue;
            C[(size_t)m * N + j] = acc[r][c] + bias[j];
        }
    }
}

// ======================= launch =======================
extern "C" void kernel_launch(void* const* d_in, const int* in_sizes, int n_in,
                              void* d_out, int out_size) {
    const int*   idx    = (const int*)  d_in[0];
    const float* tok    = (const float*)d_in[1];
    const float* pos    = (const float*)d_in[2];
    const float* ln1_g  = (const float*)d_in[3];
    const float* ln1_b  = (const float*)d_in[4];
    const float* Wq     = (const float*)d_in[5];
    const float* Wk     = (const float*)d_in[6];
    const float* Wv     = (const float*)d_in[7];
    const float* Wo     = (const float*)d_in[8];
    const float* bo     = (const float*)d_in[9];
    const float* ln2_g  = (const float*)d_in[10];
    const float* ln2_b  = (const float*)d_in[11];
    const float* gate_w = (const float*)d_in[12];
    const float* gate_b = (const float*)d_in[13];
    const float* W1     = (const float*)d_in[14];
    const float* b1     = (const float*)d_in[15];
    const float* W2     = (const float*)d_in[16];
    const float* b2     = (const float*)d_in[17];
    const float* lnf_g  = (const float*)d_in[18];
    const float* lnf_b  = (const float*)d_in[19];
    const float* lm_w   = (const float*)d_in[20];
    const float* lm_b   = (const float*)d_in[21];
    float* out = (float*)d_out;

    float *x, *h, *qkv, *gates, *eo;
    fp16 *hh, *hl, *atth, *attl, *wph, *wpl, *woh, *wol;
    fp16 *w1h, *w1l, *w2h, *w2l, *hidh;
    cudaGetSymbolAddress((void**)&x,     g_x);
    cudaGetSymbolAddress((void**)&h,     g_h);
    cudaGetSymbolAddress((void**)&qkv,   g_qkv);
    cudaGetSymbolAddress((void**)&gates, g_gates);
    cudaGetSymbolAddress((void**)&eo,    g_eo);
    cudaGetSymbolAddress((void**)&hh,    g_hh);
    cudaGetSymbolAddress((void**)&hl,    g_hl);
    cudaGetSymbolAddress((void**)&atth,  g_atth);
    cudaGetSymbolAddress((void**)&attl,  g_attl);
    cudaGetSymbolAddress((void**)&wph,   g_wph);
    cudaGetSymbolAddress((void**)&wpl,   g_wpl);
    cudaGetSymbolAddress((void**)&woh,   g_woh);
    cudaGetSymbolAddress((void**)&wol,   g_wol);
    cudaGetSymbolAddress((void**)&w1h,   g_w1h);
    cudaGetSymbolAddress((void**)&w1l,   g_w1l);
    cudaGetSymbolAddress((void**)&w2h,   g_w2h);
    cudaGetSymbolAddress((void**)&w2l,   g_w2l);
    cudaGetSymbolAddress((void**)&hidh,  g_hidh);

    cudaFuncSetAttribute((const void*)mma_gemm<0,3,2>, cudaFuncAttributeMaxDynamicSharedMemorySize, SMEM_NT3);
    cudaFuncSetAttribute((const void*)mma_gemm<2,3,2>, cudaFuncAttributeMaxDynamicSharedMemorySize, SMEM_NT3);
    cudaFuncSetAttribute((const void*)mma_gemm<3,2,3>, cudaFuncAttributeMaxDynamicSharedMemorySize, SMEM_NT2);
    cudaFuncSetAttribute((const void*)mma_gemm<1,2,3>, cudaFuncAttributeMaxDynamicSharedMemorySize, SMEM_NT2);

    const int MT = (NTOK + 127) / 128;   // 7

    // ---- streaming weight split (no transpose needed) ----
    {
        size_t n4 = (size_t)NL * NE * CDIM * F4D / 4;
        convS<<<(unsigned)((n4 + 255) / 256), 256>>>(W1, w1h, w1l, n4);
        convS<<<(unsigned)((n4 + 255) / 256), 256>>>(W2, w2h, w2l, n4);
        size_t w4 = (size_t)NL * CDIM * CDIM / 4;
        convS<<<(unsigned)((w4 + 255) / 256), 256>>>(Wo, woh, wol, w4);
    }

    embed_kernel<<<NTOK, 256>>>(idx, tok, pos, x);

    for (int l = 0; l < NL; l++) {
        // --- attention ---
        ln_kernel<<<NTOK, 256>>>(x, ln1_g + l * CDIM, ln1_b + l * CDIM, h, hh, hl);
        pack_qkv<<<(CDIM * CDIM + 255) / 256, 256>>>(
            Wq + (size_t)l * NH * CDIM * HSD,
            Wk + (size_t)l * NH * CDIM * HSD,
            Wv + (size_t)l * NH * CDIM * HSD, wph, wpl);
        mma_gemm<0,3,2><<<dim3(MT * 18, 1), 256, SMEM_NT3>>>(
            hh, hl, CDIM, 0, wph, wpl, 3 * CDIM, 0,
            nullptr, 0, qkv, nullptr, 3 * CDIM, 0,
            NTOK, 18, CDIM / 32);
        attn_kernel<<<dim3(TSEQ, NH, BSZ), 128>>>(qkv, atth, attl);
        mma_gemm<2,3,2><<<dim3(MT * 6, 1), 256, SMEM_NT3>>>(
            atth, attl, CDIM, 0,
            woh + (size_t)l * CDIM * CDIM, wol + (size_t)l * CDIM * CDIM, CDIM, 0,
            bo + l * CDIM, 0, x, nullptr, CDIM, 0,
            NTOK, 6, CDIM / 32);

        // --- MoE ---
        ln_kernel<<<NTOK, 256>>>(x, ln2_g + l * CDIM, ln2_b + l * CDIM, h, hh, hl);
        gate_kernel<<<NTOK, 32>>>(h, gate_w + (size_t)l * CDIM * NE,
                                  gate_b + l * NE, gates);
        // up: hid = gelu(h @ W1_e + b1_e) -> fp16 hi plane
        mma_gemm<3,2,3><<<dim3(MT * (F4D / 128), NE), 256, SMEM_NT2>>>(
            hh, nullptr, CDIM, 0,
            w1h + (size_t)l * NE * CDIM * F4D, w1l + (size_t)l * NE * CDIM * F4D,
            F4D, (long long)CDIM * F4D,
            b1 + (size_t)l * NE * F4D, F4D,
            nullptr, hidh, (long long)NE * F4D, F4D,
            NTOK, F4D / 128, CDIM / 32);
        // down: eo = hid_e @ W2_e + b2_e
        mma_gemm<1,2,3><<<dim3(MT * (CDIM / 128), NE), 256, SMEM_NT2>>>(
            hidh, nullptr, (long long)NE * F4D, F4D,
            w2h + (size_t)l * NE * F4D * CDIM, w2l + (size_t)l * NE * F4D * CDIM,
            CDIM, (long long)F4D * CDIM,
            b2 + (size_t)l * NE * CDIM, CDIM,
            eo, nullptr, (long long)NE * CDIM, CDIM,
            NTOK, CDIM / 128, F4D / 32);
        combine_kernel<<<NTOK, 256>>>(eo, gates, x);
    }

    // --- final LN + lm head ---
    ln_kernel<<<NTOK, 256>>>(x, lnf_g, lnf_b, h, hh, hl);
    lm_head_kernel<<<dim3((NV + 63) / 64, (NTOK + 63) / 64), 256>>>(
        h, lm_w, lm_b, out, NTOK, NV, CDIM);
}

// round 8
// speedup vs baseline: 1.4225x; 1.4225x over previous
#include <cuda_runtime.h>
#include <cuda_fp16.h>
#include <math.h>
#include <stdint.h>

// ---- problem constants ----
#define NTOK 844      // B*T = 2*422
#define TSEQ 422
#define BSZ  2
#define CDIM 768
#define NH   32
#define HSD  24
#define NE   32
#define F4D  3072
#define NL   2
#define NV   100

typedef __half fp16;

// ---- device scratch ----
__device__ float g_x  [NTOK * CDIM];
__device__ float g_h  [NTOK * CDIM];
__device__ float g_qkv[NTOK * 3 * CDIM];
__device__ float g_gates[NTOK * NE];
__device__ float g_eo [(size_t)NTOK * NE * CDIM];

__device__ fp16 g_hh [NTOK * CDIM],  g_hl [NTOK * CDIM];
__device__ fp16 g_atth[NTOK * CDIM], g_attl[NTOK * CDIM];
__device__ fp16 g_wpth[3 * CDIM * CDIM], g_wptl[3 * CDIM * CDIM];
__device__ fp16 g_woth[NL * CDIM * CDIM], g_wotl[NL * CDIM * CDIM];
__device__ fp16 g_w1th[(size_t)NL * NE * F4D * CDIM];
__device__ fp16 g_w1tl[(size_t)NL * NE * F4D * CDIM];
__device__ fp16 g_w2th[(size_t)NL * NE * CDIM * F4D];
__device__ fp16 g_w2tl[(size_t)NL * NE * CDIM * F4D];
__device__ fp16 g_hidh[(size_t)NTOK * NE * F4D];

// ======================= helpers =======================
__device__ __forceinline__ float gelu_exact(float v) {
    return 0.5f * v * (1.f + erff(v * 0.70710678118654752f));
}

__device__ __forceinline__ void mma16816(float* d, const unsigned* a, const unsigned* b) {
    asm volatile(
        "mma.sync.aligned.m16n8k16.row.col.f32.f16.f16.f32 "
        "{%0,%1,%2,%3}, {%4,%5,%6,%7}, {%8,%9}, {%0,%1,%2,%3};"
        : "+f"(d[0]), "+f"(d[1]), "+f"(d[2]), "+f"(d[3])
        : "r"(a[0]), "r"(a[1]), "r"(a[2]), "r"(a[3]), "r"(b[0]), "r"(b[1]));
}

__device__ __forceinline__ void cpa16(unsigned s, const void* g, int sz) {
    asm volatile("cp.async.cg.shared.global [%0], [%1], 16, %2;"
                 :: "r"(s), "l"(g), "r"(sz));
}
#define CPA_COMMIT() asm volatile("cp.async.commit_group;" ::: "memory")
#define CPA_WAIT(n)  asm volatile("cp.async.wait_group %0;" :: "n"(n) : "memory")

#define LDSM4(r0, r1, r2, r3, addr)                                            \
    asm volatile("ldmatrix.sync.aligned.m8n8.x4.shared.b16 {%0,%1,%2,%3}, [%4];" \
        : "=r"(r0), "=r"(r1), "=r"(r2), "=r"(r3) : "r"(addr))

// ======================= fp16 split HMMA GEMM =======================
// C_e[m,n] = epi( sum_k A_e[m,k]*B_e[n,k] ); operands pre-split fp16 hi/lo planes.
// NT=3: AhBh + AhBl + AlBh (err ~2^-22).  NT=2: AhBh + AhBl (err ~2^-12), no A-lo.
// 128x128 tile/CTA, 8 warps (64x32). EP: 0 Cf; 1 Cf+bias; 2 Cf += (+bias);
// 3 gelu(+bias) -> Ch (fp16 hi only).
#define STR 40                     // smem row stride (elems); 80B rows
#define PLANE_B (128 * 80)         // 10240
#define EPI_BYTES (128 * 132 * 4)  // 67584
#define SMEM_NT3 81920             // 2 stages * 4 planes
#define SMEM_NT2 69632             // max(2*3 planes=61440, EPI) rounded up

template <int EP, int NT>
__global__ void __launch_bounds__(256, 2)
mma_gemm(const fp16* __restrict__ Ah, const fp16* __restrict__ Al,
         long long lda, long long aExp,
         const fp16* __restrict__ Bh, const fp16* __restrict__ Bl,
         long long ldb, long long bExp,
         const float* __restrict__ bias, long long biasExp,
         float* __restrict__ Cf, fp16* __restrict__ Ch,
         long long ldc, long long cExp,
         int M, int Ntiles, int KC) {
    constexpr int APL = (NT == 3) ? 2 : 1;
    constexpr unsigned STAGE_B = (APL + 2) * PLANE_B;
    extern __shared__ char smc[];
    unsigned smbase;
    asm("{ .reg .u64 t; cvta.to.shared.u64 t, %1; cvt.u32.u64 %0, t; }"
        : "=r"(smbase) : "l"(smc));

    const int tid = threadIdx.x, wid = tid >> 5, lane = tid & 31;
    const int g = lane >> 2, tg = lane & 3;
    const int wm = wid >> 2, wn = wid & 3;
    const int e = blockIdx.y;
    const int nt = blockIdx.x % Ntiles, mt = blockIdx.x / Ntiles;
    const int n0 = nt * 128, m0 = mt * 128;

    const fp16* Abh = Ah + (size_t)e * aExp;
    const fp16* Abl = (NT == 3) ? (Al + (size_t)e * aExp) : nullptr;
    const fp16* Bbh = Bh + (size_t)e * bExp;
    const fp16* Bbl = Bl + (size_t)e * bExp;

    const int s4 = lane >> 3, lr = lane & 7;
    const int aRowL = lr + (s4 & 1) * 8, aColL = (s4 >> 1) * 8;
    const int bRowL = lr + (s4 >> 1) * 8, bColL = (s4 & 1) * 8;

    float acc[4][4][4];
#pragma unroll
    for (int i = 0; i < 4; i++)
#pragma unroll
        for (int j = 0; j < 4; j++)
#pragma unroll
            for (int r = 0; r < 4; r++) acc[i][j][r] = 0.f;

    const int fRow = tid >> 2, fCh = tid & 3;

    auto issue = [&](int c) {
        const int k0 = c * 32;
        unsigned sb = smbase + (c & 1) * STAGE_B;
#pragma unroll
        for (int i = 0; i < 2; i++) {
            int row = fRow + i * 64;
            int m = m0 + row;
            int sz = (m < M) ? 16 : 0;
            size_t go = (size_t)(m < M ? m : 0) * lda + k0 + fCh * 8;
            unsigned so = sb + row * 80 + fCh * 16;
            cpa16(so, Abh + go, sz);
            if (NT == 3) cpa16(so + PLANE_B, Abl + go, sz);
        }
#pragma unroll
        for (int i = 0; i < 2; i++) {
            int row = fRow + i * 64;
            size_t go = (size_t)(n0 + row) * ldb + k0 + fCh * 8;
            unsigned so = sb + APL * PLANE_B + row * 80 + fCh * 16;
            cpa16(so, Bbh + go, 16);
            cpa16(so + PLANE_B, Bbl + go, 16);
        }
    };

    issue(0);
    CPA_COMMIT();

    for (int c = 0; c < KC; ++c) {
        if (c + 1 < KC) { issue(c + 1); CPA_COMMIT(); CPA_WAIT(1); }
        else            { CPA_WAIT(0); }
        __syncthreads();

        unsigned sb = smbase + (c & 1) * STAGE_B;
#pragma unroll
        for (int ks = 0; ks < 2; ks++) {
            const int kb = ks * 16;
            unsigned bh_[4][2], bl_[4][2];
#pragma unroll
            for (int p = 0; p < 2; p++) {
                int rn0 = wn * 32 + p * 16;
                unsigned ba = sb + APL * PLANE_B +
                              (unsigned)((rn0 + bRowL) * STR + kb + bColL) * 2;
                LDSM4(bh_[2 * p][0], bh_[2 * p][1], bh_[2 * p + 1][0], bh_[2 * p + 1][1], ba);
                LDSM4(bl_[2 * p][0], bl_[2 * p][1], bl_[2 * p + 1][0], bl_[2 * p + 1][1],
                      ba + PLANE_B);
            }
#pragma unroll
            for (int mi = 0; mi < 4; mi++) {
                int rm0 = wm * 64 + mi * 16;
                unsigned aa = sb + (unsigned)((rm0 + aRowL) * STR + kb + aColL) * 2;
                unsigned ah_[4], al_[4];
                LDSM4(ah_[0], ah_[1], ah_[2], ah_[3], aa);
                if (NT == 3) LDSM4(al_[0], al_[1], al_[2], al_[3], aa + PLANE_B);
#pragma unroll
                for (int ni = 0; ni < 4; ni++) {
                    mma16816(acc[mi][ni], ah_, bh_[ni]);
                    mma16816(acc[mi][ni], ah_, bl_[ni]);
                    if (NT == 3) mma16816(acc[mi][ni], al_, bh_[ni]);
                }
            }
        }
        __syncthreads();
    }

    // ---- epilogue: regs -> smem (fp32, stride 132) -> coalesced gmem ----
    float* sOut = (float*)smc;
#pragma unroll
    for (int mi = 0; mi < 4; mi++) {
        int lrow = wm * 64 + mi * 16 + g;
#pragma unroll
        for (int ni = 0; ni < 4; ni++) {
            int j = wn * 32 + ni * 8 + tg * 2;
            float b0 = 0.f, b1 = 0.f;
            if (EP >= 1) {
                b0 = bias[(size_t)e * biasExp + n0 + j];
                b1 = bias[(size_t)e * biasExp + n0 + j + 1];
            }
#pragma unroll
            for (int hh = 0; hh < 2; hh++) {
                float v0 = acc[mi][ni][hh * 2 + 0] + b0;
                float v1 = acc[mi][ni][hh * 2 + 1] + b1;
                if (EP == 3) { v0 = gelu_exact(v0); v1 = gelu_exact(v1); }
                float2 o2 = make_float2(v0, v1);
                *(float2*)&sOut[(lrow + hh * 8) * 132 + j] = o2;
            }
        }
    }
    __syncthreads();

    if (EP == 3) {
        // write fp16 hi plane, coalesced 16B stores
#pragma unroll
        for (int i = 0; i < 8; i++) {
            int item = tid + i * 256;
            int row = item >> 4;
            int c8 = (item & 15) * 8;
            int m = m0 + row;
            if (m >= M) continue;
            float4 f0 = *(float4*)&sOut[row * 132 + c8];
            float4 f1 = *(float4*)&sOut[row * 132 + c8 + 4];
            __half2 h0 = __floats2half2_rn(f0.x, f0.y);
            __half2 h1 = __floats2half2_rn(f0.z, f0.w);
            __half2 h2 = __floats2half2_rn(f1.x, f1.y);
            __half2 h3 = __floats2half2_rn(f1.z, f1.w);
            uint4 u = make_uint4(*(unsigned*)&h0, *(unsigned*)&h1,
                                 *(unsigned*)&h2, *(unsigned*)&h3);
            *(uint4*)(Ch + (size_t)e * cExp + (size_t)m * ldc + n0 + c8) = u;
        }
    } else {
#pragma unroll
        for (int i = 0; i < 16; i++) {
            int item = tid + i * 256;
            int row = item >> 5;
            int c4 = (item & 31) * 4;
            int m = m0 + row;
            if (m >= M) continue;
            float4 v = *(float4*)&sOut[row * 132 + c4];
            float* p = Cf + (size_t)e * cExp + (size_t)m * ldc + n0 + c4;
            if (EP == 2) {
                float4 old = *(float4*)p;
                v.x += old.x; v.y += old.y; v.z += old.z; v.w += old.w;
            }
            *(float4*)p = v;
        }
    }
}

// ======================= transpose + split convert (improved) ===============
// src: per-expert [K][N] fp32 -> th/tl: per-expert [N][K] fp16 hi/lo.
// Phase 2: each thread converts 4 consecutive k for one n -> 8B vector stores.
__global__ void convT(const float* __restrict__ src, long long sExp, int K, int N,
                      fp16* __restrict__ th, fp16* __restrict__ tl, long long tExp) {
    __shared__ float t[32][33];
    int e = blockIdx.z;
    int k0 = blockIdx.x * 32, nn0 = blockIdx.y * 32;
    int tx = threadIdx.x & 31;
    int ty = threadIdx.x >> 5;            // 0..7
    const float* sp = src + (size_t)e * sExp;
#pragma unroll
    for (int r = 0; r < 4; r++) {
        int k = k0 + ty + r * 8;
        t[ty + r * 8][tx] = sp[(size_t)k * N + nn0 + tx];
    }
    __syncthreads();
    // 256 threads x 4 elems: thread handles n = tid>>3, kq = (tid&7)*4
    {
        int n = threadIdx.x >> 3;
        int kq = (threadIdx.x & 7) * 4;
        float v0 = t[kq + 0][n], v1 = t[kq + 1][n];
        float v2 = t[kq + 2][n], v3 = t[kq + 3][n];
        __half2 h0 = __floats2half2_rn(v0, v1);
        __half2 h1 = __floats2half2_rn(v2, v3);
        float2 r0 = __half22float2(h0), r1 = __half22float2(h1);
        __half2 l0 = __floats2half2_rn(v0 - r0.x, v1 - r0.y);
        __half2 l1 = __floats2half2_rn(v2 - r1.x, v3 - r1.y);
        size_t o = (size_t)e * tExp + (size_t)(nn0 + n) * K + k0 + kq;
        *(uint2*)(th + o) = make_uint2(*(unsigned*)&h0, *(unsigned*)&h1);
        *(uint2*)(tl + o) = make_uint2(*(unsigned*)&l0, *(unsigned*)&l1);
    }
}

// ======================= pack Wq/Wk/Wv -> transposed fp16 planes [3C][C] ======
__global__ void pack_qkvT(const float* __restrict__ Wq,
                          const float* __restrict__ Wk,
                          const float* __restrict__ Wv,
                          fp16* __restrict__ th, fp16* __restrict__ tl) {
    int j = blockIdx.x;
    int which = j / CDIM, hs = j % CDIM;
    int h = hs / HSD, s = hs % HSD;
    const float* W = (which == 0) ? Wq : ((which == 1) ? Wk : Wv);
    for (int c = threadIdx.x; c < CDIM; c += 256) {
        float v = W[((size_t)h * CDIM + c) * HSD + s];
        fp16 hi = __float2half_rn(v);
        size_t o = (size_t)j * CDIM + c;
        th[o] = hi;
        tl[o] = __float2half_rn(v - __half2float(hi));
    }
}

// ======================= embedding =======================
__global__ void embed_kernel(const int* __restrict__ idx,
                             const float* __restrict__ tok,
                             const float* __restrict__ pos,
                             float* __restrict__ x) {
    int n = blockIdx.x;
    int t = n % TSEQ;
    int v = idx[n];
    for (int c = threadIdx.x; c < CDIM; c += blockDim.x)
        x[n * CDIM + c] = tok[v * CDIM + c] + pos[t * CDIM + c];
}

// ======================= layernorm (fp32 + fp16 hi/lo planes) ==============
__global__ void ln_kernel(const float* __restrict__ x,
                          const float* __restrict__ g,
                          const float* __restrict__ b,
                          float* __restrict__ out,
                          fp16* __restrict__ oh, fp16* __restrict__ ol) {
    int n = blockIdx.x;
    int tid = threadIdx.x;
    __shared__ float s1[256], s2[256];
    const float* xr = x + (size_t)n * CDIM;
    float a = 0.f, q = 0.f;
    for (int c = tid; c < CDIM; c += 256) { float v = xr[c]; a += v; q += v * v; }
    s1[tid] = a; s2[tid] = q;
    __syncthreads();
    for (int s = 128; s > 0; s >>= 1) {
        if (tid < s) { s1[tid] += s1[tid + s]; s2[tid] += s2[tid + s]; }
        __syncthreads();
    }
    float mean = s1[0] * (1.f / CDIM);
    float var  = s2[0] * (1.f / CDIM) - mean * mean;
    float r = rsqrtf(var + 1e-5f);
    for (int c = tid; c < CDIM; c += 256) {
        float o = (xr[c] - mean) * r * g[c] + b[c];
        size_t p = (size_t)n * CDIM + c;
        out[p] = o;
        fp16 hi = __float2half_rn(o);
        oh[p] = hi;
        ol[p] = __float2half_rn(o - __half2float(hi));
    }
}

// ======================= attention =======================
__global__ void attn_kernel(const float* __restrict__ qkv,
                            fp16* __restrict__ atth, fp16* __restrict__ attl) {
    int t = blockIdx.x, h = blockIdx.y, b = blockIdx.z;
    int tid = threadIdx.x;
    __shared__ float sc[TSEQ];
    __shared__ float qs[HSD];
    __shared__ float red[128];
    __shared__ float part[5 * HSD];

    int n0 = b * TSEQ;
    const float* Q = qkv + (size_t)(n0 + t) * (3 * CDIM) + h * HSD;
    if (tid < HSD) qs[tid] = Q[tid];
    __syncthreads();

    const float scale = 0.20412414523193154f;
    float lmax = -1e30f;
    for (int u = tid; u <= t; u += 128) {
        const float* Kp = qkv + (size_t)(n0 + u) * (3 * CDIM) + CDIM + h * HSD;
        float d = 0.f;
#pragma unroll
        for (int s = 0; s < HSD; s++) d += qs[s] * Kp[s];
        d *= scale;
        sc[u] = d;
        lmax = fmaxf(lmax, d);
    }
    red[tid] = lmax;
    __syncthreads();
    for (int s = 64; s > 0; s >>= 1) {
        if (tid < s) red[tid] = fmaxf(red[tid], red[tid + s]);
        __syncthreads();
    }
    float mx = red[0];
    __syncthreads();

    float lsum = 0.f;
    for (int u = tid; u <= t; u += 128) {
        float ev = expf(sc[u] - mx);
        sc[u] = ev;
        lsum += ev;
    }
    red[tid] = lsum;
    __syncthreads();
    for (int s = 64; s > 0; s >>= 1) {
        if (tid < s) red[tid] += red[tid + s];
        __syncthreads();
    }
    float inv = 1.f / red[0];
    __syncthreads();

    if (tid < 120) {
        int s = tid % HSD, gg = tid / HSD;
        float a = 0.f;
        for (int u = gg; u <= t; u += 5) {
            const float* Vp = qkv + (size_t)(n0 + u) * (3 * CDIM) + 2 * CDIM + h * HSD;
            a += sc[u] * Vp[s];
        }
        part[gg * HSD + s] = a;
    }
    __syncthreads();
    if (tid < HSD) {
        float a = (part[tid] + part[HSD + tid] + part[2 * HSD + tid]
                 + part[3 * HSD + tid] + part[4 * HSD + tid]) * inv;
        size_t o = (size_t)(n0 + t) * CDIM + h * HSD + tid;
        fp16 hi = __float2half_rn(a);
        atth[o] = hi;
        attl[o] = __float2half_rn(a - __half2float(hi));
    }
}

// ======================= gate softmax =======================
__global__ void gate_kernel(const float* __restrict__ h2,
                            const float* __restrict__ gw,
                            const float* __restrict__ gb,
                            float* __restrict__ gates) {
    int n = blockIdx.x;
    int e = threadIdx.x;
    const float* hr = h2 + (size_t)n * CDIM;
    float acc = gb[e];
    for (int c = 0; c < CDIM; c++) acc += hr[c] * gw[c * NE + e];
    float mx = acc;
    for (int o = 16; o > 0; o >>= 1) mx = fmaxf(mx, __shfl_xor_sync(0xFFFFFFFFu, mx, o));
    float ex = expf(acc - mx);
    float sm = ex;
    for (int o = 16; o > 0; o >>= 1) sm += __shfl_xor_sync(0xFFFFFFFFu, sm, o);
    gates[n * NE + e] = ex / sm;
}

// ======================= MoE combine =======================
__global__ void combine_kernel(const float* __restrict__ eo,
                               const float* __restrict__ gates,
                               float* __restrict__ x) {
    int n = blockIdx.x;
    __shared__ float gs[NE];
    if (threadIdx.x < NE) gs[threadIdx.x] = gates[n * NE + threadIdx.x];
    __syncthreads();
    for (int c = threadIdx.x; c < CDIM; c += blockDim.x) {
        float a = 0.f;
        const float* er = eo + (size_t)n * (NE * CDIM) + c;
#pragma unroll 8
        for (int e = 0; e < NE; e++) a += gs[e] * er[e * CDIM];
        x[(size_t)n * CDIM + c] += a;
    }
}

// ======================= scalar SGEMM (lm head only) =======================
__global__ void __launch_bounds__(256)
lm_head_kernel(const float* __restrict__ A, const float* __restrict__ B,
               const float* __restrict__ bias, float* __restrict__ C,
               int M, int N, int K) {
    __shared__ float As[64][17];
    __shared__ float Bs[16][64];
    int tid = threadIdx.x;
    int jTile = blockIdx.x * 64;
    int mTile = blockIdx.y * 64;
    int tx = tid & 15, ty = tid >> 4;

    float acc[4][4];
#pragma unroll
    for (int r = 0; r < 4; r++)
#pragma unroll
        for (int c = 0; c < 4; c++) acc[r][c] = 0.f;

    int aRow = tid >> 2, aK = (tid & 3) * 4;
    int bJ = tid & 63, bK0 = tid >> 6;

    for (int k0 = 0; k0 < K; k0 += 16) {
        int m = mTile + aRow;
        if (m < M) {
            float4 av = *(const float4*)(A + (size_t)m * K + k0 + aK);
            As[aRow][aK + 0] = av.x; As[aRow][aK + 1] = av.y;
            As[aRow][aK + 2] = av.z; As[aRow][aK + 3] = av.w;
        } else {
            As[aRow][aK + 0] = 0.f; As[aRow][aK + 1] = 0.f;
            As[aRow][aK + 2] = 0.f; As[aRow][aK + 3] = 0.f;
        }
#pragma unroll
        for (int i = 0; i < 4; i++) {
            int kk = bK0 + i * 4;
            Bs[kk][bJ] = (jTile + bJ < N)
                ? B[(size_t)(k0 + kk) * N + jTile + bJ] : 0.f;
        }
        __syncthreads();
#pragma unroll
        for (int k = 0; k < 16; k++) {
            float4 bv = *(const float4*)&Bs[k][tx * 4];
            float a0 = As[ty * 4 + 0][k], a1 = As[ty * 4 + 1][k];
            float a2 = As[ty * 4 + 2][k], a3 = As[ty * 4 + 3][k];
            acc[0][0] += a0 * bv.x; acc[0][1] += a0 * bv.y; acc[0][2] += a0 * bv.z; acc[0][3] += a0 * bv.w;
            acc[1][0] += a1 * bv.x; acc[1][1] += a1 * bv.y; acc[1][2] += a1 * bv.z; acc[1][3] += a1 * bv.w;
            acc[2][0] += a2 * bv.x; acc[2][1] += a2 * bv.y; acc[2][2] += a2 * bv.z; acc[2][3] += a2 * bv.w;
            acc[3][0] += a3 * bv.x; acc[3][1] += a3 * bv.y; acc[3][2] += a3 * bv.z; acc[3][3] += a3 * bv.w;
        }
        __syncthreads();
    }
#pragma unroll
    for (int r = 0; r < 4; r++) {
        int m = mTile + ty * 4 + r;
        if (m >= M) continue;
#pragma unroll
        for (int c = 0; c < 4; c++) {
            int j = jTile + tx * 4 + c;
            if (j >= N) continue;
            C[(size_t)m * N + j] = acc[r][c] + bias[j];
        }
    }
}

// ======================= launch =======================
extern "C" void kernel_launch(void* const* d_in, const int* in_sizes, int n_in,
                              void* d_out, int out_size) {
    const int*   idx    = (const int*)  d_in[0];
    const float* tok    = (const float*)d_in[1];
    const float* pos    = (const float*)d_in[2];
    const float* ln1_g  = (const float*)d_in[3];
    const float* ln1_b  = (const float*)d_in[4];
    const float* Wq     = (const float*)d_in[5];
    const float* Wk     = (const float*)d_in[6];
    const float* Wv     = (const float*)d_in[7];
    const float* Wo     = (const float*)d_in[8];
    const float* bo     = (const float*)d_in[9];
    const float* ln2_g  = (const float*)d_in[10];
    const float* ln2_b  = (const float*)d_in[11];
    const float* gate_w = (const float*)d_in[12];
    const float* gate_b = (const float*)d_in[13];
    const float* W1     = (const float*)d_in[14];
    const float* b1     = (const float*)d_in[15];
    const float* W2     = (const float*)d_in[16];
    const float* b2     = (const float*)d_in[17];
    const float* lnf_g  = (const float*)d_in[18];
    const float* lnf_b  = (const float*)d_in[19];
    const float* lm_w   = (const float*)d_in[20];
    const float* lm_b   = (const float*)d_in[21];
    float* out = (float*)d_out;

    float *x, *h, *qkv, *gates, *eo;
    fp16 *hh, *hl, *atth, *attl, *wpth, *wptl, *woth, *wotl;
    fp16 *w1th, *w1tl, *w2th, *w2tl, *hidh;
    cudaGetSymbolAddress((void**)&x,     g_x);
    cudaGetSymbolAddress((void**)&h,     g_h);
    cudaGetSymbolAddress((void**)&qkv,   g_qkv);
    cudaGetSymbolAddress((void**)&gates, g_gates);
    cudaGetSymbolAddress((void**)&eo,    g_eo);
    cudaGetSymbolAddress((void**)&hh,    g_hh);
    cudaGetSymbolAddress((void**)&hl,    g_hl);
    cudaGetSymbolAddress((void**)&atth,  g_atth);
    cudaGetSymbolAddress((void**)&attl,  g_attl);
    cudaGetSymbolAddress((void**)&wpth,  g_wpth);
    cudaGetSymbolAddress((void**)&wptl,  g_wptl);
    cudaGetSymbolAddress((void**)&woth,  g_woth);
    cudaGetSymbolAddress((void**)&wotl,  g_wotl);
    cudaGetSymbolAddress((void**)&w1th,  g_w1th);
    cudaGetSymbolAddress((void**)&w1tl,  g_w1tl);
    cudaGetSymbolAddress((void**)&w2th,  g_w2th);
    cudaGetSymbolAddress((void**)&w2tl,  g_w2tl);
    cudaGetSymbolAddress((void**)&hidh,  g_hidh);

    cudaFuncSetAttribute(mma_gemm<0,3>, cudaFuncAttributeMaxDynamicSharedMemorySize, SMEM_NT3);
    cudaFuncSetAttribute(mma_gemm<2,3>, cudaFuncAttributeMaxDynamicSharedMemorySize, SMEM_NT3);
    cudaFuncSetAttribute(mma_gemm<3,2>, cudaFuncAttributeMaxDynamicSharedMemorySize, SMEM_NT2);
    cudaFuncSetAttribute(mma_gemm<1,2>, cudaFuncAttributeMaxDynamicSharedMemorySize, SMEM_NT2);

    const int MT = (NTOK + 127) / 128;   // 7

    // ---- pre-convert all weights (transpose + fp16 hi/lo split) ----
    for (int l = 0; l < NL; l++) {
        convT<<<dim3(CDIM / 32, F4D / 32, NE), 256>>>(
            W1 + (size_t)l * NE * CDIM * F4D, (long long)CDIM * F4D, CDIM, F4D,
            w1th + (size_t)l * NE * F4D * CDIM, w1tl + (size_t)l * NE * F4D * CDIM,
            (long long)F4D * CDIM);
        convT<<<dim3(F4D / 32, CDIM / 32, NE), 256>>>(
            W2 + (size_t)l * NE * F4D * CDIM, (long long)F4D * CDIM, F4D, CDIM,
            w2th + (size_t)l * NE * CDIM * F4D, w2tl + (size_t)l * NE * CDIM * F4D,
            (long long)CDIM * F4D);
        convT<<<dim3(CDIM / 32, CDIM / 32, 1), 256>>>(
            Wo + (size_t)l * CDIM * CDIM, 0, CDIM, CDIM,
            woth + (size_t)l * CDIM * CDIM, wotl + (size_t)l * CDIM * CDIM, 0);
    }

    embed_kernel<<<NTOK, 256>>>(idx, tok, pos, x);

    for (int l = 0; l < NL; l++) {
        // --- attention ---
        ln_kernel<<<NTOK, 256>>>(x, ln1_g + l * CDIM, ln1_b + l * CDIM, h, hh, hl);
        pack_qkvT<<<3 * CDIM, 256>>>(
            Wq + (size_t)l * NH * CDIM * HSD,
            Wk + (size_t)l * NH * CDIM * HSD,
            Wv + (size_t)l * NH * CDIM * HSD, wpth, wptl);
        mma_gemm<0,3><<<dim3(MT * 18, 1), 256, SMEM_NT3>>>(
            hh, hl, CDIM, 0, wpth, wptl, CDIM, 0,
            nullptr, 0, qkv, nullptr, 3 * CDIM, 0,
            NTOK, 18, CDIM / 32);
        attn_kernel<<<dim3(TSEQ, NH, BSZ), 128>>>(qkv, atth, attl);
        mma_gemm<2,3><<<dim3(MT * 6, 1), 256, SMEM_NT3>>>(
            atth, attl, CDIM, 0,
            woth + (size_t)l * CDIM * CDIM, wotl + (size_t)l * CDIM * CDIM, CDIM, 0,
            bo + l * CDIM, 0, x, nullptr, CDIM, 0,
            NTOK, 6, CDIM / 32);

        // --- MoE ---
        ln_kernel<<<NTOK, 256>>>(x, ln2_g + l * CDIM, ln2_b + l * CDIM, h, hh, hl);
        gate_kernel<<<NTOK, 32>>>(h, gate_w + (size_t)l * CDIM * NE,
                                  gate_b + l * NE, gates);
        // up: hid = gelu(h @ W1_e + b1_e) -> fp16 hi plane
        mma_gemm<3,2><<<dim3(MT * (F4D / 128), NE), 256, SMEM_NT2>>>(
            hh, nullptr, CDIM, 0,
            w1th + (size_t)l * NE * F4D * CDIM, w1tl + (size_t)l * NE * F4D * CDIM,
            CDIM, (long long)F4D * CDIM,
            b1 + (size_t)l * NE * F4D, F4D,
            nullptr, hidh, (long long)NE * F4D, F4D,
            NTOK, F4D / 128, CDIM / 32);
        // down: eo = hid_e @ W2_e + b2_e
        mma_gemm<1,2><<<dim3(MT * (CDIM / 128), NE), 256, SMEM_NT2>>>(
            hidh, nullptr, (long long)NE * F4D, F4D,
            w2th + (size_t)l * NE * CDIM * F4D, w2tl + (size_t)l * NE * CDIM * F4D,
            F4D, (long long)CDIM * F4D,
            b2 + (size_t)l * NE * CDIM, CDIM,
            eo, nullptr, (long long)NE * CDIM, CDIM,
            NTOK, CDIM / 128, F4D / 32);
        combine_kernel<<<NTOK, 256>>>(eo, gates, x);
    }

    // --- final LN + lm head ---
    ln_kernel<<<NTOK, 256>>>(x, lnf_g, lnf_b, h, hh, hl);
    lm_head_kernel<<<dim3((NV + 63) / 64, (NTOK + 63) / 64), 256>>>(
        h, lm_w, lm_b, out, NTOK, NV, CDIM);
}

// round 9
// speedup vs baseline: 1.5282x; 1.0743x over previous
#include <cuda_runtime.h>
#include <cuda_fp16.h>
#include <math.h>
#include <stdint.h>

// ---- problem constants ----
#define NTOK 844      // B*T = 2*422
#define TSEQ 422
#define BSZ  2
#define CDIM 768
#define NH   32
#define HSD  24
#define NE   32
#define F4D  3072
#define NL   2
#define NV   100

typedef __half fp16;

// ---- device scratch ----
__device__ float g_x  [NTOK * CDIM];
__device__ float g_h  [NTOK * CDIM];
__device__ float g_qkv[NTOK * 3 * CDIM];
__device__ float g_gates[NTOK * NE];
__device__ float g_eo [(size_t)NTOK * NE * CDIM];

__device__ fp16 g_hh [NTOK * CDIM],  g_hl [NTOK * CDIM];
__device__ fp16 g_atth[NTOK * CDIM], g_attl[NTOK * CDIM];
__device__ fp16 g_wpth[3 * CDIM * CDIM], g_wptl[3 * CDIM * CDIM];
__device__ fp16 g_woth[NL * CDIM * CDIM], g_wotl[NL * CDIM * CDIM];
__device__ fp16 g_w1th[(size_t)NL * NE * F4D * CDIM];
__device__ fp16 g_w1tl[(size_t)NL * NE * F4D * CDIM];
__device__ fp16 g_w2th[(size_t)NL * NE * CDIM * F4D];
__device__ fp16 g_w2tl[(size_t)NL * NE * CDIM * F4D];
__device__ fp16 g_hidh[(size_t)NTOK * NE * F4D];

// ======================= helpers =======================
__device__ __forceinline__ float gelu_exact(float v) {
    return 0.5f * v * (1.f + erff(v * 0.70710678118654752f));
}

__device__ __forceinline__ void mma16816(float* d, const unsigned* a, const unsigned* b) {
    asm volatile(
        "mma.sync.aligned.m16n8k16.row.col.f32.f16.f16.f32 "
        "{%0,%1,%2,%3}, {%4,%5,%6,%7}, {%8,%9}, {%0,%1,%2,%3};"
        : "+f"(d[0]), "+f"(d[1]), "+f"(d[2]), "+f"(d[3])
        : "r"(a[0]), "r"(a[1]), "r"(a[2]), "r"(a[3]), "r"(b[0]), "r"(b[1]));
}

__device__ __forceinline__ void cpa16(unsigned s, const void* g, int sz) {
    asm volatile("cp.async.cg.shared.global [%0], [%1], 16, %2;"
                 :: "r"(s), "l"(g), "r"(sz));
}
#define CPA_COMMIT() asm volatile("cp.async.commit_group;" ::: "memory")
#define CPA_WAIT(n)  asm volatile("cp.async.wait_group %0;" :: "n"(n) : "memory")

#define LDSM4(r0, r1, r2, r3, addr)                                            \
    asm volatile("ldmatrix.sync.aligned.m8n8.x4.shared.b16 {%0,%1,%2,%3}, [%4];" \
        : "=r"(r0), "=r"(r1), "=r"(r2), "=r"(r3) : "r"(addr))

// ======================= NT3 GEMM (attention paths, K-chunk 32) =============
#define STR 40                     // smem row stride (elems); 80B rows
#define PLANE_B (128 * 80)         // 10240
#define SMEM_NT3 81920             // 2 stages * 4 planes

template <int EP>
__global__ void __launch_bounds__(256, 2)
mma_gemm3(const fp16* __restrict__ Ah, const fp16* __restrict__ Al,
          long long lda,
          const fp16* __restrict__ Bh, const fp16* __restrict__ Bl,
          long long ldb,
          const float* __restrict__ bias,
          float* __restrict__ Cf, long long ldc,
          int M, int Ntiles, int KC) {
    constexpr unsigned STAGE_B = 4 * PLANE_B;
    extern __shared__ char smc[];
    unsigned smbase;
    asm("{ .reg .u64 t; cvta.to.shared.u64 t, %1; cvt.u32.u64 %0, t; }"
        : "=r"(smbase) : "l"(smc));

    const int tid = threadIdx.x, wid = tid >> 5, lane = tid & 31;
    const int g = lane >> 2, tg = lane & 3;
    const int wm = wid >> 2, wn = wid & 3;
    const int nt = blockIdx.x % Ntiles, mt = blockIdx.x / Ntiles;
    const int n0 = nt * 128, m0 = mt * 128;

    const int s4 = lane >> 3, lr = lane & 7;
    const int aRowL = lr + (s4 & 1) * 8, aColL = (s4 >> 1) * 8;
    const int bRowL = lr + (s4 >> 1) * 8, bColL = (s4 & 1) * 8;

    float acc[4][4][4];
#pragma unroll
    for (int i = 0; i < 4; i++)
#pragma unroll
        for (int j = 0; j < 4; j++)
#pragma unroll
            for (int r = 0; r < 4; r++) acc[i][j][r] = 0.f;

    const int fRow = tid >> 2, fCh = tid & 3;

    auto issue = [&](int c) {
        const int k0 = c * 32;
        unsigned sb = smbase + (c & 1) * STAGE_B;
#pragma unroll
        for (int i = 0; i < 2; i++) {
            int row = fRow + i * 64;
            int m = m0 + row;
            int sz = (m < M) ? 16 : 0;
            size_t go = (size_t)(m < M ? m : 0) * lda + k0 + fCh * 8;
            unsigned so = sb + row * 80 + fCh * 16;
            cpa16(so, Ah + go, sz);
            cpa16(so + PLANE_B, Al + go, sz);
        }
#pragma unroll
        for (int i = 0; i < 2; i++) {
            int row = fRow + i * 64;
            size_t go = (size_t)(n0 + row) * ldb + k0 + fCh * 8;
            unsigned so = sb + 2 * PLANE_B + row * 80 + fCh * 16;
            cpa16(so, Bh + go, 16);
            cpa16(so + PLANE_B, Bl + go, 16);
        }
    };

    issue(0);
    CPA_COMMIT();

    for (int c = 0; c < KC; ++c) {
        if (c + 1 < KC) { issue(c + 1); CPA_COMMIT(); CPA_WAIT(1); }
        else            { CPA_WAIT(0); }
        __syncthreads();

        unsigned sb = smbase + (c & 1) * STAGE_B;
#pragma unroll
        for (int ks = 0; ks < 2; ks++) {
            const int kb = ks * 16;
            unsigned bh_[4][2], bl_[4][2];
#pragma unroll
            for (int p = 0; p < 2; p++) {
                int rn0 = wn * 32 + p * 16;
                unsigned ba = sb + 2 * PLANE_B +
                              (unsigned)((rn0 + bRowL) * STR + kb + bColL) * 2;
                LDSM4(bh_[2 * p][0], bh_[2 * p][1], bh_[2 * p + 1][0], bh_[2 * p + 1][1], ba);
                LDSM4(bl_[2 * p][0], bl_[2 * p][1], bl_[2 * p + 1][0], bl_[2 * p + 1][1],
                      ba + PLANE_B);
            }
#pragma unroll
            for (int mi = 0; mi < 4; mi++) {
                int rm0 = wm * 64 + mi * 16;
                unsigned aa = sb + (unsigned)((rm0 + aRowL) * STR + kb + aColL) * 2;
                unsigned ah_[4], al_[4];
                LDSM4(ah_[0], ah_[1], ah_[2], ah_[3], aa);
                LDSM4(al_[0], al_[1], al_[2], al_[3], aa + PLANE_B);
#pragma unroll
                for (int ni = 0; ni < 4; ni++) {
                    mma16816(acc[mi][ni], ah_, bh_[ni]);
                    mma16816(acc[mi][ni], ah_, bl_[ni]);
                    mma16816(acc[mi][ni], al_, bh_[ni]);
                }
            }
        }
        __syncthreads();
    }

    // ---- epilogue ----
    float* sOut = (float*)smc;
#pragma unroll
    for (int mi = 0; mi < 4; mi++) {
        int lrow = wm * 64 + mi * 16 + g;
#pragma unroll
        for (int ni = 0; ni < 4; ni++) {
            int j = wn * 32 + ni * 8 + tg * 2;
            float b0 = 0.f, b1 = 0.f;
            if (EP >= 1) { b0 = bias[n0 + j]; b1 = bias[n0 + j + 1]; }
#pragma unroll
            for (int hh = 0; hh < 2; hh++) {
                float v0 = acc[mi][ni][hh * 2 + 0] + b0;
                float v1 = acc[mi][ni][hh * 2 + 1] + b1;
                *(float2*)&sOut[(lrow + hh * 8) * 132 + j] = make_float2(v0, v1);
            }
        }
    }
    __syncthreads();
#pragma unroll
    for (int i = 0; i < 16; i++) {
        int item = tid + i * 256;
        int row = item >> 5;
        int c4 = (item & 31) * 4;
        int m = m0 + row;
        if (m >= M) continue;
        float4 v = *(float4*)&sOut[row * 132 + c4];
        float* p = Cf + (size_t)m * ldc + n0 + c4;
        if (EP == 2) {
            float4 old = *(float4*)p;
            v.x += old.x; v.y += old.y; v.z += old.z; v.w += old.w;
        }
        *(float4*)p = v;
    }
}

// ======================= NT2 MoE GEMM (K-chunk 64) ==========================
#define STR64 72                   // smem row stride elems (144B), conflict-free
#define PL64 (128 * 144)           // 18432 bytes per plane
#define STAGE64 (3 * PL64)         // 55296
#define SMEM_K64 (2 * STAGE64)     // 110592

template <int EP>
__global__ void __launch_bounds__(256, 2)
mma_gemm64(const fp16* __restrict__ Ah, long long lda, long long aExp,
           const fp16* __restrict__ Bh, const fp16* __restrict__ Bl,
           long long ldb, long long bExp,
           const float* __restrict__ bias, long long biasExp,
           float* __restrict__ Cf, fp16* __restrict__ Ch,
           long long ldc, long long cExp,
           int M, int Ntiles, int KC) {
    extern __shared__ char smc[];
    unsigned smbase;
    asm("{ .reg .u64 t; cvta.to.shared.u64 t, %1; cvt.u32.u64 %0, t; }"
        : "=r"(smbase) : "l"(smc));

    const int tid = threadIdx.x, wid = tid >> 5, lane = tid & 31;
    const int g = lane >> 2, tg = lane & 3;
    const int wm = wid >> 2, wn = wid & 3;
    const int e = blockIdx.y;
    const int nt = blockIdx.x % Ntiles, mt = blockIdx.x / Ntiles;
    const int n0 = nt * 128, m0 = mt * 128;

    const fp16* Abh = Ah + (size_t)e * aExp;
    const fp16* Bbh = Bh + (size_t)e * bExp;
    const fp16* Bbl = Bl + (size_t)e * bExp;

    const int s4 = lane >> 3, lr = lane & 7;
    const int aRowL = lr + (s4 & 1) * 8, aColL = (s4 >> 1) * 8;
    const int bRowL = lr + (s4 >> 1) * 8, bColL = (s4 & 1) * 8;

    float acc[4][4][4];
#pragma unroll
    for (int i = 0; i < 4; i++)
#pragma unroll
        for (int j = 0; j < 4; j++)
#pragma unroll
            for (int r = 0; r < 4; r++) acc[i][j][r] = 0.f;

    const int fRow = tid >> 3, fC8 = tid & 7;    // 128 rows x 8 chunks of 16B

    auto issue = [&](int c) {
        const int k0 = c * 64;
        unsigned sb = smbase + (c & 1) * STAGE64;
        // A hi plane: 128 rows x 128B
#pragma unroll
        for (int i = 0; i < 4; i++) {
            int item = tid + i * 256;
            int row = item >> 3, c8 = item & 7;
            int m = m0 + row;
            int sz = (m < M) ? 16 : 0;
            size_t go = (size_t)(m < M ? m : 0) * lda + k0 + c8 * 8;
            cpa16(sb + row * 144 + c8 * 16, Abh + go, sz);
        }
        // B hi + lo planes
#pragma unroll
        for (int i = 0; i < 4; i++) {
            int item = tid + i * 256;
            int row = item >> 3, c8 = item & 7;
            size_t go = (size_t)(n0 + row) * ldb + k0 + c8 * 8;
            unsigned so = sb + PL64 + row * 144 + c8 * 16;
            cpa16(so, Bbh + go, 16);
            cpa16(so + PL64, Bbl + go, 16);
        }
    };

    issue(0);
    CPA_COMMIT();

    for (int c = 0; c < KC; ++c) {
        if (c + 1 < KC) { issue(c + 1); CPA_COMMIT(); CPA_WAIT(1); }
        else            { CPA_WAIT(0); }
        __syncthreads();

        unsigned sb = smbase + (c & 1) * STAGE64;
        unsigned sbB = sb + PL64;
#pragma unroll
        for (int ks = 0; ks < 4; ks++) {
            const int kb = ks * 16;
            unsigned bh_[4][2], bl_[4][2];
#pragma unroll
            for (int p = 0; p < 2; p++) {
                int rn0 = wn * 32 + p * 16;
                unsigned ba = sbB + (unsigned)((rn0 + bRowL) * STR64 + kb + bColL) * 2;
                LDSM4(bh_[2 * p][0], bh_[2 * p][1], bh_[2 * p + 1][0], bh_[2 * p + 1][1], ba);
                LDSM4(bl_[2 * p][0], bl_[2 * p][1], bl_[2 * p + 1][0], bl_[2 * p + 1][1],
                      ba + PL64);
            }
#pragma unroll
            for (int mi = 0; mi < 4; mi++) {
                int rm0 = wm * 64 + mi * 16;
                unsigned aa = sb + (unsigned)((rm0 + aRowL) * STR64 + kb + aColL) * 2;
                unsigned ah_[4];
                LDSM4(ah_[0], ah_[1], ah_[2], ah_[3], aa);
#pragma unroll
                for (int ni = 0; ni < 4; ni++) {
                    mma16816(acc[mi][ni], ah_, bh_[ni]);
                    mma16816(acc[mi][ni], ah_, bl_[ni]);
                }
            }
        }
        __syncthreads();
    }

    // ---- epilogue: regs -> smem -> coalesced gmem ----
    float* sOut = (float*)smc;
#pragma unroll
    for (int mi = 0; mi < 4; mi++) {
        int lrow = wm * 64 + mi * 16 + g;
#pragma unroll
        for (int ni = 0; ni < 4; ni++) {
            int j = wn * 32 + ni * 8 + tg * 2;
            float b0 = bias[(size_t)e * biasExp + n0 + j];
            float b1 = bias[(size_t)e * biasExp + n0 + j + 1];
#pragma unroll
            for (int hh = 0; hh < 2; hh++) {
                float v0 = acc[mi][ni][hh * 2 + 0] + b0;
                float v1 = acc[mi][ni][hh * 2 + 1] + b1;
                if (EP == 3) { v0 = gelu_exact(v0); v1 = gelu_exact(v1); }
                *(float2*)&sOut[(lrow + hh * 8) * 132 + j] = make_float2(v0, v1);
            }
        }
    }
    __syncthreads();

    if (EP == 3) {
#pragma unroll
        for (int i = 0; i < 8; i++) {
            int item = tid + i * 256;
            int row = item >> 4;
            int c8 = (item & 15) * 8;
            int m = m0 + row;
            if (m >= M) continue;
            float4 f0 = *(float4*)&sOut[row * 132 + c8];
            float4 f1 = *(float4*)&sOut[row * 132 + c8 + 4];
            __half2 h0 = __floats2half2_rn(f0.x, f0.y);
            __half2 h1 = __floats2half2_rn(f0.z, f0.w);
            __half2 h2 = __floats2half2_rn(f1.x, f1.y);
            __half2 h3 = __floats2half2_rn(f1.z, f1.w);
            uint4 u = make_uint4(*(unsigned*)&h0, *(unsigned*)&h1,
                                 *(unsigned*)&h2, *(unsigned*)&h3);
            *(uint4*)(Ch + (size_t)e * cExp + (size_t)m * ldc + n0 + c8) = u;
        }
    } else {
#pragma unroll
        for (int i = 0; i < 16; i++) {
            int item = tid + i * 256;
            int row = item >> 5;
            int c4 = (item & 31) * 4;
            int m = m0 + row;
            if (m >= M) continue;
            float4 v = *(float4*)&sOut[row * 132 + c4];
            *(float4*)(Cf + (size_t)e * cExp + (size_t)m * ldc + n0 + c4) = v;
        }
    }
}

// ======================= transpose + split convert ==========================
__global__ void convT(const float* __restrict__ src, long long sExp, int K, int N,
                      fp16* __restrict__ th, fp16* __restrict__ tl, long long tExp) {
    __shared__ float t[32][33];
    int e = blockIdx.z;
    int k0 = blockIdx.x * 32, nn0 = blockIdx.y * 32;
    int tx = threadIdx.x & 31;
    int ty = threadIdx.x >> 5;
    const float* sp = src + (size_t)e * sExp;
#pragma unroll
    for (int r = 0; r < 4; r++) {
        int k = k0 + ty + r * 8;
        t[ty + r * 8][tx] = sp[(size_t)k * N + nn0 + tx];
    }
    __syncthreads();
    {
        int n = threadIdx.x >> 3;
        int kq = (threadIdx.x & 7) * 4;
        float v0 = t[kq + 0][n], v1 = t[kq + 1][n];
        float v2 = t[kq + 2][n], v3 = t[kq + 3][n];
        __half2 h0 = __floats2half2_rn(v0, v1);
        __half2 h1 = __floats2half2_rn(v2, v3);
        float2 r0 = __half22float2(h0), r1 = __half22float2(h1);
        __half2 l0 = __floats2half2_rn(v0 - r0.x, v1 - r0.y);
        __half2 l1 = __floats2half2_rn(v2 - r1.x, v3 - r1.y);
        size_t o = (size_t)e * tExp + (size_t)(nn0 + n) * K + k0 + kq;
        *(uint2*)(th + o) = make_uint2(*(unsigned*)&h0, *(unsigned*)&h1);
        *(uint2*)(tl + o) = make_uint2(*(unsigned*)&l0, *(unsigned*)&l1);
    }
}

// ======================= pack Wq/Wk/Wv -> transposed fp16 planes [3C][C] ======
__global__ void pack_qkvT(const float* __restrict__ Wq,
                          const float* __restrict__ Wk,
                          const float* __restrict__ Wv,
                          fp16* __restrict__ th, fp16* __restrict__ tl) {
    int j = blockIdx.x;
    int which = j / CDIM, hs = j % CDIM;
    int h = hs / HSD, s = hs % HSD;
    const float* W = (which == 0) ? Wq : ((which == 1) ? Wk : Wv);
    for (int c = threadIdx.x; c < CDIM; c += 256) {
        float v = W[((size_t)h * CDIM + c) * HSD + s];
        fp16 hi = __float2half_rn(v);
        size_t o = (size_t)j * CDIM + c;
        th[o] = hi;
        tl[o] = __float2half_rn(v - __half2float(hi));
    }
}

// ======================= embedding =======================
__global__ void embed_kernel(const int* __restrict__ idx,
                             const float* __restrict__ tok,
                             const float* __restrict__ pos,
                             float* __restrict__ x) {
    int n = blockIdx.x;
    int t = n % TSEQ;
    int v = idx[n];
    for (int c = threadIdx.x; c < CDIM; c += blockDim.x)
        x[n * CDIM + c] = tok[v * CDIM + c] + pos[t * CDIM + c];
}

// ======================= layernorm (fp32 + fp16 hi/lo planes) ==============
__global__ void ln_kernel(const float* __restrict__ x,
                          const float* __restrict__ g,
                          const float* __restrict__ b,
                          float* __restrict__ out,
                          fp16* __restrict__ oh, fp16* __restrict__ ol) {
    int n = blockIdx.x;
    int tid = threadIdx.x;
    __shared__ float s1[256], s2[256];
    const float* xr = x + (size_t)n * CDIM;
    float a = 0.f, q = 0.f;
    for (int c = tid; c < CDIM; c += 256) { float v = xr[c]; a += v; q += v * v; }
    s1[tid] = a; s2[tid] = q;
    __syncthreads();
    for (int s = 128; s > 0; s >>= 1) {
        if (tid < s) { s1[tid] += s1[tid + s]; s2[tid] += s2[tid + s]; }
        __syncthreads();
    }
    float mean = s1[0] * (1.f / CDIM);
    float var  = s2[0] * (1.f / CDIM) - mean * mean;
    float r = rsqrtf(var + 1e-5f);
    for (int c = tid; c < CDIM; c += 256) {
        float o = (xr[c] - mean) * r * g[c] + b[c];
        size_t p = (size_t)n * CDIM + c;
        out[p] = o;
        fp16 hi = __float2half_rn(o);
        oh[p] = hi;
        ol[p] = __float2half_rn(o - __half2float(hi));
    }
}

// ======================= attention =======================
__global__ void attn_kernel(const float* __restrict__ qkv,
                            fp16* __restrict__ atth, fp16* __restrict__ attl) {
    int t = blockIdx.x, h = blockIdx.y, b = blockIdx.z;
    int tid = threadIdx.x;
    __shared__ float sc[TSEQ];
    __shared__ float qs[HSD];
    __shared__ float red[128];
    __shared__ float part[5 * HSD];

    int n0 = b * TSEQ;
    const float* Q = qkv + (size_t)(n0 + t) * (3 * CDIM) + h * HSD;
    if (tid < HSD) qs[tid] = Q[tid];
    __syncthreads();

    const float scale = 0.20412414523193154f;
    float lmax = -1e30f;
    for (int u = tid; u <= t; u += 128) {
        const float* Kp = qkv + (size_t)(n0 + u) * (3 * CDIM) + CDIM + h * HSD;
        float d = 0.f;
#pragma unroll
        for (int s = 0; s < HSD; s++) d += qs[s] * Kp[s];
        d *= scale;
        sc[u] = d;
        lmax = fmaxf(lmax, d);
    }
    red[tid] = lmax;
    __syncthreads();
    for (int s = 64; s > 0; s >>= 1) {
        if (tid < s) red[tid] = fmaxf(red[tid], red[tid + s]);
        __syncthreads();
    }
    float mx = red[0];
    __syncthreads();

    float lsum = 0.f;
    for (int u = tid; u <= t; u += 128) {
        float ev = expf(sc[u] - mx);
        sc[u] = ev;
        lsum += ev;
    }
    red[tid] = lsum;
    __syncthreads();
    for (int s = 64; s > 0; s >>= 1) {
        if (tid < s) red[tid] += red[tid + s];
        __syncthreads();
    }
    float inv = 1.f / red[0];
    __syncthreads();

    if (tid < 120) {
        int s = tid % HSD, gg = tid / HSD;
        float a = 0.f;
        for (int u = gg; u <= t; u += 5) {
            const float* Vp = qkv + (size_t)(n0 + u) * (3 * CDIM) + 2 * CDIM + h * HSD;
            a += sc[u] * Vp[s];
        }
        part[gg * HSD + s] = a;
    }
    __syncthreads();
    if (tid < HSD) {
        float a = (part[tid] + part[HSD + tid] + part[2 * HSD + tid]
                 + part[3 * HSD + tid] + part[4 * HSD + tid]) * inv;
        size_t o = (size_t)(n0 + t) * CDIM + h * HSD + tid;
        fp16 hi = __float2half_rn(a);
        atth[o] = hi;
        attl[o] = __float2half_rn(a - __half2float(hi));
    }
}

// ======================= gate softmax =======================
__global__ void gate_kernel(const float* __restrict__ h2,
                            const float* __restrict__ gw,
                            const float* __restrict__ gb,
                            float* __restrict__ gates) {
    int n = blockIdx.x;
    int e = threadIdx.x;
    const float* hr = h2 + (size_t)n * CDIM;
    float acc = gb[e];
    for (int c = 0; c < CDIM; c++) acc += hr[c] * gw[c * NE + e];
    float mx = acc;
    for (int o = 16; o > 0; o >>= 1) mx = fmaxf(mx, __shfl_xor_sync(0xFFFFFFFFu, mx, o));
    float ex = expf(acc - mx);
    float sm = ex;
    for (int o = 16; o > 0; o >>= 1) sm += __shfl_xor_sync(0xFFFFFFFFu, sm, o);
    gates[n * NE + e] = ex / sm;
}

// ======================= MoE combine =======================
__global__ void combine_kernel(const float* __restrict__ eo,
                               const float* __restrict__ gates,
                               float* __restrict__ x) {
    int n = blockIdx.x;
    __shared__ float gs[NE];
    if (threadIdx.x < NE) gs[threadIdx.x] = gates[n * NE + threadIdx.x];
    __syncthreads();
    for (int c = threadIdx.x; c < CDIM; c += blockDim.x) {
        float a = 0.f;
        const float* er = eo + (size_t)n * (NE * CDIM) + c;
#pragma unroll 8
        for (int e = 0; e < NE; e++) a += gs[e] * er[e * CDIM];
        x[(size_t)n * CDIM + c] += a;
    }
}

// ======================= scalar SGEMM (lm head only) =======================
__global__ void __launch_bounds__(256)
lm_head_kernel(const float* __restrict__ A, const float* __restrict__ B,
               const float* __restrict__ bias, float* __restrict__ C,
               int M, int N, int K) {
    __shared__ float As[64][17];
    __shared__ float Bs[16][64];
    int tid = threadIdx.x;
    int jTile = blockIdx.x * 64;
    int mTile = blockIdx.y * 64;
    int tx = tid & 15, ty = tid >> 4;

    float acc[4][4];
#pragma unroll
    for (int r = 0; r < 4; r++)
#pragma unroll
        for (int c = 0; c < 4; c++) acc[r][c] = 0.f;

    int aRow = tid >> 2, aK = (tid & 3) * 4;
    int bJ = tid & 63, bK0 = tid >> 6;

    for (int k0 = 0; k0 < K; k0 += 16) {
        int m = mTile + aRow;
        if (m < M) {
            float4 av = *(const float4*)(A + (size_t)m * K + k0 + aK);
            As[aRow][aK + 0] = av.x; As[aRow][aK + 1] = av.y;
            As[aRow][aK + 2] = av.z; As[aRow][aK + 3] = av.w;
        } else {
            As[aRow][aK + 0] = 0.f; As[aRow][aK + 1] = 0.f;
            As[aRow][aK + 2] = 0.f; As[aRow][aK + 3] = 0.f;
        }
#pragma unroll
        for (int i = 0; i < 4; i++) {
            int kk = bK0 + i * 4;
            Bs[kk][bJ] = (jTile + bJ < N)
                ? B[(size_t)(k0 + kk) * N + jTile + bJ] : 0.f;
        }
        __syncthreads();
#pragma unroll
        for (int k = 0; k < 16; k++) {
            float4 bv = *(const float4*)&Bs[k][tx * 4];
            float a0 = As[ty * 4 + 0][k], a1 = As[ty * 4 + 1][k];
            float a2 = As[ty * 4 + 2][k], a3 = As[ty * 4 + 3][k];
            acc[0][0] += a0 * bv.x; acc[0][1] += a0 * bv.y; acc[0][2] += a0 * bv.z; acc[0][3] += a0 * bv.w;
            acc[1][0] += a1 * bv.x; acc[1][1] += a1 * bv.y; acc[1][2] += a1 * bv.z; acc[1][3] += a1 * bv.w;
            acc[2][0] += a2 * bv.x; acc[2][1] += a2 * bv.y; acc[2][2] += a2 * bv.z; acc[2][3] += a2 * bv.w;
            acc[3][0] += a3 * bv.x; acc[3][1] += a3 * bv.y; acc[3][2] += a3 * bv.z; acc[3][3] += a3 * bv.w;
        }
        __syncthreads();
    }
#pragma unroll
    for (int r = 0; r < 4; r++) {
        int m = mTile + ty * 4 + r;
        if (m >= M) continue;
#pragma unroll
        for (int c = 0; c < 4; c++) {
            int j = jTile + tx * 4 + c;
            if (j >= N) continue;
            C[(size_t)m * N + j] = acc[r][c] + bias[j];
        }
    }
}

// ======================= launch =======================
extern "C" void kernel_launch(void* const* d_in, const int* in_sizes, int n_in,
                              void* d_out, int out_size) {
    const int*   idx    = (const int*)  d_in[0];
    const float* tok    = (const float*)d_in[1];
    const float* pos    = (const float*)d_in[2];
    const float* ln1_g  = (const float*)d_in[3];
    const float* ln1_b  = (const float*)d_in[4];
    const float* Wq     = (const float*)d_in[5];
    const float* Wk     = (const float*)d_in[6];
    const float* Wv     = (const float*)d_in[7];
    const float* Wo     = (const float*)d_in[8];
    const float* bo     = (const float*)d_in[9];
    const float* ln2_g  = (const float*)d_in[10];
    const float* ln2_b  = (const float*)d_in[11];
    const float* gate_w = (const float*)d_in[12];
    const float* gate_b = (const float*)d_in[13];
    const float* W1     = (const float*)d_in[14];
    const float* b1     = (const float*)d_in[15];
    const float* W2     = (const float*)d_in[16];
    const float* b2     = (const float*)d_in[17];
    const float* lnf_g  = (const float*)d_in[18];
    const float* lnf_b  = (const float*)d_in[19];
    const float* lm_w   = (const float*)d_in[20];
    const float* lm_b   = (const float*)d_in[21];
    float* out = (float*)d_out;

    float *x, *h, *qkv, *gates, *eo;
    fp16 *hh, *hl, *atth, *attl, *wpth, *wptl, *woth, *wotl;
    fp16 *w1th, *w1tl, *w2th, *w2tl, *hidh;
    cudaGetSymbolAddress((void**)&x,     g_x);
    cudaGetSymbolAddress((void**)&h,     g_h);
    cudaGetSymbolAddress((void**)&qkv,   g_qkv);
    cudaGetSymbolAddress((void**)&gates, g_gates);
    cudaGetSymbolAddress((void**)&eo,    g_eo);
    cudaGetSymbolAddress((void**)&hh,    g_hh);
    cudaGetSymbolAddress((void**)&hl,    g_hl);
    cudaGetSymbolAddress((void**)&atth,  g_atth);
    cudaGetSymbolAddress((void**)&attl,  g_attl);
    cudaGetSymbolAddress((void**)&wpth,  g_wpth);
    cudaGetSymbolAddress((void**)&wptl,  g_wptl);
    cudaGetSymbolAddress((void**)&woth,  g_woth);
    cudaGetSymbolAddress((void**)&wotl,  g_wotl);
    cudaGetSymbolAddress((void**)&w1th,  g_w1th);
    cudaGetSymbolAddress((void**)&w1tl,  g_w1tl);
    cudaGetSymbolAddress((void**)&w2th,  g_w2th);
    cudaGetSymbolAddress((void**)&w2tl,  g_w2tl);
    cudaGetSymbolAddress((void**)&hidh,  g_hidh);

    cudaFuncSetAttribute(mma_gemm3<0>, cudaFuncAttributeMaxDynamicSharedMemorySize, SMEM_NT3);
    cudaFuncSetAttribute(mma_gemm3<2>, cudaFuncAttributeMaxDynamicSharedMemorySize, SMEM_NT3);
    cudaFuncSetAttribute(mma_gemm64<3>, cudaFuncAttributeMaxDynamicSharedMemorySize, SMEM_K64);
    cudaFuncSetAttribute(mma_gemm64<1>, cudaFuncAttributeMaxDynamicSharedMemorySize, SMEM_K64);

    const int MT = (NTOK + 127) / 128;   // 7

    // ---- pre-convert all weights (transpose + fp16 hi/lo split) ----
    for (int l = 0; l < NL; l++) {
        convT<<<dim3(CDIM / 32, F4D / 32, NE), 256>>>(
            W1 + (size_t)l * NE * CDIM * F4D, (long long)CDIM * F4D, CDIM, F4D,
            w1th + (size_t)l * NE * F4D * CDIM, w1tl + (size_t)l * NE * F4D * CDIM,
            (long long)F4D * CDIM);
        convT<<<dim3(F4D / 32, CDIM / 32, NE), 256>>>(
            W2 + (size_t)l * NE * F4D * CDIM, (long long)F4D * CDIM, F4D, CDIM,
            w2th + (size_t)l * NE * CDIM * F4D, w2tl + (size_t)l * NE * CDIM * F4D,
            (long long)CDIM * F4D);
        convT<<<dim3(CDIM / 32, CDIM / 32, 1), 256>>>(
            Wo + (size_t)l * CDIM * CDIM, 0, CDIM, CDIM,
            woth + (size_t)l * CDIM * CDIM, wotl + (size_t)l * CDIM * CDIM, 0);
    }

    embed_kernel<<<NTOK, 256>>>(idx, tok, pos, x);

    for (int l = 0; l < NL; l++) {
        // --- attention ---
        ln_kernel<<<NTOK, 256>>>(x, ln1_g + l * CDIM, ln1_b + l * CDIM, h, hh, hl);
        pack_qkvT<<<3 * CDIM, 256>>>(
            Wq + (size_t)l * NH * CDIM * HSD,
            Wk + (size_t)l * NH * CDIM * HSD,
            Wv + (size_t)l * NH * CDIM * HSD, wpth, wptl);
        mma_gemm3<0><<<dim3(MT * 18, 1), 256, SMEM_NT3>>>(
            hh, hl, CDIM, wpth, wptl, CDIM, nullptr,
            qkv, 3 * CDIM, NTOK, 18, CDIM / 32);
        attn_kernel<<<dim3(TSEQ, NH, BSZ), 128>>>(qkv, atth, attl);
        mma_gemm3<2><<<dim3(MT * 6, 1), 256, SMEM_NT3>>>(
            atth, attl, CDIM,
            woth + (size_t)l * CDIM * CDIM, wotl + (size_t)l * CDIM * CDIM, CDIM,
            bo + l * CDIM, x, CDIM, NTOK, 6, CDIM / 32);

        // --- MoE ---
        ln_kernel<<<NTOK, 256>>>(x, ln2_g + l * CDIM, ln2_b + l * CDIM, h, hh, hl);
        gate_kernel<<<NTOK, 32>>>(h, gate_w + (size_t)l * CDIM * NE,
                                  gate_b + l * NE, gates);
        // up: hid = gelu(h @ W1_e + b1_e) -> fp16 hi plane  (K-chunk 64)
        mma_gemm64<3><<<dim3(MT * (F4D / 128), NE), 256, SMEM_K64>>>(
            hh, CDIM, 0,
            w1th + (size_t)l * NE * F4D * CDIM, w1tl + (size_t)l * NE * F4D * CDIM,
            CDIM, (long long)F4D * CDIM,
            b1 + (size_t)l * NE * F4D, F4D,
            nullptr, hidh, (long long)NE * F4D, F4D,
            NTOK, F4D / 128, CDIM / 64);
        // down: eo = hid_e @ W2_e + b2_e  (K-chunk 64)
        mma_gemm64<1><<<dim3(MT * (CDIM / 128), NE), 256, SMEM_K64>>>(
            hidh, (long long)NE * F4D, F4D,
            w2th + (size_t)l * NE * CDIM * F4D, w2tl + (size_t)l * NE * CDIM * F4D,
            F4D, (long long)CDIM * F4D,
            b2 + (size_t)l * NE * CDIM, CDIM,
            eo, nullptr, (long long)NE * CDIM, CDIM,
            NTOK, CDIM / 128, F4D / 64);
        combine_kernel<<<NTOK, 256>>>(eo, gates, x);
    }

    // --- final LN + lm head ---
    ln_kernel<<<NTOK, 256>>>(x, lnf_g, lnf_b, h, hh, hl);
    lm_head_kernel<<<dim3((NV + 63) / 64, (NTOK + 63) / 64), 256>>>(
        h, lm_w, lm_b, out, NTOK, NV, CDIM);
}

// round 10
// speedup vs baseline: 1.7305x; 1.1324x over previous
#include <cuda_runtime.h>
#include <cuda_fp16.h>
#include <math.h>
#include <stdint.h>

// ---- problem constants ----
#define NTOK 844      // B*T = 2*422
#define TSEQ 422
#define BSZ  2
#define CDIM 768
#define NH   32
#define HSD  24
#define NE   32
#define F4D  3072
#define NL   2
#define NV   100

typedef __half fp16;

// ---- device scratch ----
__device__ float g_x  [NTOK * CDIM];
__device__ float g_h  [NTOK * CDIM];
__device__ float g_qkv[NTOK * 3 * CDIM];
__device__ float g_gates[NTOK * NE];
__device__ float g_eo [(size_t)NTOK * NE * CDIM];

__device__ fp16 g_hh [NTOK * CDIM],  g_hl [NTOK * CDIM];
__device__ fp16 g_atth[NTOK * CDIM], g_attl[NTOK * CDIM];
__device__ fp16 g_wpth[3 * CDIM * CDIM], g_wptl[3 * CDIM * CDIM];
__device__ fp16 g_woth[NL * CDIM * CDIM], g_wotl[NL * CDIM * CDIM];
__device__ fp16 g_w1th[(size_t)NL * NE * F4D * CDIM];
__device__ fp16 g_w1tl[(size_t)NL * NE * F4D * CDIM];
__device__ fp16 g_w2th[(size_t)NL * NE * CDIM * F4D];
__device__ fp16 g_w2tl[(size_t)NL * NE * CDIM * F4D];
__device__ fp16 g_hidh[(size_t)NTOK * NE * F4D];

// ======================= helpers =======================
__device__ __forceinline__ float gelu_exact(float v) {
    return 0.5f * v * (1.f + erff(v * 0.70710678118654752f));
}

__device__ __forceinline__ void mma16816(float* d, const unsigned* a, const unsigned* b) {
    asm volatile(
        "mma.sync.aligned.m16n8k16.row.col.f32.f16.f16.f32 "
        "{%0,%1,%2,%3}, {%4,%5,%6,%7}, {%8,%9}, {%0,%1,%2,%3};"
        : "+f"(d[0]), "+f"(d[1]), "+f"(d[2]), "+f"(d[3])
        : "r"(a[0]), "r"(a[1]), "r"(a[2]), "r"(a[3]), "r"(b[0]), "r"(b[1]));
}

__device__ __forceinline__ void cpa16(unsigned s, const void* g, int sz) {
    asm volatile("cp.async.cg.shared.global [%0], [%1], 16, %2;"
                 :: "r"(s), "l"(g), "r"(sz));
}
#define CPA_COMMIT() asm volatile("cp.async.commit_group;" ::: "memory")
#define CPA_WAIT(n)  asm volatile("cp.async.wait_group %0;" :: "n"(n) : "memory")

#define LDSM4(r0, r1, r2, r3, addr)                                            \
    asm volatile("ldmatrix.sync.aligned.m8n8.x4.shared.b16 {%0,%1,%2,%3}, [%4];" \
        : "=r"(r0), "=r"(r1), "=r"(r2), "=r"(r3) : "r"(addr))

// ======================= NT3 GEMM (attention paths, K-chunk 32) =============
#define STR 40                     // smem row stride (elems); 80B rows
#define PLANE_B (128 * 80)         // 10240
#define SMEM_NT3 81920             // 2 stages * 4 planes

template <int EP>
__global__ void __launch_bounds__(256, 2)
mma_gemm3(const fp16* __restrict__ Ah, const fp16* __restrict__ Al,
          long long lda,
          const fp16* __restrict__ Bh, const fp16* __restrict__ Bl,
          long long ldb,
          const float* __restrict__ bias,
          float* __restrict__ Cf, long long ldc,
          int M, int Ntiles, int KC) {
    constexpr unsigned STAGE_B = 4 * PLANE_B;
    extern __shared__ char smc[];
    unsigned smbase;
    asm("{ .reg .u64 t; cvta.to.shared.u64 t, %1; cvt.u32.u64 %0, t; }"
        : "=r"(smbase) : "l"(smc));

    const int tid = threadIdx.x, wid = tid >> 5, lane = tid & 31;
    const int g = lane >> 2, tg = lane & 3;
    const int wm = wid >> 2, wn = wid & 3;
    const int nt = blockIdx.x % Ntiles, mt = blockIdx.x / Ntiles;
    const int n0 = nt * 128, m0 = mt * 128;

    const int s4 = lane >> 3, lr = lane & 7;
    const int aRowL = lr + (s4 & 1) * 8, aColL = (s4 >> 1) * 8;
    const int bRowL = lr + (s4 >> 1) * 8, bColL = (s4 & 1) * 8;

    float acc[4][4][4];
#pragma unroll
    for (int i = 0; i < 4; i++)
#pragma unroll
        for (int j = 0; j < 4; j++)
#pragma unroll
            for (int r = 0; r < 4; r++) acc[i][j][r] = 0.f;

    const int fRow = tid >> 2, fCh = tid & 3;

    auto issue = [&](int c) {
        const int k0 = c * 32;
        unsigned sb = smbase + (c & 1) * STAGE_B;
#pragma unroll
        for (int i = 0; i < 2; i++) {
            int row = fRow + i * 64;
            int m = m0 + row;
            int sz = (m < M) ? 16 : 0;
            size_t go = (size_t)(m < M ? m : 0) * lda + k0 + fCh * 8;
            unsigned so = sb + row * 80 + fCh * 16;
            cpa16(so, Ah + go, sz);
            cpa16(so + PLANE_B, Al + go, sz);
        }
#pragma unroll
        for (int i = 0; i < 2; i++) {
            int row = fRow + i * 64;
            size_t go = (size_t)(n0 + row) * ldb + k0 + fCh * 8;
            unsigned so = sb + 2 * PLANE_B + row * 80 + fCh * 16;
            cpa16(so, Bh + go, 16);
            cpa16(so + PLANE_B, Bl + go, 16);
        }
    };

    issue(0);
    CPA_COMMIT();

    for (int c = 0; c < KC; ++c) {
        if (c + 1 < KC) { issue(c + 1); CPA_COMMIT(); CPA_WAIT(1); }
        else            { CPA_WAIT(0); }
        __syncthreads();

        unsigned sb = smbase + (c & 1) * STAGE_B;
#pragma unroll
        for (int ks = 0; ks < 2; ks++) {
            const int kb = ks * 16;
            unsigned bh_[4][2], bl_[4][2];
#pragma unroll
            for (int p = 0; p < 2; p++) {
                int rn0 = wn * 32 + p * 16;
                unsigned ba = sb + 2 * PLANE_B +
                              (unsigned)((rn0 + bRowL) * STR + kb + bColL) * 2;
                LDSM4(bh_[2 * p][0], bh_[2 * p][1], bh_[2 * p + 1][0], bh_[2 * p + 1][1], ba);
                LDSM4(bl_[2 * p][0], bl_[2 * p][1], bl_[2 * p + 1][0], bl_[2 * p + 1][1],
                      ba + PLANE_B);
            }
#pragma unroll
            for (int mi = 0; mi < 4; mi++) {
                int rm0 = wm * 64 + mi * 16;
                unsigned aa = sb + (unsigned)((rm0 + aRowL) * STR + kb + aColL) * 2;
                unsigned ah_[4], al_[4];
                LDSM4(ah_[0], ah_[1], ah_[2], ah_[3], aa);
                LDSM4(al_[0], al_[1], al_[2], al_[3], aa + PLANE_B);
#pragma unroll
                for (int ni = 0; ni < 4; ni++) {
                    mma16816(acc[mi][ni], ah_, bh_[ni]);
                    mma16816(acc[mi][ni], ah_, bl_[ni]);
                    mma16816(acc[mi][ni], al_, bh_[ni]);
                }
            }
        }
        __syncthreads();
    }

    // ---- epilogue ----
    float* sOut = (float*)smc;
#pragma unroll
    for (int mi = 0; mi < 4; mi++) {
        int lrow = wm * 64 + mi * 16 + g;
#pragma unroll
        for (int ni = 0; ni < 4; ni++) {
            int j = wn * 32 + ni * 8 + tg * 2;
            float b0 = 0.f, b1 = 0.f;
            if (EP >= 1) { b0 = bias[n0 + j]; b1 = bias[n0 + j + 1]; }
#pragma unroll
            for (int hh = 0; hh < 2; hh++) {
                float v0 = acc[mi][ni][hh * 2 + 0] + b0;
                float v1 = acc[mi][ni][hh * 2 + 1] + b1;
                *(float2*)&sOut[(lrow + hh * 8) * 132 + j] = make_float2(v0, v1);
            }
        }
    }
    __syncthreads();
#pragma unroll
    for (int i = 0; i < 16; i++) {
        int item = tid + i * 256;
        int row = item >> 5;
        int c4 = (item & 31) * 4;
        int m = m0 + row;
        if (m >= M) continue;
        float4 v = *(float4*)&sOut[row * 132 + c4];
        float* p = Cf + (size_t)m * ldc + n0 + c4;
        if (EP == 2) {
            float4 old = *(float4*)p;
            v.x += old.x; v.y += old.y; v.z += old.z; v.w += old.w;
        }
        *(float4*)p = v;
    }
}

// ======================= NT2/NT1 MoE GEMM (K-chunk 64) ======================
// BL = 1: B hi+lo planes (2 MMA/pos).  BL = 0: B hi only (1 MMA/pos).
#define STR64 72                   // smem row stride elems (144B), conflict-free
#define PL64 (128 * 144)           // 18432 bytes per plane
#define SMEM_K64_NT2 110592        // 2 stages * 3 planes
#define SMEM_K64_NT1 73728         // 2 stages * 2 planes

template <int EP, int BL>
__global__ void __launch_bounds__(256, 2)
mma_gemm64(const fp16* __restrict__ Ah, long long lda, long long aExp,
           const fp16* __restrict__ Bh, const fp16* __restrict__ Bl,
           long long ldb, long long bExp,
           const float* __restrict__ bias, long long biasExp,
           float* __restrict__ Cf, fp16* __restrict__ Ch,
           long long ldc, long long cExp,
           int M, int Ntiles, int KC) {
    constexpr unsigned STAGE = (2 + BL) * PL64;
    extern __shared__ char smc[];
    unsigned smbase;
    asm("{ .reg .u64 t; cvta.to.shared.u64 t, %1; cvt.u32.u64 %0, t; }"
        : "=r"(smbase) : "l"(smc));

    const int tid = threadIdx.x, wid = tid >> 5, lane = tid & 31;
    const int g = lane >> 2, tg = lane & 3;
    const int wm = wid >> 2, wn = wid & 3;
    const int e = blockIdx.y;
    const int nt = blockIdx.x % Ntiles, mt = blockIdx.x / Ntiles;
    const int n0 = nt * 128, m0 = mt * 128;

    const fp16* Abh = Ah + (size_t)e * aExp;
    const fp16* Bbh = Bh + (size_t)e * bExp;
    const fp16* Bbl = BL ? (Bl + (size_t)e * bExp) : nullptr;

    const int s4 = lane >> 3, lr = lane & 7;
    const int aRowL = lr + (s4 & 1) * 8, aColL = (s4 >> 1) * 8;
    const int bRowL = lr + (s4 >> 1) * 8, bColL = (s4 & 1) * 8;

    float acc[4][4][4];
#pragma unroll
    for (int i = 0; i < 4; i++)
#pragma unroll
        for (int j = 0; j < 4; j++)
#pragma unroll
            for (int r = 0; r < 4; r++) acc[i][j][r] = 0.f;

    auto issue = [&](int c) {
        const int k0 = c * 64;
        unsigned sb = smbase + (c & 1) * STAGE;
        // A hi plane: 128 rows x 128B
#pragma unroll
        for (int i = 0; i < 4; i++) {
            int item = tid + i * 256;
            int row = item >> 3, c8 = item & 7;
            int m = m0 + row;
            int sz = (m < M) ? 16 : 0;
            size_t go = (size_t)(m < M ? m : 0) * lda + k0 + c8 * 8;
            cpa16(sb + row * 144 + c8 * 16, Abh + go, sz);
        }
        // B hi (+ lo) planes
#pragma unroll
        for (int i = 0; i < 4; i++) {
            int item = tid + i * 256;
            int row = item >> 3, c8 = item & 7;
            size_t go = (size_t)(n0 + row) * ldb + k0 + c8 * 8;
            unsigned so = sb + PL64 + row * 144 + c8 * 16;
            cpa16(so, Bbh + go, 16);
            if (BL) cpa16(so + PL64, Bbl + go, 16);
        }
    };

    issue(0);
    CPA_COMMIT();

    for (int c = 0; c < KC; ++c) {
        if (c + 1 < KC) { issue(c + 1); CPA_COMMIT(); CPA_WAIT(1); }
        else            { CPA_WAIT(0); }
        __syncthreads();

        unsigned sb = smbase + (c & 1) * STAGE;
        unsigned sbB = sb + PL64;
#pragma unroll
        for (int ks = 0; ks < 4; ks++) {
            const int kb = ks * 16;
            unsigned bh_[4][2], bl_[4][2];
#pragma unroll
            for (int p = 0; p < 2; p++) {
                int rn0 = wn * 32 + p * 16;
                unsigned ba = sbB + (unsigned)((rn0 + bRowL) * STR64 + kb + bColL) * 2;
                LDSM4(bh_[2 * p][0], bh_[2 * p][1], bh_[2 * p + 1][0], bh_[2 * p + 1][1], ba);
                if (BL)
                    LDSM4(bl_[2 * p][0], bl_[2 * p][1], bl_[2 * p + 1][0], bl_[2 * p + 1][1],
                          ba + PL64);
            }
#pragma unroll
            for (int mi = 0; mi < 4; mi++) {
                int rm0 = wm * 64 + mi * 16;
                unsigned aa = sb + (unsigned)((rm0 + aRowL) * STR64 + kb + aColL) * 2;
                unsigned ah_[4];
                LDSM4(ah_[0], ah_[1], ah_[2], ah_[3], aa);
#pragma unroll
                for (int ni = 0; ni < 4; ni++) {
                    mma16816(acc[mi][ni], ah_, bh_[ni]);
                    if (BL) mma16816(acc[mi][ni], ah_, bl_[ni]);
                }
            }
        }
        __syncthreads();
    }

    // ---- epilogue: regs -> smem -> coalesced gmem ----
    float* sOut = (float*)smc;
#pragma unroll
    for (int mi = 0; mi < 4; mi++) {
        int lrow = wm * 64 + mi * 16 + g;
#pragma unroll
        for (int ni = 0; ni < 4; ni++) {
            int j = wn * 32 + ni * 8 + tg * 2;
            float b0 = bias[(size_t)e * biasExp + n0 + j];
            float b1 = bias[(size_t)e * biasExp + n0 + j + 1];
#pragma unroll
            for (int hh = 0; hh < 2; hh++) {
                float v0 = acc[mi][ni][hh * 2 + 0] + b0;
                float v1 = acc[mi][ni][hh * 2 + 1] + b1;
                if (EP == 3) { v0 = gelu_exact(v0); v1 = gelu_exact(v1); }
                *(float2*)&sOut[(lrow + hh * 8) * 132 + j] = make_float2(v0, v1);
            }
        }
    }
    __syncthreads();

    if (EP == 3) {
#pragma unroll
        for (int i = 0; i < 8; i++) {
            int item = tid + i * 256;
            int row = item >> 4;
            int c8 = (item & 15) * 8;
            int m = m0 + row;
            if (m >= M) continue;
            float4 f0 = *(float4*)&sOut[row * 132 + c8];
            float4 f1 = *(float4*)&sOut[row * 132 + c8 + 4];
            __half2 h0 = __floats2half2_rn(f0.x, f0.y);
            __half2 h1 = __floats2half2_rn(f0.z, f0.w);
            __half2 h2 = __floats2half2_rn(f1.x, f1.y);
            __half2 h3 = __floats2half2_rn(f1.z, f1.w);
            uint4 u = make_uint4(*(unsigned*)&h0, *(unsigned*)&h1,
                                 *(unsigned*)&h2, *(unsigned*)&h3);
            *(uint4*)(Ch + (size_t)e * cExp + (size_t)m * ldc + n0 + c8) = u;
        }
    } else {
#pragma unroll
        for (int i = 0; i < 16; i++) {
            int item = tid + i * 256;
            int row = item >> 5;
            int c4 = (item & 31) * 4;
            int m = m0 + row;
            if (m >= M) continue;
            float4 v = *(float4*)&sOut[row * 132 + c4];
            *(float4*)(Cf + (size_t)e * cExp + (size_t)m * ldc + n0 + c4) = v;
        }
    }
}

// ======================= transpose + split convert ==========================
__global__ void convT(const float* __restrict__ src, long long sExp, int K, int N,
                      fp16* __restrict__ th, fp16* __restrict__ tl, long long tExp) {
    __shared__ float t[32][33];
    int e = blockIdx.z;
    int k0 = blockIdx.x * 32, nn0 = blockIdx.y * 32;
    int tx = threadIdx.x & 31;
    int ty = threadIdx.x >> 5;
    const float* sp = src + (size_t)e * sExp;
#pragma unroll
    for (int r = 0; r < 4; r++) {
        int k = k0 + ty + r * 8;
        t[ty + r * 8][tx] = sp[(size_t)k * N + nn0 + tx];
    }
    __syncthreads();
    {
        int n = threadIdx.x >> 3;
        int kq = (threadIdx.x & 7) * 4;
        float v0 = t[kq + 0][n], v1 = t[kq + 1][n];
        float v2 = t[kq + 2][n], v3 = t[kq + 3][n];
        __half2 h0 = __floats2half2_rn(v0, v1);
        __half2 h1 = __floats2half2_rn(v2, v3);
        float2 r0 = __half22float2(h0), r1 = __half22float2(h1);
        __half2 l0 = __floats2half2_rn(v0 - r0.x, v1 - r0.y);
        __half2 l1 = __floats2half2_rn(v2 - r1.x, v3 - r1.y);
        size_t o = (size_t)e * tExp + (size_t)(nn0 + n) * K + k0 + kq;
        *(uint2*)(th + o) = make_uint2(*(unsigned*)&h0, *(unsigned*)&h1);
        *(uint2*)(tl + o) = make_uint2(*(unsigned*)&l0, *(unsigned*)&l1);
    }
}

// ======================= pack Wq/Wk/Wv -> transposed fp16 planes [3C][C] ======
__global__ void pack_qkvT(const float* __restrict__ Wq,
                          const float* __restrict__ Wk,
                          const float* __restrict__ Wv,
                          fp16* __restrict__ th, fp16* __restrict__ tl) {
    int j = blockIdx.x;
    int which = j / CDIM, hs = j % CDIM;
    int h = hs / HSD, s = hs % HSD;
    const float* W = (which == 0) ? Wq : ((which == 1) ? Wk : Wv);
    for (int c = threadIdx.x; c < CDIM; c += 256) {
        float v = W[((size_t)h * CDIM + c) * HSD + s];
        fp16 hi = __float2half_rn(v);
        size_t o = (size_t)j * CDIM + c;
        th[o] = hi;
        tl[o] = __float2half_rn(v - __half2float(hi));
    }
}

// ======================= embedding =======================
__global__ void embed_kernel(const int* __restrict__ idx,
                             const float* __restrict__ tok,
                             const float* __restrict__ pos,
                             float* __restrict__ x) {
    int n = blockIdx.x;
    int t = n % TSEQ;
    int v = idx[n];
    for (int c = threadIdx.x; c < CDIM; c += blockDim.x)
        x[n * CDIM + c] = tok[v * CDIM + c] + pos[t * CDIM + c];
}

// ======================= layernorm (fp32 + fp16 hi/lo planes) ==============
__global__ void ln_kernel(const float* __restrict__ x,
                          const float* __restrict__ g,
                          const float* __restrict__ b,
                          float* __restrict__ out,
                          fp16* __restrict__ oh, fp16* __restrict__ ol) {
    int n = blockIdx.x;
    int tid = threadIdx.x;
    __shared__ float s1[256], s2[256];
    const float* xr = x + (size_t)n * CDIM;
    float a = 0.f, q = 0.f;
    for (int c = tid; c < CDIM; c += 256) { float v = xr[c]; a += v; q += v * v; }
    s1[tid] = a; s2[tid] = q;
    __syncthreads();
    for (int s = 128; s > 0; s >>= 1) {
        if (tid < s) { s1[tid] += s1[tid + s]; s2[tid] += s2[tid + s]; }
        __syncthreads();
    }
    float mean = s1[0] * (1.f / CDIM);
    float var  = s2[0] * (1.f / CDIM) - mean * mean;
    float r = rsqrtf(var + 1e-5f);
    for (int c = tid; c < CDIM; c += 256) {
        float o = (xr[c] - mean) * r * g[c] + b[c];
        size_t p = (size_t)n * CDIM + c;
        out[p] = o;
        fp16 hi = __float2half_rn(o);
        oh[p] = hi;
        ol[p] = __float2half_rn(o - __half2float(hi));
    }
}

// ======================= attention =======================
__global__ void attn_kernel(const float* __restrict__ qkv,
                            fp16* __restrict__ atth, fp16* __restrict__ attl) {
    int t = blockIdx.x, h = blockIdx.y, b = blockIdx.z;
    int tid = threadIdx.x;
    __shared__ float sc[TSEQ];
    __shared__ float qs[HSD];
    __shared__ float red[128];
    __shared__ float part[5 * HSD];

    int n0 = b * TSEQ;
    const float* Q = qkv + (size_t)(n0 + t) * (3 * CDIM) + h * HSD;
    if (tid < HSD) qs[tid] = Q[tid];
    __syncthreads();

    const float scale = 0.20412414523193154f;
    float lmax = -1e30f;
    for (int u = tid; u <= t; u += 128) {
        const float* Kp = qkv + (size_t)(n0 + u) * (3 * CDIM) + CDIM + h * HSD;
        float d = 0.f;
#pragma unroll
        for (int s = 0; s < HSD; s++) d += qs[s] * Kp[s];
        d *= scale;
        sc[u] = d;
        lmax = fmaxf(lmax, d);
    }
    red[tid] = lmax;
    __syncthreads();
    for (int s = 64; s > 0; s >>= 1) {
        if (tid < s) red[tid] = fmaxf(red[tid], red[tid + s]);
        __syncthreads();
    }
    float mx = red[0];
    __syncthreads();

    float lsum = 0.f;
    for (int u = tid; u <= t; u += 128) {
        float ev = expf(sc[u] - mx);
        sc[u] = ev;
        lsum += ev;
    }
    red[tid] = lsum;
    __syncthreads();
    for (int s = 64; s > 0; s >>= 1) {
        if (tid < s) red[tid] += red[tid + s];
        __syncthreads();
    }
    float inv = 1.f / red[0];
    __syncthreads();

    if (tid < 120) {
        int s = tid % HSD, gg = tid / HSD;
        float a = 0.f;
        for (int u = gg; u <= t; u += 5) {
            const float* Vp = qkv + (size_t)(n0 + u) * (3 * CDIM) + 2 * CDIM + h * HSD;
            a += sc[u] * Vp[s];
        }
        part[gg * HSD + s] = a;
    }
    __syncthreads();
    if (tid < HSD) {
        float a = (part[tid] + part[HSD + tid] + part[2 * HSD + tid]
                 + part[3 * HSD + tid] + part[4 * HSD + tid]) * inv;
        size_t o = (size_t)(n0 + t) * CDIM + h * HSD + tid;
        fp16 hi = __float2half_rn(a);
        atth[o] = hi;
        attl[o] = __float2half_rn(a - __half2float(hi));
    }
}

// ======================= gate softmax =======================
__global__ void gate_kernel(const float* __restrict__ h2,
                            const float* __restrict__ gw,
                            const float* __restrict__ gb,
                            float* __restrict__ gates) {
    int n = blockIdx.x;
    int e = threadIdx.x;
    const float* hr = h2 + (size_t)n * CDIM;
    float acc = gb[e];
    for (int c = 0; c < CDIM; c++) acc += hr[c] * gw[c * NE + e];
    float mx = acc;
    for (int o = 16; o > 0; o >>= 1) mx = fmaxf(mx, __shfl_xor_sync(0xFFFFFFFFu, mx, o));
    float ex = expf(acc - mx);
    float sm = ex;
    for (int o = 16; o > 0; o >>= 1) sm += __shfl_xor_sync(0xFFFFFFFFu, sm, o);
    gates[n * NE + e] = ex / sm;
}

// ======================= MoE combine =======================
__global__ void combine_kernel(const float* __restrict__ eo,
                               const float* __restrict__ gates,
                               float* __restrict__ x) {
    int n = blockIdx.x;
    __shared__ float gs[NE];
    if (threadIdx.x < NE) gs[threadIdx.x] = gates[n * NE + threadIdx.x];
    __syncthreads();
    for (int c = threadIdx.x; c < CDIM; c += blockDim.x) {
        float a = 0.f;
        const float* er = eo + (size_t)n * (NE * CDIM) + c;
#pragma unroll 8
        for (int e = 0; e < NE; e++) a += gs[e] * er[e * CDIM];
        x[(size_t)n * CDIM + c] += a;
    }
}

// ======================= scalar SGEMM (lm head only) =======================
__global__ void __launch_bounds__(256)
lm_head_kernel(const float* __restrict__ A, const float* __restrict__ B,
               const float* __restrict__ bias, float* __restrict__ C,
               int M, int N, int K) {
    __shared__ float As[64][17];
    __shared__ float Bs[16][64];
    int tid = threadIdx.x;
    int jTile = blockIdx.x * 64;
    int mTile = blockIdx.y * 64;
    int tx = tid & 15, ty = tid >> 4;

    float acc[4][4];
#pragma unroll
    for (int r = 0; r < 4; r++)
#pragma unroll
        for (int c = 0; c < 4; c++) acc[r][c] = 0.f;

    int aRow = tid >> 2, aK = (tid & 3) * 4;
    int bJ = tid & 63, bK0 = tid >> 6;

    for (int k0 = 0; k0 < K; k0 += 16) {
        int m = mTile + aRow;
        if (m < M) {
            float4 av = *(const float4*)(A + (size_t)m * K + k0 + aK);
            As[aRow][aK + 0] = av.x; As[aRow][aK + 1] = av.y;
            As[aRow][aK + 2] = av.z; As[aRow][aK + 3] = av.w;
        } else {
            As[aRow][aK + 0] = 0.f; As[aRow][aK + 1] = 0.f;
            As[aRow][aK + 2] = 0.f; As[aRow][aK + 3] = 0.f;
        }
#pragma unroll
        for (int i = 0; i < 4; i++) {
            int kk = bK0 + i * 4;
            Bs[kk][bJ] = (jTile + bJ < N)
                ? B[(size_t)(k0 + kk) * N + jTile + bJ] : 0.f;
        }
        __syncthreads();
#pragma unroll
        for (int k = 0; k < 16; k++) {
            float4 bv = *(const float4*)&Bs[k][tx * 4];
            float a0 = As[ty * 4 + 0][k], a1 = As[ty * 4 + 1][k];
            float a2 = As[ty * 4 + 2][k], a3 = As[ty * 4 + 3][k];
            acc[0][0] += a0 * bv.x; acc[0][1] += a0 * bv.y; acc[0][2] += a0 * bv.z; acc[0][3] += a0 * bv.w;
            acc[1][0] += a1 * bv.x; acc[1][1] += a1 * bv.y; acc[1][2] += a1 * bv.z; acc[1][3] += a1 * bv.w;
            acc[2][0] += a2 * bv.x; acc[2][1] += a2 * bv.y; acc[2][2] += a2 * bv.z; acc[2][3] += a2 * bv.w;
            acc[3][0] += a3 * bv.x; acc[3][1] += a3 * bv.y; acc[3][2] += a3 * bv.z; acc[3][3] += a3 * bv.w;
        }
        __syncthreads();
    }
#pragma unroll
    for (int r = 0; r < 4; r++) {
        int m = mTile + ty * 4 + r;
        if (m >= M) continue;
#pragma unroll
        for (int c = 0; c < 4; c++) {
            int j = jTile + tx * 4 + c;
            if (j >= N) continue;
            C[(size_t)m * N + j] = acc[r][c] + bias[j];
        }
    }
}

// ======================= launch =======================
extern "C" void kernel_launch(void* const* d_in, const int* in_sizes, int n_in,
                              void* d_out, int out_size) {
    const int*   idx    = (const int*)  d_in[0];
    const float* tok    = (const float*)d_in[1];
    const float* pos    = (const float*)d_in[2];
    const float* ln1_g  = (const float*)d_in[3];
    const float* ln1_b  = (const float*)d_in[4];
    const float* Wq     = (const float*)d_in[5];
    const float* Wk     = (const float*)d_in[6];
    const float* Wv     = (const float*)d_in[7];
    const float* Wo     = (const float*)d_in[8];
    const float* bo     = (const float*)d_in[9];
    const float* ln2_g  = (const float*)d_in[10];
    const float* ln2_b  = (const float*)d_in[11];
    const float* gate_w = (const float*)d_in[12];
    const float* gate_b = (const float*)d_in[13];
    const float* W1     = (const float*)d_in[14];
    const float* b1     = (const float*)d_in[15];
    const float* W2     = (const float*)d_in[16];
    const float* b2     = (const float*)d_in[17];
    const float* lnf_g  = (const float*)d_in[18];
    const float* lnf_b  = (const float*)d_in[19];
    const float* lm_w   = (const float*)d_in[20];
    const float* lm_b   = (const float*)d_in[21];
    float* out = (float*)d_out;

    float *x, *h, *qkv, *gates, *eo;
    fp16 *hh, *hl, *atth, *attl, *wpth, *wptl, *woth, *wotl;
    fp16 *w1th, *w1tl, *w2th, *w2tl, *hidh;
    cudaGetSymbolAddress((void**)&x,     g_x);
    cudaGetSymbolAddress((void**)&h,     g_h);
    cudaGetSymbolAddress((void**)&qkv,   g_qkv);
    cudaGetSymbolAddress((void**)&gates, g_gates);
    cudaGetSymbolAddress((void**)&eo,    g_eo);
    cudaGetSymbolAddress((void**)&hh,    g_hh);
    cudaGetSymbolAddress((void**)&hl,    g_hl);
    cudaGetSymbolAddress((void**)&atth,  g_atth);
    cudaGetSymbolAddress((void**)&attl,  g_attl);
    cudaGetSymbolAddress((void**)&wpth,  g_wpth);
    cudaGetSymbolAddress((void**)&wptl,  g_wptl);
    cudaGetSymbolAddress((void**)&woth,  g_woth);
    cudaGetSymbolAddress((void**)&wotl,  g_wotl);
    cudaGetSymbolAddress((void**)&w1th,  g_w1th);
    cudaGetSymbolAddress((void**)&w1tl,  g_w1tl);
    cudaGetSymbolAddress((void**)&w2th,  g_w2th);
    cudaGetSymbolAddress((void**)&w2tl,  g_w2tl);
    cudaGetSymbolAddress((void**)&hidh,  g_hidh);

    cudaFuncSetAttribute(mma_gemm3<0>, cudaFuncAttributeMaxDynamicSharedMemorySize, SMEM_NT3);
    cudaFuncSetAttribute(mma_gemm3<2>, cudaFuncAttributeMaxDynamicSharedMemorySize, SMEM_NT3);
    cudaFuncSetAttribute((const void*)mma_gemm64<3, 1>,
                         cudaFuncAttributeMaxDynamicSharedMemorySize, SMEM_K64_NT2);
    cudaFuncSetAttribute((const void*)mma_gemm64<1, 0>,
                         cudaFuncAttributeMaxDynamicSharedMemorySize, SMEM_K64_NT1);

    const int MT = (NTOK + 127) / 128;   // 7

    // ---- pre-convert all weights (transpose + fp16 hi/lo split) ----
    // NOTE: W2 lo plane still produced by convT (harmless) but unused by NT1 down.
    for (int l = 0; l < NL; l++) {
        convT<<<dim3(CDIM / 32, F4D / 32, NE), 256>>>(
            W1 + (size_t)l * NE * CDIM * F4D, (long long)CDIM * F4D, CDIM, F4D,
            w1th + (size_t)l * NE * F4D * CDIM, w1tl + (size_t)l * NE * F4D * CDIM,
            (long long)F4D * CDIM);
        convT<<<dim3(F4D / 32, CDIM / 32, NE), 256>>>(
            W2 + (size_t)l * NE * F4D * CDIM, (long long)F4D * CDIM, F4D, CDIM,
            w2th + (size_t)l * NE * CDIM * F4D, w2tl + (size_t)l * NE * CDIM * F4D,
            (long long)CDIM * F4D);
        convT<<<dim3(CDIM / 32, CDIM / 32, 1), 256>>>(
            Wo + (size_t)l * CDIM * CDIM, 0, CDIM, CDIM,
            woth + (size_t)l * CDIM * CDIM, wotl + (size_t)l * CDIM * CDIM, 0);
    }

    embed_kernel<<<NTOK, 256>>>(idx, tok, pos, x);

    for (int l = 0; l < NL; l++) {
        // --- attention ---
        ln_kernel<<<NTOK, 256>>>(x, ln1_g + l * CDIM, ln1_b + l * CDIM, h, hh, hl);
        pack_qkvT<<<3 * CDIM, 256>>>(
            Wq + (size_t)l * NH * CDIM * HSD,
            Wk + (size_t)l * NH * CDIM * HSD,
            Wv + (size_t)l * NH * CDIM * HSD, wpth, wptl);
        mma_gemm3<0><<<dim3(MT * 18, 1), 256, SMEM_NT3>>>(
            hh, hl, CDIM, wpth, wptl, CDIM, nullptr,
            qkv, 3 * CDIM, NTOK, 18, CDIM / 32);
        attn_kernel<<<dim3(TSEQ, NH, BSZ), 128>>>(qkv, atth, attl);
        mma_gemm3<2><<<dim3(MT * 6, 1), 256, SMEM_NT3>>>(
            atth, attl, CDIM,
            woth + (size_t)l * CDIM * CDIM, wotl + (size_t)l * CDIM * CDIM, CDIM,
            bo + l * CDIM, x, CDIM, NTOK, 6, CDIM / 32);

        // --- MoE ---
        ln_kernel<<<NTOK, 256>>>(x, ln2_g + l * CDIM, ln2_b + l * CDIM, h, hh, hl);
        gate_kernel<<<NTOK, 32>>>(h, gate_w + (size_t)l * CDIM * NE,
                                  gate_b + l * NE, gates);
        // up: hid = gelu(h @ W1_e + b1_e) -> fp16 hi plane  (NT2, K-chunk 64)
        mma_gemm64<3, 1><<<dim3(MT * (F4D / 128), NE), 256, SMEM_K64_NT2>>>(
            hh, CDIM, 0,
            w1th + (size_t)l * NE * F4D * CDIM, w1tl + (size_t)l * NE * F4D * CDIM,
            CDIM, (long long)F4D * CDIM,
            b1 + (size_t)l * NE * F4D, F4D,
            nullptr, hidh, (long long)NE * F4D, F4D,
            NTOK, F4D / 128, CDIM / 64);
        // down: eo = hid_e @ W2_e + b2_e  (NT1: hi planes only, K-chunk 64)
        mma_gemm64<1, 0><<<dim3(MT * (CDIM / 128), NE), 256, SMEM_K64_NT1>>>(
            hidh, (long long)NE * F4D, F4D,
            w2th + (size_t)l * NE * CDIM * F4D, nullptr,
            F4D, (long long)CDIM * F4D,
            b2 + (size_t)l * NE * CDIM, CDIM,
            eo, nullptr, (long long)NE * CDIM, CDIM,
            NTOK, CDIM / 128, F4D / 64);
        combine_kernel<<<NTOK, 256>>>(eo, gates, x);
    }

    // --- final LN + lm head ---
    ln_kernel<<<NTOK, 256>>>(x, lnf_g, lnf_b, h, hh, hl);
    lm_head_kernel<<<dim3((NV + 63) / 64, (NTOK + 63) / 64), 256>>>(
        h, lm_w, lm_b, out, NTOK, NV, CDIM);
}

// round 11
// speedup vs baseline: 2.0318x; 1.1741x over previous
#include <cuda_runtime.h>
#include <cuda_fp16.h>
#include <math.h>
#include <stdint.h>

// ---- problem constants ----
#define NTOK 844      // B*T = 2*422
#define TSEQ 422
#define BSZ  2
#define CDIM 768
#define NH   32
#define HSD  24
#define NE   32
#define F4D  3072
#define NL   2
#define NV   100

typedef __half fp16;

// ---- device scratch ----
__device__ float g_x  [NTOK * CDIM];
__device__ float g_h  [NTOK * CDIM];
__device__ float g_qkv[NTOK * 3 * CDIM];
__device__ float g_gates[NTOK * NE];
__device__ float g_eo [(size_t)NTOK * NE * CDIM];

__device__ fp16 g_hh [NTOK * CDIM],  g_hl [NTOK * CDIM];
__device__ fp16 g_atth[NTOK * CDIM], g_attl[NTOK * CDIM];
__device__ fp16 g_wpth[3 * CDIM * CDIM], g_wptl[3 * CDIM * CDIM];
__device__ fp16 g_woth[NL * CDIM * CDIM], g_wotl[NL * CDIM * CDIM];
__device__ fp16 g_w1th[(size_t)NL * NE * F4D * CDIM];
__device__ fp16 g_w2th[(size_t)NL * NE * CDIM * F4D];
__device__ fp16 g_hidh[(size_t)NTOK * NE * F4D];

// ======================= helpers =======================
__device__ __forceinline__ float gelu_exact(float v) {
    return 0.5f * v * (1.f + erff(v * 0.70710678118654752f));
}

__device__ __forceinline__ void mma16816(float* d, const unsigned* a, const unsigned* b) {
    asm volatile(
        "mma.sync.aligned.m16n8k16.row.col.f32.f16.f16.f32 "
        "{%0,%1,%2,%3}, {%4,%5,%6,%7}, {%8,%9}, {%0,%1,%2,%3};"
        : "+f"(d[0]), "+f"(d[1]), "+f"(d[2]), "+f"(d[3])
        : "r"(a[0]), "r"(a[1]), "r"(a[2]), "r"(a[3]), "r"(b[0]), "r"(b[1]));
}

__device__ __forceinline__ void cpa16(unsigned s, const void* g, int sz) {
    asm volatile("cp.async.cg.shared.global [%0], [%1], 16, %2;"
                 :: "r"(s), "l"(g), "r"(sz));
}
#define CPA_COMMIT() asm volatile("cp.async.commit_group;" ::: "memory")
#define CPA_WAIT(n)  asm volatile("cp.async.wait_group %0;" :: "n"(n) : "memory")

#define LDSM4(r0, r1, r2, r3, addr)                                            \
    asm volatile("ldmatrix.sync.aligned.m8n8.x4.shared.b16 {%0,%1,%2,%3}, [%4];" \
        : "=r"(r0), "=r"(r1), "=r"(r2), "=r"(r3) : "r"(addr))

// ======================= NT3 GEMM (attention paths, K-chunk 32) =============
#define STR 40                     // smem row stride (elems); 80B rows
#define PLANE_B (128 * 80)         // 10240
#define SMEM_NT3 81920             // 2 stages * 4 planes

template <int EP>
__global__ void __launch_bounds__(256, 2)
mma_gemm3(const fp16* __restrict__ Ah, const fp16* __restrict__ Al,
          long long lda,
          const fp16* __restrict__ Bh, const fp16* __restrict__ Bl,
          long long ldb,
          const float* __restrict__ bias,
          float* __restrict__ Cf, long long ldc,
          int M, int Ntiles, int KC) {
    constexpr unsigned STAGE_B = 4 * PLANE_B;
    extern __shared__ char smc[];
    unsigned smbase;
    asm("{ .reg .u64 t; cvta.to.shared.u64 t, %1; cvt.u32.u64 %0, t; }"
        : "=r"(smbase) : "l"(smc));

    const int tid = threadIdx.x, wid = tid >> 5, lane = tid & 31;
    const int g = lane >> 2, tg = lane & 3;
    const int wm = wid >> 2, wn = wid & 3;
    const int nt = blockIdx.x % Ntiles, mt = blockIdx.x / Ntiles;
    const int n0 = nt * 128, m0 = mt * 128;

    const int s4 = lane >> 3, lr = lane & 7;
    const int aRowL = lr + (s4 & 1) * 8, aColL = (s4 >> 1) * 8;
    const int bRowL = lr + (s4 >> 1) * 8, bColL = (s4 & 1) * 8;

    float acc[4][4][4];
#pragma unroll
    for (int i = 0; i < 4; i++)
#pragma unroll
        for (int j = 0; j < 4; j++)
#pragma unroll
            for (int r = 0; r < 4; r++) acc[i][j][r] = 0.f;

    const int fRow = tid >> 2, fCh = tid & 3;

    auto issue = [&](int c) {
        const int k0 = c * 32;
        unsigned sb = smbase + (c & 1) * STAGE_B;
#pragma unroll
        for (int i = 0; i < 2; i++) {
            int row = fRow + i * 64;
            int m = m0 + row;
            int sz = (m < M) ? 16 : 0;
            size_t go = (size_t)(m < M ? m : 0) * lda + k0 + fCh * 8;
            unsigned so = sb + row * 80 + fCh * 16;
            cpa16(so, Ah + go, sz);
            cpa16(so + PLANE_B, Al + go, sz);
        }
#pragma unroll
        for (int i = 0; i < 2; i++) {
            int row = fRow + i * 64;
            size_t go = (size_t)(n0 + row) * ldb + k0 + fCh * 8;
            unsigned so = sb + 2 * PLANE_B + row * 80 + fCh * 16;
            cpa16(so, Bh + go, 16);
            cpa16(so + PLANE_B, Bl + go, 16);
        }
    };

    issue(0);
    CPA_COMMIT();

    for (int c = 0; c < KC; ++c) {
        if (c + 1 < KC) { issue(c + 1); CPA_COMMIT(); CPA_WAIT(1); }
        else            { CPA_WAIT(0); }
        __syncthreads();

        unsigned sb = smbase + (c & 1) * STAGE_B;
#pragma unroll
        for (int ks = 0; ks < 2; ks++) {
            const int kb = ks * 16;
            unsigned bh_[4][2], bl_[4][2];
#pragma unroll
            for (int p = 0; p < 2; p++) {
                int rn0 = wn * 32 + p * 16;
                unsigned ba = sb + 2 * PLANE_B +
                              (unsigned)((rn0 + bRowL) * STR + kb + bColL) * 2;
                LDSM4(bh_[2 * p][0], bh_[2 * p][1], bh_[2 * p + 1][0], bh_[2 * p + 1][1], ba);
                LDSM4(bl_[2 * p][0], bl_[2 * p][1], bl_[2 * p + 1][0], bl_[2 * p + 1][1],
                      ba + PLANE_B);
            }
#pragma unroll
            for (int mi = 0; mi < 4; mi++) {
                int rm0 = wm * 64 + mi * 16;
                unsigned aa = sb + (unsigned)((rm0 + aRowL) * STR + kb + aColL) * 2;
                unsigned ah_[4], al_[4];
                LDSM4(ah_[0], ah_[1], ah_[2], ah_[3], aa);
                LDSM4(al_[0], al_[1], al_[2], al_[3], aa + PLANE_B);
#pragma unroll
                for (int ni = 0; ni < 4; ni++) {
                    mma16816(acc[mi][ni], ah_, bh_[ni]);
                    mma16816(acc[mi][ni], ah_, bl_[ni]);
                    mma16816(acc[mi][ni], al_, bh_[ni]);
                }
            }
        }
        __syncthreads();
    }

    // ---- epilogue ----
    float* sOut = (float*)smc;
#pragma unroll
    for (int mi = 0; mi < 4; mi++) {
        int lrow = wm * 64 + mi * 16 + g;
#pragma unroll
        for (int ni = 0; ni < 4; ni++) {
            int j = wn * 32 + ni * 8 + tg * 2;
            float b0 = 0.f, b1 = 0.f;
            if (EP >= 1) { b0 = bias[n0 + j]; b1 = bias[n0 + j + 1]; }
#pragma unroll
            for (int hh = 0; hh < 2; hh++) {
                float v0 = acc[mi][ni][hh * 2 + 0] + b0;
                float v1 = acc[mi][ni][hh * 2 + 1] + b1;
                *(float2*)&sOut[(lrow + hh * 8) * 132 + j] = make_float2(v0, v1);
            }
        }
    }
    __syncthreads();
#pragma unroll
    for (int i = 0; i < 16; i++) {
        int item = tid + i * 256;
        int row = item >> 5;
        int c4 = (item & 31) * 4;
        int m = m0 + row;
        if (m >= M) continue;
        float4 v = *(float4*)&sOut[row * 132 + c4];
        float* p = Cf + (size_t)m * ldc + n0 + c4;
        if (EP == 2) {
            float4 old = *(float4*)p;
            v.x += old.x; v.y += old.y; v.z += old.z; v.w += old.w;
        }
        *(float4*)p = v;
    }
}

// ======================= NT1 MoE GEMM (K-chunk 64, hi planes only) ==========
#define STR64 72                   // smem row stride elems (144B), conflict-free
#define PL64 (128 * 144)           // 18432 bytes per plane
#define SMEM_K64_NT1 73728         // 2 stages * 2 planes

template <int EP>
__global__ void __launch_bounds__(256, 2)
mma_gemm64(const fp16* __restrict__ Ah, long long lda, long long aExp,
           const fp16* __restrict__ Bh, long long ldb, long long bExp,
           const float* __restrict__ bias, long long biasExp,
           float* __restrict__ Cf, fp16* __restrict__ Ch,
           long long ldc, long long cExp,
           int M, int Ntiles, int KC) {
    constexpr unsigned STAGE = 2 * PL64;
    extern __shared__ char smc[];
    unsigned smbase;
    asm("{ .reg .u64 t; cvta.to.shared.u64 t, %1; cvt.u32.u64 %0, t; }"
        : "=r"(smbase) : "l"(smc));

    const int tid = threadIdx.x, wid = tid >> 5, lane = tid & 31;
    const int g = lane >> 2, tg = lane & 3;
    const int wm = wid >> 2, wn = wid & 3;
    const int e = blockIdx.y;
    const int nt = blockIdx.x % Ntiles, mt = blockIdx.x / Ntiles;
    const int n0 = nt * 128, m0 = mt * 128;

    const fp16* Abh = Ah + (size_t)e * aExp;
    const fp16* Bbh = Bh + (size_t)e * bExp;

    const int s4 = lane >> 3, lr = lane & 7;
    const int aRowL = lr + (s4 & 1) * 8, aColL = (s4 >> 1) * 8;
    const int bRowL = lr + (s4 >> 1) * 8, bColL = (s4 & 1) * 8;

    float acc[4][4][4];
#pragma unroll
    for (int i = 0; i < 4; i++)
#pragma unroll
        for (int j = 0; j < 4; j++)
#pragma unroll
            for (int r = 0; r < 4; r++) acc[i][j][r] = 0.f;

    auto issue = [&](int c) {
        const int k0 = c * 64;
        unsigned sb = smbase + (c & 1) * STAGE;
#pragma unroll
        for (int i = 0; i < 4; i++) {
            int item = tid + i * 256;
            int row = item >> 3, c8 = item & 7;
            int m = m0 + row;
            int sz = (m < M) ? 16 : 0;
            size_t go = (size_t)(m < M ? m : 0) * lda + k0 + c8 * 8;
            cpa16(sb + row * 144 + c8 * 16, Abh + go, sz);
        }
#pragma unroll
        for (int i = 0; i < 4; i++) {
            int item = tid + i * 256;
            int row = item >> 3, c8 = item & 7;
            size_t go = (size_t)(n0 + row) * ldb + k0 + c8 * 8;
            cpa16(sb + PL64 + row * 144 + c8 * 16, Bbh + go, 16);
        }
    };

    issue(0);
    CPA_COMMIT();

    for (int c = 0; c < KC; ++c) {
        if (c + 1 < KC) { issue(c + 1); CPA_COMMIT(); CPA_WAIT(1); }
        else            { CPA_WAIT(0); }
        __syncthreads();

        unsigned sb = smbase + (c & 1) * STAGE;
        unsigned sbB = sb + PL64;
#pragma unroll
        for (int ks = 0; ks < 4; ks++) {
            const int kb = ks * 16;
            unsigned bh_[4][2];
#pragma unroll
            for (int p = 0; p < 2; p++) {
                int rn0 = wn * 32 + p * 16;
                unsigned ba = sbB + (unsigned)((rn0 + bRowL) * STR64 + kb + bColL) * 2;
                LDSM4(bh_[2 * p][0], bh_[2 * p][1], bh_[2 * p + 1][0], bh_[2 * p + 1][1], ba);
            }
#pragma unroll
            for (int mi = 0; mi < 4; mi++) {
                int rm0 = wm * 64 + mi * 16;
                unsigned aa = sb + (unsigned)((rm0 + aRowL) * STR64 + kb + aColL) * 2;
                unsigned ah_[4];
                LDSM4(ah_[0], ah_[1], ah_[2], ah_[3], aa);
#pragma unroll
                for (int ni = 0; ni < 4; ni++)
                    mma16816(acc[mi][ni], ah_, bh_[ni]);
            }
        }
        __syncthreads();
    }

    // ---- epilogue: regs -> smem -> coalesced gmem ----
    float* sOut = (float*)smc;
#pragma unroll
    for (int mi = 0; mi < 4; mi++) {
        int lrow = wm * 64 + mi * 16 + g;
#pragma unroll
        for (int ni = 0; ni < 4; ni++) {
            int j = wn * 32 + ni * 8 + tg * 2;
            float b0 = bias[(size_t)e * biasExp + n0 + j];
            float b1 = bias[(size_t)e * biasExp + n0 + j + 1];
#pragma unroll
            for (int hh = 0; hh < 2; hh++) {
                float v0 = acc[mi][ni][hh * 2 + 0] + b0;
                float v1 = acc[mi][ni][hh * 2 + 1] + b1;
                if (EP == 3) { v0 = gelu_exact(v0); v1 = gelu_exact(v1); }
                *(float2*)&sOut[(lrow + hh * 8) * 132 + j] = make_float2(v0, v1);
            }
        }
    }
    __syncthreads();

    if (EP == 3) {
#pragma unroll
        for (int i = 0; i < 8; i++) {
            int item = tid + i * 256;
            int row = item >> 4;
            int c8 = (item & 15) * 8;
            int m = m0 + row;
            if (m >= M) continue;
            float4 f0 = *(float4*)&sOut[row * 132 + c8];
            float4 f1 = *(float4*)&sOut[row * 132 + c8 + 4];
            __half2 h0 = __floats2half2_rn(f0.x, f0.y);
            __half2 h1 = __floats2half2_rn(f0.z, f0.w);
            __half2 h2 = __floats2half2_rn(f1.x, f1.y);
            __half2 h3 = __floats2half2_rn(f1.z, f1.w);
            uint4 u = make_uint4(*(unsigned*)&h0, *(unsigned*)&h1,
                                 *(unsigned*)&h2, *(unsigned*)&h3);
            *(uint4*)(Ch + (size_t)e * cExp + (size_t)m * ldc + n0 + c8) = u;
        }
    } else {
#pragma unroll
        for (int i = 0; i < 16; i++) {
            int item = tid + i * 256;
            int row = item >> 5;
            int c4 = (item & 31) * 4;
            int m = m0 + row;
            if (m >= M) continue;
            float4 v = *(float4*)&sOut[row * 132 + c4];
            *(float4*)(Cf + (size_t)e * cExp + (size_t)m * ldc + n0 + c4) = v;
        }
    }
}

// ======================= transpose + split convert ==========================
// LO=1: write hi+lo planes; LO=0: hi plane only.
template <int LO>
__global__ void convT(const float* __restrict__ src, long long sExp, int K, int N,
                      fp16* __restrict__ th, fp16* __restrict__ tl, long long tExp) {
    __shared__ float t[32][33];
    int e = blockIdx.z;
    int k0 = blockIdx.x * 32, nn0 = blockIdx.y * 32;
    int tx = threadIdx.x & 31;
    int ty = threadIdx.x >> 5;
    const float* sp = src + (size_t)e * sExp;
#pragma unroll
    for (int r = 0; r < 4; r++) {
        int k = k0 + ty + r * 8;
        t[ty + r * 8][tx] = sp[(size_t)k * N + nn0 + tx];
    }
    __syncthreads();
    {
        int n = threadIdx.x >> 3;
        int kq = (threadIdx.x & 7) * 4;
        float v0 = t[kq + 0][n], v1 = t[kq + 1][n];
        float v2 = t[kq + 2][n], v3 = t[kq + 3][n];
        __half2 h0 = __floats2half2_rn(v0, v1);
        __half2 h1 = __floats2half2_rn(v2, v3);
        size_t o = (size_t)e * tExp + (size_t)(nn0 + n) * K + k0 + kq;
        *(uint2*)(th + o) = make_uint2(*(unsigned*)&h0, *(unsigned*)&h1);
        if (LO) {
            float2 r0 = __half22float2(h0), r1 = __half22float2(h1);
            __half2 l0 = __floats2half2_rn(v0 - r0.x, v1 - r0.y);
            __half2 l1 = __floats2half2_rn(v2 - r1.x, v3 - r1.y);
            *(uint2*)(tl + o) = make_uint2(*(unsigned*)&l0, *(unsigned*)&l1);
        }
    }
}

// ======================= pack Wq/Wk/Wv -> transposed fp16 planes [3C][C] ======
__global__ void pack_qkvT(const float* __restrict__ Wq,
                          const float* __restrict__ Wk,
                          const float* __restrict__ Wv,
                          fp16* __restrict__ th, fp16* __restrict__ tl) {
    int j = blockIdx.x;
    int which = j / CDIM, hs = j % CDIM;
    int h = hs / HSD, s = hs % HSD;
    const float* W = (which == 0) ? Wq : ((which == 1) ? Wk : Wv);
    for (int c = threadIdx.x; c < CDIM; c += 256) {
        float v = W[((size_t)h * CDIM + c) * HSD + s];
        fp16 hi = __float2half_rn(v);
        size_t o = (size_t)j * CDIM + c;
        th[o] = hi;
        tl[o] = __float2half_rn(v - __half2float(hi));
    }
}

// ======================= embedding =======================
__global__ void embed_kernel(const int* __restrict__ idx,
                             const float* __restrict__ tok,
                             const float* __restrict__ pos,
                             float* __restrict__ x) {
    int n = blockIdx.x;
    int t = n % TSEQ;
    int v = idx[n];
    for (int c = threadIdx.x; c < CDIM; c += blockDim.x)
        x[n * CDIM + c] = tok[v * CDIM + c] + pos[t * CDIM + c];
}

// ======================= layernorm (fp32 + fp16 hi/lo planes) ==============
__global__ void ln_kernel(const float* __restrict__ x,
                          const float* __restrict__ g,
                          const float* __restrict__ b,
                          float* __restrict__ out,
                          fp16* __restrict__ oh, fp16* __restrict__ ol) {
    int n = blockIdx.x;
    int tid = threadIdx.x;
    __shared__ float s1[256], s2[256];
    const float* xr = x + (size_t)n * CDIM;
    float a = 0.f, q = 0.f;
    for (int c = tid; c < CDIM; c += 256) { float v = xr[c]; a += v; q += v * v; }
    s1[tid] = a; s2[tid] = q;
    __syncthreads();
    for (int s = 128; s > 0; s >>= 1) {
        if (tid < s) { s1[tid] += s1[tid + s]; s2[tid] += s2[tid + s]; }
        __syncthreads();
    }
    float mean = s1[0] * (1.f / CDIM);
    float var  = s2[0] * (1.f / CDIM) - mean * mean;
    float r = rsqrtf(var + 1e-5f);
    for (int c = tid; c < CDIM; c += 256) {
        float o = (xr[c] - mean) * r * g[c] + b[c];
        size_t p = (size_t)n * CDIM + c;
        out[p] = o;
        fp16 hi = __float2half_rn(o);
        oh[p] = hi;
        ol[p] = __float2half_rn(o - __half2float(hi));
    }
}

// ======================= attention =======================
__global__ void attn_kernel(const float* __restrict__ qkv,
                            fp16* __restrict__ atth, fp16* __restrict__ attl) {
    int t = blockIdx.x, h = blockIdx.y, b = blockIdx.z;
    int tid = threadIdx.x;
    __shared__ float sc[TSEQ];
    __shared__ float qs[HSD];
    __shared__ float red[128];
    __shared__ float part[5 * HSD];

    int n0 = b * TSEQ;
    const float* Q = qkv + (size_t)(n0 + t) * (3 * CDIM) + h * HSD;
    if (tid < HSD) qs[tid] = Q[tid];
    __syncthreads();

    const float scale = 0.20412414523193154f;
    float lmax = -1e30f;
    for (int u = tid; u <= t; u += 128) {
        const float* Kp = qkv + (size_t)(n0 + u) * (3 * CDIM) + CDIM + h * HSD;
        float d = 0.f;
#pragma unroll
        for (int s = 0; s < HSD; s++) d += qs[s] * Kp[s];
        d *= scale;
        sc[u] = d;
        lmax = fmaxf(lmax, d);
    }
    red[tid] = lmax;
    __syncthreads();
    for (int s = 64; s > 0; s >>= 1) {
        if (tid < s) red[tid] = fmaxf(red[tid], red[tid + s]);
        __syncthreads();
    }
    float mx = red[0];
    __syncthreads();

    float lsum = 0.f;
    for (int u = tid; u <= t; u += 128) {
        float ev = expf(sc[u] - mx);
        sc[u] = ev;
        lsum += ev;
    }
    red[tid] = lsum;
    __syncthreads();
    for (int s = 64; s > 0; s >>= 1) {
        if (tid < s) red[tid] += red[tid + s];
        __syncthreads();
    }
    float inv = 1.f / red[0];
    __syncthreads();

    if (tid < 120) {
        int s = tid % HSD, gg = tid / HSD;
        float a = 0.f;
        for (int u = gg; u <= t; u += 5) {
            const float* Vp = qkv + (size_t)(n0 + u) * (3 * CDIM) + 2 * CDIM + h * HSD;
            a += sc[u] * Vp[s];
        }
        part[gg * HSD + s] = a;
    }
    __syncthreads();
    if (tid < HSD) {
        float a = (part[tid] + part[HSD + tid] + part[2 * HSD + tid]
                 + part[3 * HSD + tid] + part[4 * HSD + tid]) * inv;
        size_t o = (size_t)(n0 + t) * CDIM + h * HSD + tid;
        fp16 hi = __float2half_rn(a);
        atth[o] = hi;
        attl[o] = __float2half_rn(a - __half2float(hi));
    }
}

// ======================= gate softmax =======================
__global__ void gate_kernel(const float* __restrict__ h2,
                            const float* __restrict__ gw,
                            const float* __restrict__ gb,
                            float* __restrict__ gates) {
    int n = blockIdx.x;
    int e = threadIdx.x;
    const float* hr = h2 + (size_t)n * CDIM;
    float acc = gb[e];
    for (int c = 0; c < CDIM; c++) acc += hr[c] * gw[c * NE + e];
    float mx = acc;
    for (int o = 16; o > 0; o >>= 1) mx = fmaxf(mx, __shfl_xor_sync(0xFFFFFFFFu, mx, o));
    float ex = expf(acc - mx);
    float sm = ex;
    for (int o = 16; o > 0; o >>= 1) sm += __shfl_xor_sync(0xFFFFFFFFu, sm, o);
    gates[n * NE + e] = ex / sm;
}

// ======================= MoE combine =======================
__global__ void combine_kernel(const float* __restrict__ eo,
                               const float* __restrict__ gates,
                               float* __restrict__ x) {
    int n = blockIdx.x;
    __shared__ float gs[NE];
    if (threadIdx.x < NE) gs[threadIdx.x] = gates[n * NE + threadIdx.x];
    __syncthreads();
    for (int c = threadIdx.x; c < CDIM; c += blockDim.x) {
        float a = 0.f;
        const float* er = eo + (size_t)n * (NE * CDIM) + c;
#pragma unroll 8
        for (int e = 0; e < NE; e++) a += gs[e] * er[e * CDIM];
        x[(size_t)n * CDIM + c] += a;
    }
}

// ======================= scalar SGEMM (lm head only) =======================
__global__ void __launch_bounds__(256)
lm_head_kernel(const float* __restrict__ A, const float* __restrict__ B,
               const float* __restrict__ bias, float* __restrict__ C,
               int M, int N, int K) {
    __shared__ float As[64][17];
    __shared__ float Bs[16][64];
    int tid = threadIdx.x;
    int jTile = blockIdx.x * 64;
    int mTile = blockIdx.y * 64;
    int tx = tid & 15, ty = tid >> 4;

    float acc[4][4];
#pragma unroll
    for (int r = 0; r < 4; r++)
#pragma unroll
        for (int c = 0; c < 4; c++) acc[r][c] = 0.f;

    int aRow = tid >> 2, aK = (tid & 3) * 4;
    int bJ = tid & 63, bK0 = tid >> 6;

    for (int k0 = 0; k0 < K; k0 += 16) {
        int m = mTile + aRow;
        if (m < M) {
            float4 av = *(const float4*)(A + (size_t)m * K + k0 + aK);
            As[aRow][aK + 0] = av.x; As[aRow][aK + 1] = av.y;
            As[aRow][aK + 2] = av.z; As[aRow][aK + 3] = av.w;
        } else {
            As[aRow][aK + 0] = 0.f; As[aRow][aK + 1] = 0.f;
            As[aRow][aK + 2] = 0.f; As[aRow][aK + 3] = 0.f;
        }
#pragma unroll
        for (int i = 0; i < 4; i++) {
            int kk = bK0 + i * 4;
            Bs[kk][bJ] = (jTile + bJ < N)
                ? B[(size_t)(k0 + kk) * N + jTile + bJ] : 0.f;
        }
        __syncthreads();
#pragma unroll
        for (int k = 0; k < 16; k++) {
            float4 bv = *(const float4*)&Bs[k][tx * 4];
            float a0 = As[ty * 4 + 0][k], a1 = As[ty * 4 + 1][k];
            float a2 = As[ty * 4 + 2][k], a3 = As[ty * 4 + 3][k];
            acc[0][0] += a0 * bv.x; acc[0][1] += a0 * bv.y; acc[0][2] += a0 * bv.z; acc[0][3] += a0 * bv.w;
            acc[1][0] += a1 * bv.x; acc[1][1] += a1 * bv.y; acc[1][2] += a1 * bv.z; acc[1][3] += a1 * bv.w;
            acc[2][0] += a2 * bv.x; acc[2][1] += a2 * bv.y; acc[2][2] += a2 * bv.z; acc[2][3] += a2 * bv.w;
            acc[3][0] += a3 * bv.x; acc[3][1] += a3 * bv.y; acc[3][2] += a3 * bv.z; acc[3][3] += a3 * bv.w;
        }
        __syncthreads();
    }
#pragma unroll
    for (int r = 0; r < 4; r++) {
        int m = mTile + ty * 4 + r;
        if (m >= M) continue;
#pragma unroll
        for (int c = 0; c < 4; c++) {
            int j = jTile + tx * 4 + c;
            if (j >= N) continue;
            C[(size_t)m * N + j] = acc[r][c] + bias[j];
        }
    }
}

// ======================= launch =======================
extern "C" void kernel_launch(void* const* d_in, const int* in_sizes, int n_in,
                              void* d_out, int out_size) {
    const int*   idx    = (const int*)  d_in[0];
    const float* tok    = (const float*)d_in[1];
    const float* pos    = (const float*)d_in[2];
    const float* ln1_g  = (const float*)d_in[3];
    const float* ln1_b  = (const float*)d_in[4];
    const float* Wq     = (const float*)d_in[5];
    const float* Wk     = (const float*)d_in[6];
    const float* Wv     = (const float*)d_in[7];
    const float* Wo     = (const float*)d_in[8];
    const float* bo     = (const float*)d_in[9];
    const float* ln2_g  = (const float*)d_in[10];
    const float* ln2_b  = (const float*)d_in[11];
    const float* gate_w = (const float*)d_in[12];
    const float* gate_b = (const float*)d_in[13];
    const float* W1     = (const float*)d_in[14];
    const float* b1     = (const float*)d_in[15];
    const float* W2     = (const float*)d_in[16];
    const float* b2     = (const float*)d_in[17];
    const float* lnf_g  = (const float*)d_in[18];
    const float* lnf_b  = (const float*)d_in[19];
    const float* lm_w   = (const float*)d_in[20];
    const float* lm_b   = (const float*)d_in[21];
    float* out = (float*)d_out;

    float *x, *h, *qkv, *gates, *eo;
    fp16 *hh, *hl, *atth, *attl, *wpth, *wptl, *woth, *wotl;
    fp16 *w1th, *w2th, *hidh;
    cudaGetSymbolAddress((void**)&x,     g_x);
    cudaGetSymbolAddress((void**)&h,     g_h);
    cudaGetSymbolAddress((void**)&qkv,   g_qkv);
    cudaGetSymbolAddress((void**)&gates, g_gates);
    cudaGetSymbolAddress((void**)&eo,    g_eo);
    cudaGetSymbolAddress((void**)&hh,    g_hh);
    cudaGetSymbolAddress((void**)&hl,    g_hl);
    cudaGetSymbolAddress((void**)&atth,  g_atth);
    cudaGetSymbolAddress((void**)&attl,  g_attl);
    cudaGetSymbolAddress((void**)&wpth,  g_wpth);
    cudaGetSymbolAddress((void**)&wptl,  g_wptl);
    cudaGetSymbolAddress((void**)&woth,  g_woth);
    cudaGetSymbolAddress((void**)&wotl,  g_wotl);
    cudaGetSymbolAddress((void**)&w1th,  g_w1th);
    cudaGetSymbolAddress((void**)&w2th,  g_w2th);
    cudaGetSymbolAddress((void**)&hidh,  g_hidh);

    cudaFuncSetAttribute(mma_gemm3<0>, cudaFuncAttributeMaxDynamicSharedMemorySize, SMEM_NT3);
    cudaFuncSetAttribute(mma_gemm3<2>, cudaFuncAttributeMaxDynamicSharedMemorySize, SMEM_NT3);
    cudaFuncSetAttribute(mma_gemm64<3>, cudaFuncAttributeMaxDynamicSharedMemorySize, SMEM_K64_NT1);
    cudaFuncSetAttribute(mma_gemm64<1>, cudaFuncAttributeMaxDynamicSharedMemorySize, SMEM_K64_NT1);

    const int MT = (NTOK + 127) / 128;   // 7

    // ---- pre-convert all weights (transpose + fp16 hi split; lo only for Wo) ----
    for (int l = 0; l < NL; l++) {
        convT<0><<<dim3(CDIM / 32, F4D / 32, NE), 256>>>(
            W1 + (size_t)l * NE * CDIM * F4D, (long long)CDIM * F4D, CDIM, F4D,
            w1th + (size_t)l * NE * F4D * CDIM, nullptr,
            (long long)F4D * CDIM);
        convT<0><<<dim3(F4D / 32, CDIM / 32, NE), 256>>>(
            W2 + (size_t)l * NE * F4D * CDIM, (long long)F4D * CDIM, F4D, CDIM,
            w2th + (size_t)l * NE * CDIM * F4D, nullptr,
            (long long)CDIM * F4D);
        convT<1><<<dim3(CDIM / 32, CDIM / 32, 1), 256>>>(
            Wo + (size_t)l * CDIM * CDIM, 0, CDIM, CDIM,
            woth + (size_t)l * CDIM * CDIM, wotl + (size_t)l * CDIM * CDIM, 0);
    }

    embed_kernel<<<NTOK, 256>>>(idx, tok, pos, x);

    for (int l = 0; l < NL; l++) {
        // --- attention ---
        ln_kernel<<<NTOK, 256>>>(x, ln1_g + l * CDIM, ln1_b + l * CDIM, h, hh, hl);
        pack_qkvT<<<3 * CDIM, 256>>>(
            Wq + (size_t)l * NH * CDIM * HSD,
            Wk + (size_t)l * NH * CDIM * HSD,
            Wv + (size_t)l * NH * CDIM * HSD, wpth, wptl);
        mma_gemm3<0><<<dim3(MT * 18, 1), 256, SMEM_NT3>>>(
            hh, hl, CDIM, wpth, wptl, CDIM, nullptr,
            qkv, 3 * CDIM, NTOK, 18, CDIM / 32);
        attn_kernel<<<dim3(TSEQ, NH, BSZ), 128>>>(qkv, atth, attl);
        mma_gemm3<2><<<dim3(MT * 6, 1), 256, SMEM_NT3>>>(
            atth, attl, CDIM,
            woth + (size_t)l * CDIM * CDIM, wotl + (size_t)l * CDIM * CDIM, CDIM,
            bo + l * CDIM, x, CDIM, NTOK, 6, CDIM / 32);

        // --- MoE ---
        ln_kernel<<<NTOK, 256>>>(x, ln2_g + l * CDIM, ln2_b + l * CDIM, h, hh, hl);
        gate_kernel<<<NTOK, 32>>>(h, gate_w + (size_t)l * CDIM * NE,
                                  gate_b + l * NE, gates);
        // up: hid = gelu(h @ W1_e + b1_e) -> fp16 hi plane  (NT1, K-chunk 64)
        mma_gemm64<3><<<dim3(MT * (F4D / 128), NE), 256, SMEM_K64_NT1>>>(
            hh, CDIM, 0,
            w1th + (size_t)l * NE * F4D * CDIM, CDIM, (long long)F4D * CDIM,
            b1 + (size_t)l * NE * F4D, F4D,
            nullptr, hidh, (long long)NE * F4D, F4D,
            NTOK, F4D / 128, CDIM / 64);
        // down: eo = hid_e @ W2_e + b2_e  (NT1, K-chunk 64)
        mma_gemm64<1><<<dim3(MT * (CDIM / 128), NE), 256, SMEM_K64_NT1>>>(
            hidh, (long long)NE * F4D, F4D,
            w2th + (size_t)l * NE * CDIM * F4D, F4D, (long long)CDIM * F4D,
            b2 + (size_t)l * NE * CDIM, CDIM,
            eo, nullptr, (long long)NE * CDIM, CDIM,
            NTOK, CDIM / 128, F4D / 64);
        combine_kernel<<<NTOK, 256>>>(eo, gates, x);
    }

    // --- final LN + lm head ---
    ln_kernel<<<NTOK, 256>>>(x, lnf_g, lnf_b, h, hh, hl);
    lm_head_kernel<<<dim3((NV + 63) / 64, (NTOK + 63) / 64), 256>>>(
        h, lm_w, lm_b, out, NTOK, NV, CDIM);
}

// round 12
// speedup vs baseline: 2.5264x; 1.2434x over previous
#include <cuda_runtime.h>
#include <cuda_fp16.h>
#include <math.h>
#include <stdint.h>

// ---- problem constants ----
#define NTOK 844      // B*T = 2*422
#define TSEQ 422
#define BSZ  2
#define CDIM 768
#define NH   32
#define HSD  24
#define NE   32
#define F4D  3072
#define NL   2
#define NV   100

typedef __half fp16;

// ---- device scratch ----
__device__ float g_x  [NTOK * CDIM];
__device__ float g_h  [NTOK * CDIM];
__device__ float g_qkv[NTOK * 3 * CDIM];
__device__ float g_gates[NTOK * NE];
__device__ float g_gwT[NE * CDIM];

__device__ fp16 g_eo [(size_t)NTOK * NE * CDIM];
__device__ fp16 g_hh [NTOK * CDIM],  g_hl [NTOK * CDIM];
__device__ fp16 g_atth[NTOK * CDIM], g_attl[NTOK * CDIM];
__device__ fp16 g_wpth[3 * CDIM * CDIM], g_wptl[3 * CDIM * CDIM];
__device__ fp16 g_woth[NL * CDIM * CDIM], g_wotl[NL * CDIM * CDIM];
__device__ fp16 g_w1th[(size_t)NL * NE * F4D * CDIM];
__device__ fp16 g_w2th[(size_t)NL * NE * CDIM * F4D];
__device__ fp16 g_hidh[(size_t)NTOK * NE * F4D];

// ======================= helpers =======================
__device__ __forceinline__ float gelu_exact(float v) {
    return 0.5f * v * (1.f + erff(v * 0.70710678118654752f));
}

__device__ __forceinline__ void mma16816(float* d, const unsigned* a, const unsigned* b) {
    asm volatile(
        "mma.sync.aligned.m16n8k16.row.col.f32.f16.f16.f32 "
        "{%0,%1,%2,%3}, {%4,%5,%6,%7}, {%8,%9}, {%0,%1,%2,%3};"
        : "+f"(d[0]), "+f"(d[1]), "+f"(d[2]), "+f"(d[3])
        : "r"(a[0]), "r"(a[1]), "r"(a[2]), "r"(a[3]), "r"(b[0]), "r"(b[1]));
}

__device__ __forceinline__ void cpa16(unsigned s, const void* g, int sz) {
    asm volatile("cp.async.cg.shared.global [%0], [%1], 16, %2;"
                 :: "r"(s), "l"(g), "r"(sz));
}
#define CPA_COMMIT() asm volatile("cp.async.commit_group;" ::: "memory")
#define CPA_WAIT(n)  asm volatile("cp.async.wait_group %0;" :: "n"(n) : "memory")

#define LDSM4(r0, r1, r2, r3, addr)                                            \
    asm volatile("ldmatrix.sync.aligned.m8n8.x4.shared.b16 {%0,%1,%2,%3}, [%4];" \
        : "=r"(r0), "=r"(r1), "=r"(r2), "=r"(r3) : "r"(addr))

// ======================= NT3 GEMM (attention paths, K-chunk 32) =============
#define STR 40
#define PLANE_B (128 * 80)
#define SMEM_NT3 81920

template <int EP>
__global__ void __launch_bounds__(256, 2)
mma_gemm3(const fp16* __restrict__ Ah, const fp16* __restrict__ Al,
          long long lda,
          const fp16* __restrict__ Bh, const fp16* __restrict__ Bl,
          long long ldb,
          const float* __restrict__ bias,
          float* __restrict__ Cf, long long ldc,
          int M, int Ntiles, int KC) {
    constexpr unsigned STAGE_B = 4 * PLANE_B;
    extern __shared__ char smc[];
    unsigned smbase;
    asm("{ .reg .u64 t; cvta.to.shared.u64 t, %1; cvt.u32.u64 %0, t; }"
        : "=r"(smbase) : "l"(smc));

    const int tid = threadIdx.x, wid = tid >> 5, lane = tid & 31;
    const int g = lane >> 2, tg = lane & 3;
    const int wm = wid >> 2, wn = wid & 3;
    const int nt = blockIdx.x % Ntiles, mt = blockIdx.x / Ntiles;
    const int n0 = nt * 128, m0 = mt * 128;

    const int s4 = lane >> 3, lr = lane & 7;
    const int aRowL = lr + (s4 & 1) * 8, aColL = (s4 >> 1) * 8;
    const int bRowL = lr + (s4 >> 1) * 8, bColL = (s4 & 1) * 8;

    float acc[4][4][4];
#pragma unroll
    for (int i = 0; i < 4; i++)
#pragma unroll
        for (int j = 0; j < 4; j++)
#pragma unroll
            for (int r = 0; r < 4; r++) acc[i][j][r] = 0.f;

    const int fRow = tid >> 2, fCh = tid & 3;

    auto issue = [&](int c) {
        const int k0 = c * 32;
        unsigned sb = smbase + (c & 1) * STAGE_B;
#pragma unroll
        for (int i = 0; i < 2; i++) {
            int row = fRow + i * 64;
            int m = m0 + row;
            int sz = (m < M) ? 16 : 0;
            size_t go = (size_t)(m < M ? m : 0) * lda + k0 + fCh * 8;
            unsigned so = sb + row * 80 + fCh * 16;
            cpa16(so, Ah + go, sz);
            cpa16(so + PLANE_B, Al + go, sz);
        }
#pragma unroll
        for (int i = 0; i < 2; i++) {
            int row = fRow + i * 64;
            size_t go = (size_t)(n0 + row) * ldb + k0 + fCh * 8;
            unsigned so = sb + 2 * PLANE_B + row * 80 + fCh * 16;
            cpa16(so, Bh + go, 16);
            cpa16(so + PLANE_B, Bl + go, 16);
        }
    };

    issue(0);
    CPA_COMMIT();

    for (int c = 0; c < KC; ++c) {
        if (c + 1 < KC) { issue(c + 1); CPA_COMMIT(); CPA_WAIT(1); }
        else            { CPA_WAIT(0); }
        __syncthreads();

        unsigned sb = smbase + (c & 1) * STAGE_B;
#pragma unroll
        for (int ks = 0; ks < 2; ks++) {
            const int kb = ks * 16;
            unsigned bh_[4][2], bl_[4][2];
#pragma unroll
            for (int p = 0; p < 2; p++) {
                int rn0 = wn * 32 + p * 16;
                unsigned ba = sb + 2 * PLANE_B +
                              (unsigned)((rn0 + bRowL) * STR + kb + bColL) * 2;
                LDSM4(bh_[2 * p][0], bh_[2 * p][1], bh_[2 * p + 1][0], bh_[2 * p + 1][1], ba);
                LDSM4(bl_[2 * p][0], bl_[2 * p][1], bl_[2 * p + 1][0], bl_[2 * p + 1][1],
                      ba + PLANE_B);
            }
#pragma unroll
            for (int mi = 0; mi < 4; mi++) {
                int rm0 = wm * 64 + mi * 16;
                unsigned aa = sb + (unsigned)((rm0 + aRowL) * STR + kb + aColL) * 2;
                unsigned ah_[4], al_[4];
                LDSM4(ah_[0], ah_[1], ah_[2], ah_[3], aa);
                LDSM4(al_[0], al_[1], al_[2], al_[3], aa + PLANE_B);
#pragma unroll
                for (int ni = 0; ni < 4; ni++) {
                    mma16816(acc[mi][ni], ah_, bh_[ni]);
                    mma16816(acc[mi][ni], ah_, bl_[ni]);
                    mma16816(acc[mi][ni], al_, bh_[ni]);
                }
            }
        }
        __syncthreads();
    }

    float* sOut = (float*)smc;
#pragma unroll
    for (int mi = 0; mi < 4; mi++) {
        int lrow = wm * 64 + mi * 16 + g;
#pragma unroll
        for (int ni = 0; ni < 4; ni++) {
            int j = wn * 32 + ni * 8 + tg * 2;
            float b0 = 0.f, b1 = 0.f;
            if (EP >= 1) { b0 = bias[n0 + j]; b1 = bias[n0 + j + 1]; }
#pragma unroll
            for (int hh = 0; hh < 2; hh++) {
                float v0 = acc[mi][ni][hh * 2 + 0] + b0;
                float v1 = acc[mi][ni][hh * 2 + 1] + b1;
                *(float2*)&sOut[(lrow + hh * 8) * 132 + j] = make_float2(v0, v1);
            }
        }
    }
    __syncthreads();
#pragma unroll
    for (int i = 0; i < 16; i++) {
        int item = tid + i * 256;
        int row = item >> 5;
        int c4 = (item & 31) * 4;
        int m = m0 + row;
        if (m >= M) continue;
        float4 v = *(float4*)&sOut[row * 132 + c4];
        float* p = Cf + (size_t)m * ldc + n0 + c4;
        if (EP == 2) {
            float4 old = *(float4*)p;
            v.x += old.x; v.y += old.y; v.z += old.z; v.w += old.w;
        }
        *(float4*)p = v;
    }
}

// ======================= NT1 MoE GEMM (K-chunk 64, hi planes only) ==========
// EP: 3 = gelu(+bias) -> fp16 Ch; 4 = +bias -> fp16 Ch
#define STR64 72
#define PL64 (128 * 144)
#define SMEM_K64_NT1 73728

template <int EP>
__global__ void __launch_bounds__(256, 2)
mma_gemm64(const fp16* __restrict__ Ah, long long lda, long long aExp,
           const fp16* __restrict__ Bh, long long ldb, long long bExp,
           const float* __restrict__ bias, long long biasExp,
           fp16* __restrict__ Ch, long long ldc, long long cExp,
           int M, int Ntiles, int KC) {
    constexpr unsigned STAGE = 2 * PL64;
    extern __shared__ char smc[];
    unsigned smbase;
    asm("{ .reg .u64 t; cvta.to.shared.u64 t, %1; cvt.u32.u64 %0, t; }"
        : "=r"(smbase) : "l"(smc));

    const int tid = threadIdx.x, wid = tid >> 5, lane = tid & 31;
    const int g = lane >> 2, tg = lane & 3;
    const int wm = wid >> 2, wn = wid & 3;
    const int e = blockIdx.y;
    const int nt = blockIdx.x % Ntiles, mt = blockIdx.x / Ntiles;
    const int n0 = nt * 128, m0 = mt * 128;

    const fp16* Abh = Ah + (size_t)e * aExp;
    const fp16* Bbh = Bh + (size_t)e * bExp;

    const int s4 = lane >> 3, lr = lane & 7;
    const int aRowL = lr + (s4 & 1) * 8, aColL = (s4 >> 1) * 8;
    const int bRowL = lr + (s4 >> 1) * 8, bColL = (s4 & 1) * 8;

    float acc[4][4][4];
#pragma unroll
    for (int i = 0; i < 4; i++)
#pragma unroll
        for (int j = 0; j < 4; j++)
#pragma unroll
            for (int r = 0; r < 4; r++) acc[i][j][r] = 0.f;

    auto issue = [&](int c) {
        const int k0 = c * 64;
        unsigned sb = smbase + (c & 1) * STAGE;
#pragma unroll
        for (int i = 0; i < 4; i++) {
            int item = tid + i * 256;
            int row = item >> 3, c8 = item & 7;
            int m = m0 + row;
            int sz = (m < M) ? 16 : 0;
            size_t go = (size_t)(m < M ? m : 0) * lda + k0 + c8 * 8;
            cpa16(sb + row * 144 + c8 * 16, Abh + go, sz);
        }
#pragma unroll
        for (int i = 0; i < 4; i++) {
            int item = tid + i * 256;
            int row = item >> 3, c8 = item & 7;
            size_t go = (size_t)(n0 + row) * ldb + k0 + c8 * 8;
            cpa16(sb + PL64 + row * 144 + c8 * 16, Bbh + go, 16);
        }
    };

    issue(0);
    CPA_COMMIT();

    for (int c = 0; c < KC; ++c) {
        if (c + 1 < KC) { issue(c + 1); CPA_COMMIT(); CPA_WAIT(1); }
        else            { CPA_WAIT(0); }
        __syncthreads();

        unsigned sb = smbase + (c & 1) * STAGE;
        unsigned sbB = sb + PL64;
#pragma unroll
        for (int ks = 0; ks < 4; ks++) {
            const int kb = ks * 16;
            unsigned bh_[4][2];
#pragma unroll
            for (int p = 0; p < 2; p++) {
                int rn0 = wn * 32 + p * 16;
                unsigned ba = sbB + (unsigned)((rn0 + bRowL) * STR64 + kb + bColL) * 2;
                LDSM4(bh_[2 * p][0], bh_[2 * p][1], bh_[2 * p + 1][0], bh_[2 * p + 1][1], ba);
            }
#pragma unroll
            for (int mi = 0; mi < 4; mi++) {
                int rm0 = wm * 64 + mi * 16;
                unsigned aa = sb + (unsigned)((rm0 + aRowL) * STR64 + kb + aColL) * 2;
                unsigned ah_[4];
                LDSM4(ah_[0], ah_[1], ah_[2], ah_[3], aa);
#pragma unroll
                for (int ni = 0; ni < 4; ni++)
                    mma16816(acc[mi][ni], ah_, bh_[ni]);
            }
        }
        __syncthreads();
    }

    // ---- epilogue: regs -> smem -> fp16 coalesced gmem ----
    float* sOut = (float*)smc;
#pragma unroll
    for (int mi = 0; mi < 4; mi++) {
        int lrow = wm * 64 + mi * 16 + g;
#pragma unroll
        for (int ni = 0; ni < 4; ni++) {
            int j = wn * 32 + ni * 8 + tg * 2;
            float b0 = bias[(size_t)e * biasExp + n0 + j];
            float b1 = bias[(size_t)e * biasExp + n0 + j + 1];
#pragma unroll
            for (int hh = 0; hh < 2; hh++) {
                float v0 = acc[mi][ni][hh * 2 + 0] + b0;
                float v1 = acc[mi][ni][hh * 2 + 1] + b1;
                if (EP == 3) { v0 = gelu_exact(v0); v1 = gelu_exact(v1); }
                *(float2*)&sOut[(lrow + hh * 8) * 132 + j] = make_float2(v0, v1);
            }
        }
    }
    __syncthreads();
#pragma unroll
    for (int i = 0; i < 8; i++) {
        int item = tid + i * 256;
        int row = item >> 4;
        int c8 = (item & 15) * 8;
        int m = m0 + row;
        if (m >= M) continue;
        float4 f0 = *(float4*)&sOut[row * 132 + c8];
        float4 f1 = *(float4*)&sOut[row * 132 + c8 + 4];
        __half2 h0 = __floats2half2_rn(f0.x, f0.y);
        __half2 h1 = __floats2half2_rn(f0.z, f0.w);
        __half2 h2 = __floats2half2_rn(f1.x, f1.y);
        __half2 h3 = __floats2half2_rn(f1.z, f1.w);
        uint4 u = make_uint4(*(unsigned*)&h0, *(unsigned*)&h1,
                             *(unsigned*)&h2, *(unsigned*)&h3);
        *(uint4*)(Ch + (size_t)e * cExp + (size_t)m * ldc + n0 + c8) = u;
    }
}

// ======================= transpose + split convert ==========================
template <int LO>
__global__ void convT(const float* __restrict__ src, long long sExp, int K, int N,
                      fp16* __restrict__ th, fp16* __restrict__ tl, long long tExp) {
    __shared__ float t[32][33];
    int e = blockIdx.z;
    int k0 = blockIdx.x * 32, nn0 = blockIdx.y * 32;
    int tx = threadIdx.x & 31;
    int ty = threadIdx.x >> 5;
    const float* sp = src + (size_t)e * sExp;
#pragma unroll
    for (int r = 0; r < 4; r++) {
        int k = k0 + ty + r * 8;
        t[ty + r * 8][tx] = sp[(size_t)k * N + nn0 + tx];
    }
    __syncthreads();
    {
        int n = threadIdx.x >> 3;
        int kq = (threadIdx.x & 7) * 4;
        float v0 = t[kq + 0][n], v1 = t[kq + 1][n];
        float v2 = t[kq + 2][n], v3 = t[kq + 3][n];
        __half2 h0 = __floats2half2_rn(v0, v1);
        __half2 h1 = __floats2half2_rn(v2, v3);
        size_t o = (size_t)e * tExp + (size_t)(nn0 + n) * K + k0 + kq;
        *(uint2*)(th + o) = make_uint2(*(unsigned*)&h0, *(unsigned*)&h1);
        if (LO) {
            float2 r0 = __half22float2(h0), r1 = __half22float2(h1);
            __half2 l0 = __floats2half2_rn(v0 - r0.x, v1 - r0.y);
            __half2 l1 = __floats2half2_rn(v2 - r1.x, v3 - r1.y);
            *(uint2*)(tl + o) = make_uint2(*(unsigned*)&l0, *(unsigned*)&l1);
        }
    }
}

// ======================= gate_w transpose (fp32, [C][E] -> [E][C]) ==========
__global__ void gwT_kernel(const float* __restrict__ gw, float* __restrict__ gwT) {
    int i = blockIdx.x * blockDim.x + threadIdx.x;
    if (i >= NE * CDIM) return;
    int e = i / CDIM, c = i % CDIM;
    gwT[i] = gw[c * NE + e];
}

// ======================= pack Wq/Wk/Wv -> transposed fp16 planes [3C][C] ======
__global__ void pack_qkvT(const float* __restrict__ Wq,
                          const float* __restrict__ Wk,
                          const float* __restrict__ Wv,
                          fp16* __restrict__ th, fp16* __restrict__ tl) {
    int j = blockIdx.x;
    int which = j / CDIM, hs = j % CDIM;
    int h = hs / HSD, s = hs % HSD;
    const float* W = (which == 0) ? Wq : ((which == 1) ? Wk : Wv);
    for (int c = threadIdx.x; c < CDIM; c += 256) {
        float v = W[((size_t)h * CDIM + c) * HSD + s];
        fp16 hi = __float2half_rn(v);
        size_t o = (size_t)j * CDIM + c;
        th[o] = hi;
        tl[o] = __float2half_rn(v - __half2float(hi));
    }
}

// ======================= embedding =======================
__global__ void embed_kernel(const int* __restrict__ idx,
                             const float* __restrict__ tok,
                             const float* __restrict__ pos,
                             float* __restrict__ x) {
    int n = blockIdx.x;
    int t = n % TSEQ;
    int v = idx[n];
    for (int c = threadIdx.x; c < CDIM; c += blockDim.x)
        x[n * CDIM + c] = tok[v * CDIM + c] + pos[t * CDIM + c];
}

// ======================= layernorm =======================
__global__ void ln_kernel(const float* __restrict__ x,
                          const float* __restrict__ g,
                          const float* __restrict__ b,
                          float* __restrict__ out,
                          fp16* __restrict__ oh, fp16* __restrict__ ol) {
    int n = blockIdx.x;
    int tid = threadIdx.x;
    __shared__ float s1[256], s2[256];
    const float* xr = x + (size_t)n * CDIM;
    float a = 0.f, q = 0.f;
    for (int c = tid; c < CDIM; c += 256) { float v = xr[c]; a += v; q += v * v; }
    s1[tid] = a; s2[tid] = q;
    __syncthreads();
    for (int s = 128; s > 0; s >>= 1) {
        if (tid < s) { s1[tid] += s1[tid + s]; s2[tid] += s2[tid + s]; }
        __syncthreads();
    }
    float mean = s1[0] * (1.f / CDIM);
    float var  = s2[0] * (1.f / CDIM) - mean * mean;
    float r = rsqrtf(var + 1e-5f);
    for (int c = tid; c < CDIM; c += 256) {
        float o = (xr[c] - mean) * r * g[c] + b[c];
        size_t p = (size_t)n * CDIM + c;
        out[p] = o;
        fp16 hi = __float2half_rn(o);
        oh[p] = hi;
        ol[p] = __float2half_rn(o - __half2float(hi));
    }
}

// ======================= attention v2: block per (b,h), K/V staged ==========
#define KV_STR 25
#define ATTN_SMEM ((TSEQ * KV_STR * 2 + 8 * 424 + 8 * 24) * 4)   // 98736 B

__global__ void __launch_bounds__(256)
attn2_kernel(const float* __restrict__ qkv,
             fp16* __restrict__ atth, fp16* __restrict__ attl) {
    int h = blockIdx.x, b = blockIdx.y;
    extern __shared__ float sm[];
    float* Ks = sm;                          // [TSEQ][25]
    float* Vs = Ks + TSEQ * KV_STR;          // [TSEQ][25]
    float* sc = Vs + TSEQ * KV_STR;          // [8][424]
    float* qb = sc + 8 * 424;                // [8][24]

    int tid = threadIdx.x, wid = tid >> 5, lane = tid & 31;
    int n0 = b * TSEQ;

    // stage K and V for this head
    for (int i = tid; i < TSEQ * HSD; i += 256) {
        int u = i / HSD, s = i - u * HSD;
        const float* base = qkv + (size_t)(n0 + u) * (3 * CDIM) + h * HSD + s;
        Ks[u * KV_STR + s] = base[CDIM];
        Vs[u * KV_STR + s] = base[2 * CDIM];
    }
    __syncthreads();

    const float scale = 0.20412414523193154f;
    float* scw = sc + wid * 424;
    float* qw  = qb + wid * 24;

    for (int t = wid; t < TSEQ; t += 8) {
        if (lane < HSD)
            qw[lane] = qkv[(size_t)(n0 + t) * (3 * CDIM) + h * HSD + lane];
        __syncwarp();

        float lmax = -1e30f;
        for (int u = lane; u <= t; u += 32) {
            const float* kr = Ks + u * KV_STR;
            float d = 0.f;
#pragma unroll
            for (int s = 0; s < HSD; s++) d += qw[s] * kr[s];
            d *= scale;
            scw[u] = d;
            lmax = fmaxf(lmax, d);
        }
        for (int o = 16; o > 0; o >>= 1)
            lmax = fmaxf(lmax, __shfl_xor_sync(0xFFFFFFFFu, lmax, o));

        float lsum = 0.f;
        for (int u = lane; u <= t; u += 32) {
            float ev = expf(scw[u] - lmax);
            scw[u] = ev;
            lsum += ev;
        }
        for (int o = 16; o > 0; o >>= 1)
            lsum += __shfl_xor_sync(0xFFFFFFFFu, lsum, o);
        float inv = 1.f / lsum;
        __syncwarp();

        if (lane < HSD) {
            float a = 0.f;
            for (int u = 0; u <= t; u++)
                a += scw[u] * Vs[u * KV_STR + lane];
            a *= inv;
            size_t o = (size_t)(n0 + t) * CDIM + h * HSD + lane;
            fp16 hi = __float2half_rn(a);
            atth[o] = hi;
            attl[o] = __float2half_rn(a - __half2float(hi));
        }
        __syncwarp();
    }
}

// ======================= gate softmax v2 =======================
__global__ void __launch_bounds__(256)
gate2_kernel(const float* __restrict__ h2, const float* __restrict__ gwT,
             const float* __restrict__ gb, float* __restrict__ gates) {
    int n = blockIdx.x;
    int tid = threadIdx.x, wid = tid >> 5, lane = tid & 31;
    __shared__ float lg[NE];
    __shared__ float hsm[CDIM];
    for (int c = tid; c < CDIM; c += 256) hsm[c] = h2[(size_t)n * CDIM + c];
    __syncthreads();
    for (int e = wid; e < NE; e += 8) {
        const float* w = gwT + (size_t)e * CDIM;
        float a = 0.f;
        for (int c = lane; c < CDIM; c += 32) a += hsm[c] * w[c];
        for (int o = 16; o > 0; o >>= 1) a += __shfl_xor_sync(0xFFFFFFFFu, a, o);
        if (lane == 0) lg[e] = a + gb[e];
    }
    __syncthreads();
    if (tid < 32) {
        float v = lg[tid];
        float mx = v;
        for (int o = 16; o > 0; o >>= 1) mx = fmaxf(mx, __shfl_xor_sync(0xFFFFFFFFu, mx, o));
        float ex = expf(v - mx);
        float smv = ex;
        for (int o = 16; o > 0; o >>= 1) smv += __shfl_xor_sync(0xFFFFFFFFu, smv, o);
        gates[n * NE + tid] = ex / smv;
    }
}

// ======================= MoE combine (fp16 eo) =======================
__global__ void combine_kernel(const fp16* __restrict__ eo,
                               const float* __restrict__ gates,
                               float* __restrict__ x) {
    int n = blockIdx.x;
    __shared__ float gs[NE];
    if (threadIdx.x < NE) gs[threadIdx.x] = gates[n * NE + threadIdx.x];
    __syncthreads();
    for (int c = threadIdx.x; c < CDIM; c += blockDim.x) {
        float a = 0.f;
        const fp16* er = eo + (size_t)n * (NE * CDIM) + c;
#pragma unroll 8
        for (int e = 0; e < NE; e++) a += gs[e] * __half2float(er[e * CDIM]);
        x[(size_t)n * CDIM + c] += a;
    }
}

// ======================= scalar SGEMM (lm head only) =======================
__global__ void __launch_bounds__(256)
lm_head_kernel(const float* __restrict__ A, const float* __restrict__ B,
               const float* __restrict__ bias, float* __restrict__ C,
               int M, int N, int K) {
    __shared__ float As[64][17];
    __shared__ float Bs[16][64];
    int tid = threadIdx.x;
    int jTile = blockIdx.x * 64;
    int mTile = blockIdx.y * 64;
    int tx = tid & 15, ty = tid >> 4;

    float acc[4][4];
#pragma unroll
    for (int r = 0; r < 4; r++)
#pragma unroll
        for (int c = 0; c < 4; c++) acc[r][c] = 0.f;

    int aRow = tid >> 2, aK = (tid & 3) * 4;
    int bJ = tid & 63, bK0 = tid >> 6;

    for (int k0 = 0; k0 < K; k0 += 16) {
        int m = mTile + aRow;
        if (m < M) {
            float4 av = *(const float4*)(A + (size_t)m * K + k0 + aK);
            As[aRow][aK + 0] = av.x; As[aRow][aK + 1] = av.y;
            As[aRow][aK + 2] = av.z; As[aRow][aK + 3] = av.w;
        } else {
            As[aRow][aK + 0] = 0.f; As[aRow][aK + 1] = 0.f;
            As[aRow][aK + 2] = 0.f; As[aRow][aK + 3] = 0.f;
        }
#pragma unroll
        for (int i = 0; i < 4; i++) {
            int kk = bK0 + i * 4;
            Bs[kk][bJ] = (jTile + bJ < N)
                ? B[(size_t)(k0 + kk) * N + jTile + bJ] : 0.f;
        }
        __syncthreads();
#pragma unroll
        for (int k = 0; k < 16; k++) {
            float4 bv = *(const float4*)&Bs[k][tx * 4];
            float a0 = As[ty * 4 + 0][k], a1 = As[ty * 4 + 1][k];
            float a2 = As[ty * 4 + 2][k], a3 = As[ty * 4 + 3][k];
            acc[0][0] += a0 * bv.x; acc[0][1] += a0 * bv.y; acc[0][2] += a0 * bv.z; acc[0][3] += a0 * bv.w;
            acc[1][0] += a1 * bv.x; acc[1][1] += a1 * bv.y; acc[1][2] += a1 * bv.z; acc[1][3] += a1 * bv.w;
            acc[2][0] += a2 * bv.x; acc[2][1] += a2 * bv.y; acc[2][2] += a2 * bv.z; acc[2][3] += a2 * bv.w;
            acc[3][0] += a3 * bv.x; acc[3][1] += a3 * bv.y; acc[3][2] += a3 * bv.z; acc[3][3] += a3 * bv.w;
        }
        __syncthreads();
    }
#pragma unroll
    for (int r = 0; r < 4; r++) {
        int m = mTile + ty * 4 + r;
        if (m >= M) continue;
#pragma unroll
        for (int c = 0; c < 4; c++) {
            int j = jTile + tx * 4 + c;
            if (j >= N) continue;
            C[(size_t)m * N + j] = acc[r][c] + bias[j];
        }
    }
}

// ======================= launch =======================
extern "C" void kernel_launch(void* const* d_in, const int* in_sizes, int n_in,
                              void* d_out, int out_size) {
    const int*   idx    = (const int*)  d_in[0];
    const float* tok    = (const float*)d_in[1];
    const float* pos    = (const float*)d_in[2];
    const float* ln1_g  = (const float*)d_in[3];
    const float* ln1_b  = (const float*)d_in[4];
    const float* Wq     = (const float*)d_in[5];
    const float* Wk     = (const float*)d_in[6];
    const float* Wv     = (const float*)d_in[7];
    const float* Wo     = (const float*)d_in[8];
    const float* bo     = (const float*)d_in[9];
    const float* ln2_g  = (const float*)d_in[10];
    const float* ln2_b  = (const float*)d_in[11];
    const float* gate_w = (const float*)d_in[12];
    const float* gate_b = (const float*)d_in[13];
    const float* W1     = (const float*)d_in[14];
    const float* b1     = (const float*)d_in[15];
    const float* W2     = (const float*)d_in[16];
    const float* b2     = (const float*)d_in[17];
    const float* lnf_g  = (const float*)d_in[18];
    const float* lnf_b  = (const float*)d_in[19];
    const float* lm_w   = (const float*)d_in[20];
    const float* lm_b   = (const float*)d_in[21];
    float* out = (float*)d_out;

    float *x, *h, *qkv, *gates, *gwT;
    fp16 *eo, *hh, *hl, *atth, *attl, *wpth, *wptl, *woth, *wotl;
    fp16 *w1th, *w2th, *hidh;
    cudaGetSymbolAddress((void**)&x,     g_x);
    cudaGetSymbolAddress((void**)&h,     g_h);
    cudaGetSymbolAddress((void**)&qkv,   g_qkv);
    cudaGetSymbolAddress((void**)&gates, g_gates);
    cudaGetSymbolAddress((void**)&gwT,   g_gwT);
    cudaGetSymbolAddress((void**)&eo,    g_eo);
    cudaGetSymbolAddress((void**)&hh,    g_hh);
    cudaGetSymbolAddress((void**)&hl,    g_hl);
    cudaGetSymbolAddress((void**)&atth,  g_atth);
    cudaGetSymbolAddress((void**)&attl,  g_attl);
    cudaGetSymbolAddress((void**)&wpth,  g_wpth);
    cudaGetSymbolAddress((void**)&wptl,  g_wptl);
    cudaGetSymbolAddress((void**)&woth,  g_woth);
    cudaGetSymbolAddress((void**)&wotl,  g_wotl);
    cudaGetSymbolAddress((void**)&w1th,  g_w1th);
    cudaGetSymbolAddress((void**)&w2th,  g_w2th);
    cudaGetSymbolAddress((void**)&hidh,  g_hidh);

    cudaFuncSetAttribute(mma_gemm3<0>, cudaFuncAttributeMaxDynamicSharedMemorySize, SMEM_NT3);
    cudaFuncSetAttribute(mma_gemm3<2>, cudaFuncAttributeMaxDynamicSharedMemorySize, SMEM_NT3);
    cudaFuncSetAttribute(mma_gemm64<3>, cudaFuncAttributeMaxDynamicSharedMemorySize, SMEM_K64_NT1);
    cudaFuncSetAttribute(mma_gemm64<4>, cudaFuncAttributeMaxDynamicSharedMemorySize, SMEM_K64_NT1);
    cudaFuncSetAttribute(attn2_kernel, cudaFuncAttributeMaxDynamicSharedMemorySize, ATTN_SMEM);

    const int MT = (NTOK + 127) / 128;   // 7

    // ---- pre-convert weights ----
    for (int l = 0; l < NL; l++) {
        convT<0><<<dim3(CDIM / 32, F4D / 32, NE), 256>>>(
            W1 + (size_t)l * NE * CDIM * F4D, (long long)CDIM * F4D, CDIM, F4D,
            w1th + (size_t)l * NE * F4D * CDIM, nullptr,
            (long long)F4D * CDIM);
        convT<0><<<dim3(F4D / 32, CDIM / 32, NE), 256>>>(
            W2 + (size_t)l * NE * F4D * CDIM, (long long)F4D * CDIM, F4D, CDIM,
            w2th + (size_t)l * NE * CDIM * F4D, nullptr,
            (long long)CDIM * F4D);
        convT<1><<<dim3(CDIM / 32, CDIM / 32, 1), 256>>>(
            Wo + (size_t)l * CDIM * CDIM, 0, CDIM, CDIM,
            woth + (size_t)l * CDIM * CDIM, wotl + (size_t)l * CDIM * CDIM, 0);
    }

    embed_kernel<<<NTOK, 256>>>(idx, tok, pos, x);

    for (int l = 0; l < NL; l++) {
        // --- attention ---
        ln_kernel<<<NTOK, 256>>>(x, ln1_g + l * CDIM, ln1_b + l * CDIM, h, hh, hl);
        pack_qkvT<<<3 * CDIM, 256>>>(
            Wq + (size_t)l * NH * CDIM * HSD,
            Wk + (size_t)l * NH * CDIM * HSD,
            Wv + (size_t)l * NH * CDIM * HSD, wpth, wptl);
        mma_gemm3<0><<<dim3(MT * 18, 1), 256, SMEM_NT3>>>(
            hh, hl, CDIM, wpth, wptl, CDIM, nullptr,
            qkv, 3 * CDIM, NTOK, 18, CDIM / 32);
        attn2_kernel<<<dim3(NH, BSZ), 256, ATTN_SMEM>>>(qkv, atth, attl);
        mma_gemm3<2><<<dim3(MT * 6, 1), 256, SMEM_NT3>>>(
            atth, attl, CDIM,
            woth + (size_t)l * CDIM * CDIM, wotl + (size_t)l * CDIM * CDIM, CDIM,
            bo + l * CDIM, x, CDIM, NTOK, 6, CDIM / 32);

        // --- MoE ---
        ln_kernel<<<NTOK, 256>>>(x, ln2_g + l * CDIM, ln2_b + l * CDIM, h, hh, hl);
        gwT_kernel<<<(NE * CDIM + 255) / 256, 256>>>(
            gate_w + (size_t)l * CDIM * NE, gwT);
        gate2_kernel<<<NTOK, 256>>>(h, gwT, gate_b + l * NE, gates);
        // up: hid = gelu(h @ W1_e + b1_e) -> fp16  (NT1, K-chunk 64)
        mma_gemm64<3><<<dim3(MT * (F4D / 128), NE), 256, SMEM_K64_NT1>>>(
            hh, CDIM, 0,
            w1th + (size_t)l * NE * F4D * CDIM, CDIM, (long long)F4D * CDIM,
            b1 + (size_t)l * NE * F4D, F4D,
            hidh, (long long)NE * F4D, F4D,
            NTOK, F4D / 128, CDIM / 64);
        // down: eo = hid_e @ W2_e + b2_e -> fp16  (NT1, K-chunk 64)
        mma_gemm64<4><<<dim3(MT * (CDIM / 128), NE), 256, SMEM_K64_NT1>>>(
            hidh, (long long)NE * F4D, F4D,
            w2th + (size_t)l * NE * CDIM * F4D, F4D, (long long)CDIM * F4D,
            b2 + (size_t)l * NE * CDIM, CDIM,
            eo, (long long)NE * CDIM, CDIM,
            NTOK, CDIM / 128, F4D / 64);
        combine_kernel<<<NTOK, 256>>>(eo, gates, x);
    }

    // --- final LN + lm head ---
    ln_kernel<<<NTOK, 256>>>(x, lnf_g, lnf_b, h, hh, hl);
    lm_head_kernel<<<dim3((NV + 63) / 64, (NTOK + 63) / 64), 256>>>(
        h, lm_w, lm_b, out, NTOK, NV, CDIM);
}

// round 13
// speedup vs baseline: 2.5677x; 1.0163x over previous
#include <cuda_runtime.h>
#include <cuda_fp16.h>
#include <math.h>
#include <stdint.h>

// ---- problem constants ----
#define NTOK 844      // B*T = 2*422
#define TSEQ 422
#define BSZ  2
#define CDIM 768
#define NH   32
#define HSD  24
#define NE   32
#define F4D  3072
#define NL   2
#define NV   100

typedef __half fp16;

// ---- device scratch ----
__device__ float g_x  [NTOK * CDIM];
__device__ float g_h  [NTOK * CDIM];
__device__ float g_qkv[NTOK * 3 * CDIM];
__device__ float g_gates[NTOK * NE];
__device__ float g_gwT[NE * CDIM];

__device__ fp16 g_eo [(size_t)NTOK * NE * CDIM];
__device__ fp16 g_hh [NTOK * CDIM];
__device__ fp16 g_atth[NTOK * CDIM];
__device__ fp16 g_wpth[3 * CDIM * CDIM], g_wptl[3 * CDIM * CDIM];
__device__ fp16 g_woth[NL * CDIM * CDIM], g_wotl[NL * CDIM * CDIM];
__device__ fp16 g_w1th[(size_t)NL * NE * F4D * CDIM];
__device__ fp16 g_w2th[(size_t)NL * NE * CDIM * F4D];
__device__ fp16 g_hidh[(size_t)NTOK * NE * F4D];

// ======================= helpers =======================
__device__ __forceinline__ float gelu_exact(float v) {
    return 0.5f * v * (1.f + erff(v * 0.70710678118654752f));
}

__device__ __forceinline__ void mma16816(float* d, const unsigned* a, const unsigned* b) {
    asm volatile(
        "mma.sync.aligned.m16n8k16.row.col.f32.f16.f16.f32 "
        "{%0,%1,%2,%3}, {%4,%5,%6,%7}, {%8,%9}, {%0,%1,%2,%3};"
        : "+f"(d[0]), "+f"(d[1]), "+f"(d[2]), "+f"(d[3])
        : "r"(a[0]), "r"(a[1]), "r"(a[2]), "r"(a[3]), "r"(b[0]), "r"(b[1]));
}

__device__ __forceinline__ void cpa16(unsigned s, const void* g, int sz) {
    asm volatile("cp.async.cg.shared.global [%0], [%1], 16, %2;"
                 :: "r"(s), "l"(g), "r"(sz));
}
#define CPA_COMMIT() asm volatile("cp.async.commit_group;" ::: "memory")
#define CPA_WAIT(n)  asm volatile("cp.async.wait_group %0;" :: "n"(n) : "memory")

#define LDSM4(r0, r1, r2, r3, addr)                                            \
    asm volatile("ldmatrix.sync.aligned.m8n8.x4.shared.b16 {%0,%1,%2,%3}, [%4];" \
        : "=r"(r0), "=r"(r1), "=r"(r2), "=r"(r3) : "r"(addr))

// ======================= shared GEMM geometry =======================
#define STR64 72
#define PL64 (128 * 144)
#define SMEM_2PL  73728            // 2 stages * 2 planes (MoE NT1)
#define SMEM_3PL 110592            // 2 stages * 3 planes (attn NT2)

// ======================= NT2 attention GEMM (A hi; B hi+lo; K-chunk 64) =====
// EP: 0 = Cf plain; 2 = Cf += acc(+bias)
template <int EP>
__global__ void __launch_bounds__(256, 2)
mma_gemmA(const fp16* __restrict__ Ah, long long lda,
          const fp16* __restrict__ Bh, const fp16* __restrict__ Bl,
          long long ldb,
          const float* __restrict__ bias,
          float* __restrict__ Cf, long long ldc,
          int M, int Ntiles, int KC) {
    constexpr unsigned STAGE = 3 * PL64;
    extern __shared__ char smc[];
    unsigned smbase;
    asm("{ .reg .u64 t; cvta.to.shared.u64 t, %1; cvt.u32.u64 %0, t; }"
        : "=r"(smbase) : "l"(smc));

    const int tid = threadIdx.x, wid = tid >> 5, lane = tid & 31;
    const int g = lane >> 2, tg = lane & 3;
    const int wm = wid >> 2, wn = wid & 3;
    const int nt = blockIdx.x % Ntiles, mt = blockIdx.x / Ntiles;
    const int n0 = nt * 128, m0 = mt * 128;

    const int s4 = lane >> 3, lr = lane & 7;
    const int aRowL = lr + (s4 & 1) * 8, aColL = (s4 >> 1) * 8;
    const int bRowL = lr + (s4 >> 1) * 8, bColL = (s4 & 1) * 8;

    float acc[4][4][4];
#pragma unroll
    for (int i = 0; i < 4; i++)
#pragma unroll
        for (int j = 0; j < 4; j++)
#pragma unroll
            for (int r = 0; r < 4; r++) acc[i][j][r] = 0.f;

    auto issue = [&](int c) {
        const int k0 = c * 64;
        unsigned sb = smbase + (c & 1) * STAGE;
#pragma unroll
        for (int i = 0; i < 4; i++) {
            int item = tid + i * 256;
            int row = item >> 3, c8 = item & 7;
            int m = m0 + row;
            int sz = (m < M) ? 16 : 0;
            size_t go = (size_t)(m < M ? m : 0) * lda + k0 + c8 * 8;
            cpa16(sb + row * 144 + c8 * 16, Ah + go, sz);
        }
#pragma unroll
        for (int i = 0; i < 4; i++) {
            int item = tid + i * 256;
            int row = item >> 3, c8 = item & 7;
            size_t go = (size_t)(n0 + row) * ldb + k0 + c8 * 8;
            unsigned so = sb + PL64 + row * 144 + c8 * 16;
            cpa16(so, Bh + go, 16);
            cpa16(so + PL64, Bl + go, 16);
        }
    };

    issue(0);
    CPA_COMMIT();

    for (int c = 0; c < KC; ++c) {
        if (c + 1 < KC) { issue(c + 1); CPA_COMMIT(); CPA_WAIT(1); }
        else            { CPA_WAIT(0); }
        __syncthreads();

        unsigned sb = smbase + (c & 1) * STAGE;
        unsigned sbB = sb + PL64;
#pragma unroll
        for (int ks = 0; ks < 4; ks++) {
            const int kb = ks * 16;
            unsigned bh_[4][2], bl_[4][2];
#pragma unroll
            for (int p = 0; p < 2; p++) {
                int rn0 = wn * 32 + p * 16;
                unsigned ba = sbB + (unsigned)((rn0 + bRowL) * STR64 + kb + bColL) * 2;
                LDSM4(bh_[2 * p][0], bh_[2 * p][1], bh_[2 * p + 1][0], bh_[2 * p + 1][1], ba);
                LDSM4(bl_[2 * p][0], bl_[2 * p][1], bl_[2 * p + 1][0], bl_[2 * p + 1][1],
                      ba + PL64);
            }
#pragma unroll
            for (int mi = 0; mi < 4; mi++) {
                int rm0 = wm * 64 + mi * 16;
                unsigned aa = sb + (unsigned)((rm0 + aRowL) * STR64 + kb + aColL) * 2;
                unsigned ah_[4];
                LDSM4(ah_[0], ah_[1], ah_[2], ah_[3], aa);
#pragma unroll
                for (int ni = 0; ni < 4; ni++) {
                    mma16816(acc[mi][ni], ah_, bh_[ni]);
                    mma16816(acc[mi][ni], ah_, bl_[ni]);
                }
            }
        }
        __syncthreads();
    }

    // ---- epilogue: regs -> smem (fp32) -> coalesced gmem ----
    float* sOut = (float*)smc;
#pragma unroll
    for (int mi = 0; mi < 4; mi++) {
        int lrow = wm * 64 + mi * 16 + g;
#pragma unroll
        for (int ni = 0; ni < 4; ni++) {
            int j = wn * 32 + ni * 8 + tg * 2;
            float b0 = 0.f, b1 = 0.f;
            if (EP == 2) { b0 = bias[n0 + j]; b1 = bias[n0 + j + 1]; }
#pragma unroll
            for (int hh = 0; hh < 2; hh++) {
                float v0 = acc[mi][ni][hh * 2 + 0] + b0;
                float v1 = acc[mi][ni][hh * 2 + 1] + b1;
                *(float2*)&sOut[(lrow + hh * 8) * 132 + j] = make_float2(v0, v1);
            }
        }
    }
    __syncthreads();
#pragma unroll
    for (int i = 0; i < 16; i++) {
        int item = tid + i * 256;
        int row = item >> 5;
        int c4 = (item & 31) * 4;
        int m = m0 + row;
        if (m >= M) continue;
        float4 v = *(float4*)&sOut[row * 132 + c4];
        float* p = Cf + (size_t)m * ldc + n0 + c4;
        if (EP == 2) {
            float4 old = *(float4*)p;
            v.x += old.x; v.y += old.y; v.z += old.z; v.w += old.w;
        }
        *(float4*)p = v;
    }
}

// ======================= NT1 MoE GEMM (K-chunk 64, hi planes only) ==========
// EP: 3 = gelu(+bias) -> fp16 Ch; 4 = +bias -> fp16 Ch
template <int EP>
__global__ void __launch_bounds__(256, 2)
mma_gemm64(const fp16* __restrict__ Ah, long long lda, long long aExp,
           const fp16* __restrict__ Bh, long long ldb, long long bExp,
           const float* __restrict__ bias, long long biasExp,
           fp16* __restrict__ Ch, long long ldc, long long cExp,
           int M, int Ntiles, int KC) {
    constexpr unsigned STAGE = 2 * PL64;
    extern __shared__ char smc[];
    unsigned smbase;
    asm("{ .reg .u64 t; cvta.to.shared.u64 t, %1; cvt.u32.u64 %0, t; }"
        : "=r"(smbase) : "l"(smc));

    const int tid = threadIdx.x, wid = tid >> 5, lane = tid & 31;
    const int g = lane >> 2, tg = lane & 3;
    const int wm = wid >> 2, wn = wid & 3;
    const int e = blockIdx.y;
    const int nt = blockIdx.x % Ntiles, mt = blockIdx.x / Ntiles;
    const int n0 = nt * 128, m0 = mt * 128;

    const fp16* Abh = Ah + (size_t)e * aExp;
    const fp16* Bbh = Bh + (size_t)e * bExp;

    const int s4 = lane >> 3, lr = lane & 7;
    const int aRowL = lr + (s4 & 1) * 8, aColL = (s4 >> 1) * 8;
    const int bRowL = lr + (s4 >> 1) * 8, bColL = (s4 & 1) * 8;

    float acc[4][4][4];
#pragma unroll
    for (int i = 0; i < 4; i++)
#pragma unroll
        for (int j = 0; j < 4; j++)
#pragma unroll
            for (int r = 0; r < 4; r++) acc[i][j][r] = 0.f;

    auto issue = [&](int c) {
        const int k0 = c * 64;
        unsigned sb = smbase + (c & 1) * STAGE;
#pragma unroll
        for (int i = 0; i < 4; i++) {
            int item = tid + i * 256;
            int row = item >> 3, c8 = item & 7;
            int m = m0 + row;
            int sz = (m < M) ? 16 : 0;
            size_t go = (size_t)(m < M ? m : 0) * lda + k0 + c8 * 8;
            cpa16(sb + row * 144 + c8 * 16, Abh + go, sz);
        }
#pragma unroll
        for (int i = 0; i < 4; i++) {
            int item = tid + i * 256;
            int row = item >> 3, c8 = item & 7;
            size_t go = (size_t)(n0 + row) * ldb + k0 + c8 * 8;
            cpa16(sb + PL64 + row * 144 + c8 * 16, Bbh + go, 16);
        }
    };

    issue(0);
    CPA_COMMIT();

    for (int c = 0; c < KC; ++c) {
        if (c + 1 < KC) { issue(c + 1); CPA_COMMIT(); CPA_WAIT(1); }
        else            { CPA_WAIT(0); }
        __syncthreads();

        unsigned sb = smbase + (c & 1) * STAGE;
        unsigned sbB = sb + PL64;
#pragma unroll
        for (int ks = 0; ks < 4; ks++) {
            const int kb = ks * 16;
            unsigned bh_[4][2];
#pragma unroll
            for (int p = 0; p < 2; p++) {
                int rn0 = wn * 32 + p * 16;
                unsigned ba = sbB + (unsigned)((rn0 + bRowL) * STR64 + kb + bColL) * 2;
                LDSM4(bh_[2 * p][0], bh_[2 * p][1], bh_[2 * p + 1][0], bh_[2 * p + 1][1], ba);
            }
#pragma unroll
            for (int mi = 0; mi < 4; mi++) {
                int rm0 = wm * 64 + mi * 16;
                unsigned aa = sb + (unsigned)((rm0 + aRowL) * STR64 + kb + aColL) * 2;
                unsigned ah_[4];
                LDSM4(ah_[0], ah_[1], ah_[2], ah_[3], aa);
#pragma unroll
                for (int ni = 0; ni < 4; ni++)
                    mma16816(acc[mi][ni], ah_, bh_[ni]);
            }
        }
        __syncthreads();
    }

    float* sOut = (float*)smc;
#pragma unroll
    for (int mi = 0; mi < 4; mi++) {
        int lrow = wm * 64 + mi * 16 + g;
#pragma unroll
        for (int ni = 0; ni < 4; ni++) {
            int j = wn * 32 + ni * 8 + tg * 2;
            float b0 = bias[(size_t)e * biasExp + n0 + j];
            float b1 = bias[(size_t)e * biasExp + n0 + j + 1];
#pragma unroll
            for (int hh = 0; hh < 2; hh++) {
                float v0 = acc[mi][ni][hh * 2 + 0] + b0;
                float v1 = acc[mi][ni][hh * 2 + 1] + b1;
                if (EP == 3) { v0 = gelu_exact(v0); v1 = gelu_exact(v1); }
                *(float2*)&sOut[(lrow + hh * 8) * 132 + j] = make_float2(v0, v1);
            }
        }
    }
    __syncthreads();
#pragma unroll
    for (int i = 0; i < 8; i++) {
        int item = tid + i * 256;
        int row = item >> 4;
        int c8 = (item & 15) * 8;
        int m = m0 + row;
        if (m >= M) continue;
        float4 f0 = *(float4*)&sOut[row * 132 + c8];
        float4 f1 = *(float4*)&sOut[row * 132 + c8 + 4];
        __half2 h0 = __floats2half2_rn(f0.x, f0.y);
        __half2 h1 = __floats2half2_rn(f0.z, f0.w);
        __half2 h2 = __floats2half2_rn(f1.x, f1.y);
        __half2 h3 = __floats2half2_rn(f1.z, f1.w);
        uint4 u = make_uint4(*(unsigned*)&h0, *(unsigned*)&h1,
                             *(unsigned*)&h2, *(unsigned*)&h3);
        *(uint4*)(Ch + (size_t)e * cExp + (size_t)m * ldc + n0 + c8) = u;
    }
}

// ======================= transpose + split convert (64x64 tiles) ============
// src [K][N] fp32 -> th (+tl if LO) [N][K] fp16
template <int LO>
__global__ void __launch_bounds__(256)
convT(const float* __restrict__ src, long long sExp, int K, int N,
      fp16* __restrict__ th, fp16* __restrict__ tl, long long tExp) {
    __shared__ float t[64][65];
    int e = blockIdx.z;
    int k0 = blockIdx.x * 64, nn0 = blockIdx.y * 64;
    const float* sp = src + (size_t)e * sExp;
    // phase 1: 256 threads x 4 float4 reads (64 rows x 16 float4/row)
    {
        int rrow = threadIdx.x >> 4;            // 0..15
        int c4 = (threadIdx.x & 15) * 4;        // 0..60
#pragma unroll
        for (int r = 0; r < 4; r++) {
            int k = rrow + r * 16;
            float4 v = *(const float4*)(sp + (size_t)(k0 + k) * N + nn0 + c4);
            t[k][c4 + 0] = v.x; t[k][c4 + 1] = v.y;
            t[k][c4 + 2] = v.z; t[k][c4 + 3] = v.w;
        }
    }
    __syncthreads();
    // phase 2: each thread: one n (tid>>2), 16 consecutive k ((tid&3)*16)
    {
        int n = threadIdx.x >> 2;
        int kq = (threadIdx.x & 3) * 16;
        size_t o = (size_t)e * tExp + (size_t)(nn0 + n) * K + k0 + kq;
#pragma unroll
        for (int i = 0; i < 4; i++) {
            float v0 = t[kq + i * 4 + 0][n], v1 = t[kq + i * 4 + 1][n];
            float v2 = t[kq + i * 4 + 2][n], v3 = t[kq + i * 4 + 3][n];
            __half2 h0 = __floats2half2_rn(v0, v1);
            __half2 h1 = __floats2half2_rn(v2, v3);
            *(uint2*)(th + o + i * 4) = make_uint2(*(unsigned*)&h0, *(unsigned*)&h1);
            if (LO) {
                float2 r0 = __half22float2(h0), r1 = __half22float2(h1);
                __half2 l0 = __floats2half2_rn(v0 - r0.x, v1 - r0.y);
                __half2 l1 = __floats2half2_rn(v2 - r1.x, v3 - r1.y);
                *(uint2*)(tl + o + i * 4) = make_uint2(*(unsigned*)&l0, *(unsigned*)&l1);
            }
        }
    }
}

// ======================= gate_w transpose =======================
__global__ void gwT_kernel(const float* __restrict__ gw, float* __restrict__ gwT) {
    int i = blockIdx.x * blockDim.x + threadIdx.x;
    if (i >= NE * CDIM) return;
    int e = i / CDIM, c = i % CDIM;
    gwT[i] = gw[c * NE + e];
}

// ======================= pack Wq/Wk/Wv -> [3C][C] fp16 hi/lo =================
__global__ void pack_qkvT(const float* __restrict__ Wq,
                          const float* __restrict__ Wk,
                          const float* __restrict__ Wv,
                          fp16* __restrict__ th, fp16* __restrict__ tl) {
    int j = blockIdx.x;
    int which = j / CDIM, hs = j % CDIM;
    int h = hs / HSD, s = hs % HSD;
    const float* W = (which == 0) ? Wq : ((which == 1) ? Wk : Wv);
    for (int c = threadIdx.x; c < CDIM; c += 256) {
        float v = W[((size_t)h * CDIM + c) * HSD + s];
        fp16 hi = __float2half_rn(v);
        size_t o = (size_t)j * CDIM + c;
        th[o] = hi;
        tl[o] = __float2half_rn(v - __half2float(hi));
    }
}

// ======================= embedding =======================
__global__ void embed_kernel(const int* __restrict__ idx,
                             const float* __restrict__ tok,
                             const float* __restrict__ pos,
                             float* __restrict__ x) {
    int n = blockIdx.x;
    int t = n % TSEQ;
    int v = idx[n];
    for (int c = threadIdx.x; c < CDIM; c += blockDim.x)
        x[n * CDIM + c] = tok[v * CDIM + c] + pos[t * CDIM + c];
}

// ======================= layernorm (fp32 + fp16 hi plane) ==================
__global__ void ln_kernel(const float* __restrict__ x,
                          const float* __restrict__ g,
                          const float* __restrict__ b,
                          float* __restrict__ out,
                          fp16* __restrict__ oh) {
    int n = blockIdx.x;
    int tid = threadIdx.x;
    __shared__ float s1[256], s2[256];
    const float* xr = x + (size_t)n * CDIM;
    float a = 0.f, q = 0.f;
    for (int c = tid; c < CDIM; c += 256) { float v = xr[c]; a += v; q += v * v; }
    s1[tid] = a; s2[tid] = q;
    __syncthreads();
    for (int s = 128; s > 0; s >>= 1) {
        if (tid < s) { s1[tid] += s1[tid + s]; s2[tid] += s2[tid + s]; }
        __syncthreads();
    }
    float mean = s1[0] * (1.f / CDIM);
    float var  = s2[0] * (1.f / CDIM) - mean * mean;
    float r = rsqrtf(var + 1e-5f);
    for (int c = tid; c < CDIM; c += 256) {
        float o = (xr[c] - mean) * r * g[c] + b[c];
        size_t p = (size_t)n * CDIM + c;
        out[p] = o;
        oh[p] = __float2half_rn(o);
    }
}

// ======================= attention v2 =======================
#define KV_STR 25
#define ATTN_SMEM ((TSEQ * KV_STR * 2 + 8 * 424 + 8 * 24) * 4)   // 98736 B

__global__ void __launch_bounds__(256)
attn2_kernel(const float* __restrict__ qkv, fp16* __restrict__ atth) {
    int h = blockIdx.x, b = blockIdx.y;
    extern __shared__ float sm[];
    float* Ks = sm;
    float* Vs = Ks + TSEQ * KV_STR;
    float* sc = Vs + TSEQ * KV_STR;
    float* qb = sc + 8 * 424;

    int tid = threadIdx.x, wid = tid >> 5, lane = tid & 31;
    int n0 = b * TSEQ;

    for (int i = tid; i < TSEQ * HSD; i += 256) {
        int u = i / HSD, s = i - u * HSD;
        const float* base = qkv + (size_t)(n0 + u) * (3 * CDIM) + h * HSD + s;
        Ks[u * KV_STR + s] = base[CDIM];
        Vs[u * KV_STR + s] = base[2 * CDIM];
    }
    __syncthreads();

    const float scale = 0.20412414523193154f;
    float* scw = sc + wid * 424;
    float* qw  = qb + wid * 24;

    for (int t = wid; t < TSEQ; t += 8) {
        if (lane < HSD)
            qw[lane] = qkv[(size_t)(n0 + t) * (3 * CDIM) + h * HSD + lane];
        __syncwarp();

        float lmax = -1e30f;
        for (int u = lane; u <= t; u += 32) {
            const float* kr = Ks + u * KV_STR;
            float d = 0.f;
#pragma unroll
            for (int s = 0; s < HSD; s++) d += qw[s] * kr[s];
            d *= scale;
            scw[u] = d;
            lmax = fmaxf(lmax, d);
        }
        for (int o = 16; o > 0; o >>= 1)
            lmax = fmaxf(lmax, __shfl_xor_sync(0xFFFFFFFFu, lmax, o));

        float lsum = 0.f;
        for (int u = lane; u <= t; u += 32) {
            float ev = expf(scw[u] - lmax);
            scw[u] = ev;
            lsum += ev;
        }
        for (int o = 16; o > 0; o >>= 1)
            lsum += __shfl_xor_sync(0xFFFFFFFFu, lsum, o);
        float inv = 1.f / lsum;
        __syncwarp();

        if (lane < HSD) {
            float a = 0.f;
            for (int u = 0; u <= t; u++)
                a += scw[u] * Vs[u * KV_STR + lane];
            a *= inv;
            atth[(size_t)(n0 + t) * CDIM + h * HSD + lane] = __float2half_rn(a);
        }
        __syncwarp();
    }
}

// ======================= gate softmax v2 =======================
__global__ void __launch_bounds__(256)
gate2_kernel(const float* __restrict__ h2, const float* __restrict__ gwT,
             const float* __restrict__ gb, float* __restrict__ gates) {
    int n = blockIdx.x;
    int tid = threadIdx.x, wid = tid >> 5, lane = tid & 31;
    __shared__ float lg[NE];
    __shared__ float hsm[CDIM];
    for (int c = tid; c < CDIM; c += 256) hsm[c] = h2[(size_t)n * CDIM + c];
    __syncthreads();
    for (int e = wid; e < NE; e += 8) {
        const float* w = gwT + (size_t)e * CDIM;
        float a = 0.f;
        for (int c = lane; c < CDIM; c += 32) a += hsm[c] * w[c];
        for (int o = 16; o > 0; o >>= 1) a += __shfl_xor_sync(0xFFFFFFFFu, a, o);
        if (lane == 0) lg[e] = a + gb[e];
    }
    __syncthreads();
    if (tid < 32) {
        float v = lg[tid];
        float mx = v;
        for (int o = 16; o > 0; o >>= 1) mx = fmaxf(mx, __shfl_xor_sync(0xFFFFFFFFu, mx, o));
        float ex = expf(v - mx);
        float smv = ex;
        for (int o = 16; o > 0; o >>= 1) smv += __shfl_xor_sync(0xFFFFFFFFu, smv, o);
        gates[n * NE + tid] = ex / smv;
    }
}

// ======================= MoE combine (fp16 eo) =======================
__global__ void combine_kernel(const fp16* __restrict__ eo,
                               const float* __restrict__ gates,
                               float* __restrict__ x) {
    int n = blockIdx.x;
    __shared__ float gs[NE];
    if (threadIdx.x < NE) gs[threadIdx.x] = gates[n * NE + threadIdx.x];
    __syncthreads();
    for (int c = threadIdx.x; c < CDIM; c += blockDim.x) {
        float a = 0.f;
        const fp16* er = eo + (size_t)n * (NE * CDIM) + c;
#pragma unroll 8
        for (int e = 0; e < NE; e++) a += gs[e] * __half2float(er[e * CDIM]);
        x[(size_t)n * CDIM + c] += a;
    }
}

// ======================= scalar SGEMM (lm head only) =======================
__global__ void __launch_bounds__(256)
lm_head_kernel(const float* __restrict__ A, const float* __restrict__ B,
               const float* __restrict__ bias, float* __restrict__ C,
               int M, int N, int K) {
    __shared__ float As[64][17];
    __shared__ float Bs[16][64];
    int tid = threadIdx.x;
    int jTile = blockIdx.x * 64;
    int mTile = blockIdx.y * 64;
    int tx = tid & 15, ty = tid >> 4;

    float acc[4][4];
#pragma unroll
    for (int r = 0; r < 4; r++)
#pragma unroll
        for (int c = 0; c < 4; c++) acc[r][c] = 0.f;

    int aRow = tid >> 2, aK = (tid & 3) * 4;
    int bJ = tid & 63, bK0 = tid >> 6;

    for (int k0 = 0; k0 < K; k0 += 16) {
        int m = mTile + aRow;
        if (m < M) {
            float4 av = *(const float4*)(A + (size_t)m * K + k0 + aK);
            As[aRow][aK + 0] = av.x; As[aRow][aK + 1] = av.y;
            As[aRow][aK + 2] = av.z; As[aRow][aK + 3] = av.w;
        } else {
            As[aRow][aK + 0] = 0.f; As[aRow][aK + 1] = 0.f;
            As[aRow][aK + 2] = 0.f; As[aRow][aK + 3] = 0.f;
        }
#pragma unroll
        for (int i = 0; i < 4; i++) {
            int kk = bK0 + i * 4;
            Bs[kk][bJ] = (jTile + bJ < N)
                ? B[(size_t)(k0 + kk) * N + jTile + bJ] : 0.f;
        }
        __syncthreads();
#pragma unroll
        for (int k = 0; k < 16; k++) {
            float4 bv = *(const float4*)&Bs[k][tx * 4];
            float a0 = As[ty * 4 + 0][k], a1 = As[ty * 4 + 1][k];
            float a2 = As[ty * 4 + 2][k], a3 = As[ty * 4 + 3][k];
            acc[0][0] += a0 * bv.x; acc[0][1] += a0 * bv.y; acc[0][2] += a0 * bv.z; acc[0][3] += a0 * bv.w;
            acc[1][0] += a1 * bv.x; acc[1][1] += a1 * bv.y; acc[1][2] += a1 * bv.z; acc[1][3] += a1 * bv.w;
            acc[2][0] += a2 * bv.x; acc[2][1] += a2 * bv.y; acc[2][2] += a2 * bv.z; acc[2][3] += a2 * bv.w;
            acc[3][0] += a3 * bv.x; acc[3][1] += a3 * bv.y; acc[3][2] += a3 * bv.z; acc[3][3] += a3 * bv.w;
        }
        __syncthreads();
    }
#pragma unroll
    for (int r = 0; r < 4; r++) {
        int m = mTile + ty * 4 + r;
        if (m >= M) continue;
#pragma unroll
        for (int c = 0; c < 4; c++) {
            int j = jTile + tx * 4 + c;
            if (j >= N) continue;
            C[(size_t)m * N + j] = acc[r][c] + bias[j];
        }
    }
}

// ======================= launch =======================
extern "C" void kernel_launch(void* const* d_in, const int* in_sizes, int n_in,
                              void* d_out, int out_size) {
    const int*   idx    = (const int*)  d_in[0];
    const float* tok    = (const float*)d_in[1];
    const float* pos    = (const float*)d_in[2];
    const float* ln1_g  = (const float*)d_in[3];
    const float* ln1_b  = (const float*)d_in[4];
    const float* Wq     = (const float*)d_in[5];
    const float* Wk     = (const float*)d_in[6];
    const float* Wv     = (const float*)d_in[7];
    const float* Wo     = (const float*)d_in[8];
    const float* bo     = (const float*)d_in[9];
    const float* ln2_g  = (const float*)d_in[10];
    const float* ln2_b  = (const float*)d_in[11];
    const float* gate_w = (const float*)d_in[12];
    const float* gate_b = (const float*)d_in[13];
    const float* W1     = (const float*)d_in[14];
    const float* b1     = (const float*)d_in[15];
    const float* W2     = (const float*)d_in[16];
    const float* b2     = (const float*)d_in[17];
    const float* lnf_g  = (const float*)d_in[18];
    const float* lnf_b  = (const float*)d_in[19];
    const float* lm_w   = (const float*)d_in[20];
    const float* lm_b   = (const float*)d_in[21];
    float* out = (float*)d_out;

    float *x, *h, *qkv, *gates, *gwT;
    fp16 *eo, *hh, *atth, *wpth, *wptl, *woth, *wotl;
    fp16 *w1th, *w2th, *hidh;
    cudaGetSymbolAddress((void**)&x,     g_x);
    cudaGetSymbolAddress((void**)&h,     g_h);
    cudaGetSymbolAddress((void**)&qkv,   g_qkv);
    cudaGetSymbolAddress((void**)&gates, g_gates);
    cudaGetSymbolAddress((void**)&gwT,   g_gwT);
    cudaGetSymbolAddress((void**)&eo,    g_eo);
    cudaGetSymbolAddress((void**)&hh,    g_hh);
    cudaGetSymbolAddress((void**)&atth,  g_atth);
    cudaGetSymbolAddress((void**)&wpth,  g_wpth);
    cudaGetSymbolAddress((void**)&wptl,  g_wptl);
    cudaGetSymbolAddress((void**)&woth,  g_woth);
    cudaGetSymbolAddress((void**)&wotl,  g_wotl);
    cudaGetSymbolAddress((void**)&w1th,  g_w1th);
    cudaGetSymbolAddress((void**)&w2th,  g_w2th);
    cudaGetSymbolAddress((void**)&hidh,  g_hidh);

    cudaFuncSetAttribute(mma_gemmA<0>, cudaFuncAttributeMaxDynamicSharedMemorySize, SMEM_3PL);
    cudaFuncSetAttribute(mma_gemmA<2>, cudaFuncAttributeMaxDynamicSharedMemorySize, SMEM_3PL);
    cudaFuncSetAttribute(mma_gemm64<3>, cudaFuncAttributeMaxDynamicSharedMemorySize, SMEM_2PL);
    cudaFuncSetAttribute(mma_gemm64<4>, cudaFuncAttributeMaxDynamicSharedMemorySize, SMEM_2PL);
    cudaFuncSetAttribute(attn2_kernel, cudaFuncAttributeMaxDynamicSharedMemorySize, ATTN_SMEM);

    const int MT = (NTOK + 127) / 128;   // 7

    // ---- pre-convert weights ----
    for (int l = 0; l < NL; l++) {
        convT<0><<<dim3(CDIM / 64, F4D / 64, NE), 256>>>(
            W1 + (size_t)l * NE * CDIM * F4D, (long long)CDIM * F4D, CDIM, F4D,
            w1th + (size_t)l * NE * F4D * CDIM, nullptr,
            (long long)F4D * CDIM);
        convT<0><<<dim3(F4D / 64, CDIM / 64, NE), 256>>>(
            W2 + (size_t)l * NE * F4D * CDIM, (long long)F4D * CDIM, F4D, CDIM,
            w2th + (size_t)l * NE * CDIM * F4D, nullptr,
            (long long)CDIM * F4D);
        convT<1><<<dim3(CDIM / 64, CDIM / 64, 1), 256>>>(
            Wo + (size_t)l * CDIM * CDIM, 0, CDIM, CDIM,
            woth + (size_t)l * CDIM * CDIM, wotl + (size_t)l * CDIM * CDIM, 0);
    }

    embed_kernel<<<NTOK, 256>>>(idx, tok, pos, x);

    for (int l = 0; l < NL; l++) {
        // --- attention ---
        ln_kernel<<<NTOK, 256>>>(x, ln1_g + l * CDIM, ln1_b + l * CDIM, h, hh);
        pack_qkvT<<<3 * CDIM, 256>>>(
            Wq + (size_t)l * NH * CDIM * HSD,
            Wk + (size_t)l * NH * CDIM * HSD,
            Wv + (size_t)l * NH * CDIM * HSD, wpth, wptl);
        mma_gemmA<0><<<dim3(MT * 18), 256, SMEM_3PL>>>(
            hh, CDIM, wpth, wptl, CDIM, nullptr,
            qkv, 3 * CDIM, NTOK, 18, CDIM / 64);
        attn2_kernel<<<dim3(NH, BSZ), 256, ATTN_SMEM>>>(qkv, atth);
        mma_gemmA<2><<<dim3(MT * 6), 256, SMEM_3PL>>>(
            atth, CDIM,
            woth + (size_t)l * CDIM * CDIM, wotl + (size_t)l * CDIM * CDIM, CDIM,
            bo + l * CDIM, x, CDIM, NTOK, 6, CDIM / 64);

        // --- MoE ---
        ln_kernel<<<NTOK, 256>>>(x, ln2_g + l * CDIM, ln2_b + l * CDIM, h, hh);
        gwT_kernel<<<(NE * CDIM + 255) / 256, 256>>>(
            gate_w + (size_t)l * CDIM * NE, gwT);
        gate2_kernel<<<NTOK, 256>>>(h, gwT, gate_b + l * NE, gates);
        mma_gemm64<3><<<dim3(MT * (F4D / 128), NE), 256, SMEM_2PL>>>(
            hh, CDIM, 0,
            w1th + (size_t)l * NE * F4D * CDIM, CDIM, (long long)F4D * CDIM,
            b1 + (size_t)l * NE * F4D, F4D,
            hidh, (long long)NE * F4D, F4D,
            NTOK, F4D / 128, CDIM / 64);
        mma_gemm64<4><<<dim3(MT * (CDIM / 128), NE), 256, SMEM_2PL>>>(
            hidh, (long long)NE * F4D, F4D,
            w2th + (size_t)l * NE * CDIM * F4D, F4D, (long long)CDIM * F4D,
            b2 + (size_t)l * NE * CDIM, CDIM,
            eo, (long long)NE * CDIM, CDIM,
            NTOK, CDIM / 128, F4D / 64);
        combine_kernel<<<NTOK, 256>>>(eo, gates, x);
    }

    // --- final LN + lm head ---
    ln_kernel<<<NTOK, 256>>>(x, lnf_g, lnf_b, h, hh);
    lm_head_kernel<<<dim3((NV + 63) / 64, (NTOK + 63) / 64), 256>>>(
        h, lm_w, lm_b, out, NTOK, NV, CDIM);
}